// round 5
// baseline (speedup 1.0000x reference)
#include <cuda_runtime.h>
#include <cuda_bf16.h>
#include <float.h>
#include <math.h>
#include <stdint.h>

#define NWIN 30000
#define NEX  30000
#define EDG  480000
#define HDIM 512
#define NLAYERS 4
#define KWIN 1949
#define KEXP 100
#define NOUT 100
#define MP   30080
#define KP_WIN 1984

// ================= fp32 scratch =================
__device__ __align__(256) float g_hw0[NWIN*HDIM];
__device__ __align__(256) float g_hw1[NWIN*HDIM];
__device__ __align__(256) float g_he0[NEX*HDIM];
__device__ __align__(256) float g_he1[NEX*HDIM];
__device__ float g_score[NEX];
__device__ float g_bsum[NLAYERS*HDIM];

// ================= CSR scratch =================
__device__ int g_cnt[3*NWIN];
__device__ int g_off[3*(NWIN+1)];
__device__ int g_cur[3*NWIN];
__device__ int g_csrc[3*EDG];

// ================= bf16 weight buffers [N][Kp], hi & lo =================
#define WOFF_STEP   (HDIM*HDIM)
#define WOFF_LAYER  (5*WOFF_STEP)
#define WOFF_WLN(l) ((l)*WOFF_LAYER + 0*WOFF_STEP)
#define WOFF_WLR(l) ((l)*WOFF_LAYER + 1*WOFF_STEP)
#define WOFF_WSUM(l)((l)*WOFF_LAYER + 2*WOFF_STEP)
#define WOFF_WLC(l) ((l)*WOFF_LAYER + 3*WOFF_STEP)
#define WOFF_WRC(l) ((l)*WOFF_LAYER + 4*WOFF_STEP)
#define WOFF_POST   (NLAYERS*WOFF_LAYER)
#define WOFF_WIN    (WOFF_POST + WOFF_STEP)
#define WOFF_EXP    (WOFF_WIN + HDIM*KP_WIN)
#define WOFF_LIN    (WOFF_EXP + HDIM*128)
#define WTOTAL      (WOFF_LIN + 128*HDIM)
__device__ __align__(256) __nv_bfloat16 g_wth[WTOTAL];
__device__ __align__(256) __nv_bfloat16 g_wtl[WTOTAL];

// ================= bf16 activation plane buffers =================
__device__ __align__(256) __nv_bfloat16 g_bigh[(size_t)MP*KP_WIN];
__device__ __align__(256) __nv_bfloat16 g_bigl[(size_t)MP*KP_WIN];
__device__ __align__(256) __nv_bfloat16 g_pth[(size_t)MP*HDIM];
__device__ __align__(256) __nv_bfloat16 g_ptl[(size_t)MP*HDIM];
__device__ __align__(256) __nv_bfloat16 g_phw0h[(size_t)MP*HDIM];
__device__ __align__(256) __nv_bfloat16 g_phw0l[(size_t)MP*HDIM];
__device__ __align__(256) __nv_bfloat16 g_phw1h[(size_t)MP*HDIM];
__device__ __align__(256) __nv_bfloat16 g_phw1l[(size_t)MP*HDIM];
__device__ __align__(256) __nv_bfloat16 g_phe0h[(size_t)MP*HDIM];
__device__ __align__(256) __nv_bfloat16 g_phe0l[(size_t)MP*HDIM];
__device__ __align__(256) __nv_bfloat16 g_phe1h[(size_t)MP*HDIM];
__device__ __align__(256) __nv_bfloat16 g_phe1l[(size_t)MP*HDIM];
__device__ __align__(256) __nv_bfloat16 g_pa0h[(size_t)MP*HDIM];
__device__ __align__(256) __nv_bfloat16 g_pa0l[(size_t)MP*HDIM];
__device__ __align__(256) __nv_bfloat16 g_pa1h[(size_t)MP*HDIM];
__device__ __align__(256) __nv_bfloat16 g_pa1l[(size_t)MP*HDIM];
__device__ __align__(256) __nv_bfloat16 g_pa2h[(size_t)MP*HDIM];
__device__ __align__(256) __nv_bfloat16 g_pa2l[(size_t)MP*HDIM];

// ================= helpers =================
__device__ __forceinline__ void split2(float v0, float v1, __nv_bfloat162& h, __nv_bfloat162& l)
{
    __nv_bfloat16 h0 = __float2bfloat16_rn(v0);
    __nv_bfloat16 h1 = __float2bfloat16_rn(v1);
    h.x = h0; h.y = h1;
    l.x = __float2bfloat16_rn(v0 - __bfloat162float(h0));
    l.y = __float2bfloat16_rn(v1 - __bfloat162float(h1));
}

// ================= batched HxH weight conversion (transpose + split) =================
#define NBATCH 21
struct ConvBatch {
    const float* W1[NBATCH];
    const float* W2[NBATCH];
    int dstoff[NBATCH];
};

__global__ void conv_w_batch(const __grid_constant__ ConvBatch cb,
                             __nv_bfloat16* __restrict__ ohb,
                             __nv_bfloat16* __restrict__ olb)
{
    __shared__ float t[32][33];
    int z = blockIdx.z;
    const float* W = cb.W1[z];
    const float* W2 = cb.W2[z];
    __nv_bfloat16* oh = ohb + cb.dstoff[z];
    __nv_bfloat16* ol = olb + cb.dstoff[z];
    int k0 = blockIdx.x * 32, n0 = blockIdx.y * 32;
    int tx = threadIdx.x, ty = threadIdx.y;
#pragma unroll
    for (int i = 0; i < 4; i++) {
        int k = k0 + ty + i * 8, n = n0 + tx;
        float v = W[(size_t)k * HDIM + n];
        if (W2) v += W2[(size_t)k * HDIM + n];
        t[ty + i * 8][tx] = v;
    }
    __syncthreads();
#pragma unroll
    for (int i = 0; i < 4; i++) {
        int n = n0 + ty + i * 8, k = k0 + tx;
        float v = t[tx][ty + i * 8];
        __nv_bfloat16 hb = __float2bfloat16_rn(v);
        oh[(size_t)n * HDIM + k] = hb;
        ol[(size_t)n * HDIM + k] = __float2bfloat16_rn(v - __bfloat162float(hb));
    }
}

// generic single conv_w for odd shapes (WIN, EXP, LIN)
__global__ void conv_w(const float* __restrict__ W, int K, int N, int Kp,
                       __nv_bfloat16* __restrict__ oh, __nv_bfloat16* __restrict__ ol)
{
    __shared__ float t[32][33];
    int k0 = blockIdx.x * 32, n0 = blockIdx.y * 32;
    int tx = threadIdx.x, ty = threadIdx.y;
#pragma unroll
    for (int i = 0; i < 4; i++) {
        int k = k0 + ty + i * 8, n = n0 + tx;
        float v = 0.f;
        if (k < K && n < N) v = W[(size_t)k * N + n];
        t[ty + i * 8][tx] = v;
    }
    __syncthreads();
#pragma unroll
    for (int i = 0; i < 4; i++) {
        int n = n0 + ty + i * 8, k = k0 + tx;
        float v = t[tx][ty + i * 8];
        __nv_bfloat16 hb = __float2bfloat16_rn(v);
        oh[(size_t)n * Kp + k] = hb;
        ol[(size_t)n * Kp + k] = __float2bfloat16_rn(v - __bfloat162float(hb));
    }
}

__global__ void conv_a(const float* __restrict__ A, int M, int K, int Kp, long long total,
                       __nv_bfloat16* __restrict__ oh, __nv_bfloat16* __restrict__ ol)
{
    long long i = (long long)blockIdx.x * blockDim.x + threadIdx.x;
    if (i >= total) return;
    int m = (int)(i / Kp);
    int k = (int)(i % Kp);
    float v = 0.f;
    if (m < M && k < K) v = A[(size_t)m * K + k];
    __nv_bfloat16 hb = __float2bfloat16_rn(v);
    oh[i] = hb;
    ol[i] = __float2bfloat16_rn(v - __bfloat162float(hb));
}

__global__ void bias_sum_all(const float* a, const float* b, float* o)
{
    int i = blockIdx.x * blockDim.x + threadIdx.x;
    if (i < NLAYERS * HDIM) o[i] = a[i] + b[i];
}

__global__ void zero_int(int* p, int n)
{
    int i = blockIdx.x * blockDim.x + threadIdx.x;
    if (i < n) p[i] = 0;
}

struct PadPtrs { __nv_bfloat16* h[5]; __nv_bfloat16* l[5]; };
__global__ void zero_pad_all(const __grid_constant__ PadPtrs pp)
{
    int i = blockIdx.x * blockDim.x + threadIdx.x;
    const int per = (MP - NWIN) * HDIM;
    int z = i / per;
    if (z >= 5) return;
    int r = i - z * per;
    pp.h[z][(size_t)NWIN * HDIM + r] = __float2bfloat16_rn(0.f);
    pp.l[z][(size_t)NWIN * HDIM + r] = __float2bfloat16_rn(0.f);
}

// ================= CSR build (z-batched over 3 relations) =================
struct EdgePtrs { const int* es[3]; const int* ed[3]; };

__global__ void hist_all(const __grid_constant__ EdgePtrs ep, int* __restrict__ cnt)
{
    int r = blockIdx.y;
    int e = blockIdx.x * blockDim.x + threadIdx.x;
    if (e < EDG) atomicAdd(&cnt[r * NWIN + ep.ed[r][e]], 1);
}

__global__ void scan_all(const int* __restrict__ cnt, int* __restrict__ off,
                         int* __restrict__ cur)
{
    __shared__ int s[1024];
    int r = blockIdx.x;
    const int* c = cnt + r * NWIN;
    int* of = off + r * (NWIN + 1);
    int* cu = cur + r * NWIN;
    int t = threadIdx.x;
    int chunk = (NWIN + 1023) >> 10;
    int b = t * chunk, e = min(b + chunk, NWIN);
    int sum = 0;
    for (int i = b; i < e; i++) sum += c[i];
    s[t] = sum;
    __syncthreads();
    for (int d = 1; d < 1024; d <<= 1) {
        int v = (t >= d) ? s[t - d] : 0;
        __syncthreads();
        s[t] += v;
        __syncthreads();
    }
    int run = (t == 0) ? 0 : s[t - 1];
    for (int i = b; i < e; i++) {
        of[i] = run; cu[i] = run; run += c[i];
    }
    if (t == 0) of[NWIN] = s[1023];
}

__global__ void fill_all(const __grid_constant__ EdgePtrs ep, int* __restrict__ cur,
                         int* __restrict__ csrc)
{
    int r = blockIdx.y;
    int e = blockIdx.x * blockDim.x + threadIdx.x;
    if (e < EDG) {
        int p = atomicAdd(&cur[r * NWIN + ep.ed[r][e]], 1);
        csrc[(size_t)r * EDG + p] = ep.es[r][e];
    }
}

// ================= CSR gather-mean -> bf16 planes =================
__global__ void gather_mean(const float* __restrict__ src, const int* __restrict__ off,
                            const int* __restrict__ csrc, int ndst,
                            __nv_bfloat16* __restrict__ oh, __nv_bfloat16* __restrict__ ol)
{
    int d = blockIdx.x;
    int t = threadIdx.x;
    float4 acc = make_float4(0.f, 0.f, 0.f, 0.f);
    int deg = 0;
    if (d < ndst) {
        int s0 = off[d], s1 = off[d + 1];
        deg = s1 - s0;
        for (int e = s0; e < s1; e++) {
            float4 v = ((const float4*)(src + (size_t)csrc[e] * HDIM))[t];
            acc.x += v.x; acc.y += v.y; acc.z += v.z; acc.w += v.w;
        }
    }
    float inv = 1.f / (float)max(deg, 1);
    acc.x *= inv; acc.y *= inv; acc.z *= inv; acc.w *= inv;
    __nv_bfloat162 h0, l0, h1, l1;
    split2(acc.x, acc.y, h0, l0);
    split2(acc.z, acc.w, h1, l1);
    size_t o = (size_t)d * HDIM + t * 4;
    *(__nv_bfloat162*)(oh + o) = h0;
    *(__nv_bfloat162*)(oh + o + 2) = h1;
    *(__nv_bfloat162*)(ol + o) = l0;
    *(__nv_bfloat162*)(ol + o + 2) = l1;
}

// ================= CSR softmax pooling =================
__global__ void pool_gather(const float* __restrict__ he, const float* __restrict__ hw,
                            const float* __restrict__ score,
                            const int* __restrict__ off, const int* __restrict__ csrc,
                            int ndst,
                            __nv_bfloat16* __restrict__ oh, __nv_bfloat16* __restrict__ ol)
{
    __shared__ float red[128];
    int d = blockIdx.x;
    int t = threadIdx.x;
    float4 res = make_float4(0.f, 0.f, 0.f, 0.f);
    if (d < ndst) {
        int s0 = off[d], s1 = off[d + 1];
        float m = -FLT_MAX;
        for (int e = s0 + t; e < s1; e += 128) m = fmaxf(m, score[csrc[e]]);
        red[t] = m; __syncthreads();
        for (int w = 64; w; w >>= 1) {
            if (t < w) red[t] = fmaxf(red[t], red[t + w]);
            __syncthreads();
        }
        float smax = red[0];
        __syncthreads();
        float z = 0.f;
        for (int e = s0 + t; e < s1; e += 128) z += expf(score[csrc[e]] - smax);
        red[t] = z; __syncthreads();
        for (int w = 64; w; w >>= 1) {
            if (t < w) red[t] += red[t + w];
            __syncthreads();
        }
        float invz = 1.f / fmaxf(red[0], 1e-12f);
        float4 acc = make_float4(0.f, 0.f, 0.f, 0.f);
        for (int e = s0; e < s1; e++) {
            int sidx = csrc[e];
            float w = expf(score[sidx] - smax) * invz;
            float4 v = ((const float4*)(he + (size_t)sidx * HDIM))[t];
            acc.x += w * v.x; acc.y += w * v.y; acc.z += w * v.z; acc.w += w * v.w;
        }
        float4 h = ((const float4*)(hw + (size_t)d * HDIM))[t];
        res.x = h.x + 0.5f * acc.x;
        res.y = h.y + 0.5f * acc.y;
        res.z = h.z + 0.5f * acc.z;
        res.w = h.w + 0.5f * acc.w;
    }
    __nv_bfloat162 h0, l0, h1, l1;
    split2(res.x, res.y, h0, l0);
    split2(res.z, res.w, h1, l1);
    size_t o = (size_t)d * HDIM + t * 4;
    *(__nv_bfloat162*)(oh + o) = h0;
    *(__nv_bfloat162*)(oh + o + 2) = h1;
    *(__nv_bfloat162*)(ol + o) = l0;
    *(__nv_bfloat162*)(ol + o + 2) = l1;
}

__global__ void gemv_score(const float* __restrict__ he, const float* __restrict__ w,
                           float* __restrict__ sc)
{
    int row = blockIdx.x * 8 + (threadIdx.x >> 5);
    if (row >= NEX) return;
    int lane = threadIdx.x & 31;
    const float* r = he + (size_t)row * HDIM;
    float s = 0.f;
#pragma unroll
    for (int k = lane; k < HDIM; k += 32) s += r[k] * w[k];
#pragma unroll
    for (int o = 16; o; o >>= 1) s += __shfl_down_sync(0xFFFFFFFFu, s, o);
    if (lane == 0) sc[row] = s;
}

// ================= mma.sync bf16 GEMM (3-pass split), templated BN =================
struct GemmArgs {
    const __nv_bfloat16 *Ah[3], *Al[3], *Bh[3], *Bl[3];
    int Kp[3];
    int nops, totChunks;
    int M, Nstore, ldd;
    const float* bias;
    float ps;
    int act;
    float* D;
    __nv_bfloat16 *Dh, *Dl;
};

__device__ __forceinline__ uint32_t smem_u32(const void* p) {
    uint32_t a;
    asm("{ .reg .u64 t; cvta.to.shared.u64 t, %1; cvt.u32.u64 %0, t; }" : "=r"(a) : "l"(p));
    return a;
}
__device__ __forceinline__ void cp16(uint32_t dst, const void* src) {
    asm volatile("cp.async.cg.shared.global [%0], [%1], 16;" :: "r"(dst), "l"(src));
}
__device__ __forceinline__ void cp_commit() { asm volatile("cp.async.commit_group;"); }
__device__ __forceinline__ void cp_wait0() { asm volatile("cp.async.wait_group 0;"); }
__device__ __forceinline__ void cp_wait1() { asm volatile("cp.async.wait_group 1;"); }

__device__ __forceinline__ void ldm_x4(uint32_t* r, uint32_t addr) {
    asm volatile("ldmatrix.sync.aligned.m8n8.x4.shared.b16 {%0,%1,%2,%3}, [%4];"
                 : "=r"(r[0]), "=r"(r[1]), "=r"(r[2]), "=r"(r[3]) : "r"(addr));
}
__device__ __forceinline__ void mma16816(float* c, const uint32_t* a, const uint32_t* b) {
    asm volatile("mma.sync.aligned.m16n8k16.row.col.f32.bf16.bf16.f32 "
                 "{%0,%1,%2,%3},{%4,%5,%6,%7},{%8,%9},{%0,%1,%2,%3};"
                 : "+f"(c[0]), "+f"(c[1]), "+f"(c[2]), "+f"(c[3])
                 : "r"(a[0]), "r"(a[1]), "r"(a[2]), "r"(a[3]), "r"(b[0]), "r"(b[1]));
}

__device__ __forceinline__ void map_oc(const GemmArgs& g, int t, int& o, int& c) {
    o = 0;
    int rem = t;
    while (o < g.nops - 1 && rem >= (g.Kp[o] >> 6)) { rem -= (g.Kp[o] >> 6); o++; }
    c = rem;
}

// stage layout: Ah(16KB) Al(16KB) Bh(BN*128) Bl(BN*128)
template<int BN>
__device__ __forceinline__ void load_stage(const GemmArgs& g, int t, uint32_t sb,
                                           int tid, int m0, int n0)
{
    int o, c;
    map_oc(g, t, o, c);
    const int Kp = g.Kp[o];
    const int k0 = c << 6;
    // A planes: 128 rows x 64 cols
    {
        const __nv_bfloat16* baseh = g.Ah[o] + (size_t)m0 * Kp + k0;
        const __nv_bfloat16* basel = g.Al[o] + (size_t)m0 * Kp + k0;
#pragma unroll
        for (int it = 0; it < 4; it++) {
            int idx = it * 256 + tid;
            int r = idx >> 3;
            int j = idx & 7;
            uint32_t sw = r * 128 + ((j ^ (r & 7)) << 4);
            cp16(sb + sw, baseh + (size_t)r * Kp + j * 8);
            cp16(sb + 16384 + sw, basel + (size_t)r * Kp + j * 8);
        }
    }
    // B planes: BN rows x 64 cols
    {
        const __nv_bfloat16* baseh = g.Bh[o] + (size_t)n0 * Kp + k0;
        const __nv_bfloat16* basel = g.Bl[o] + (size_t)n0 * Kp + k0;
        const uint32_t bh0 = sb + 32768;
        const uint32_t bl0 = sb + 32768 + BN * 128;
#pragma unroll
        for (int it = 0; it < BN / 32; it++) {
            int idx = it * 256 + tid;
            int r = idx >> 3;
            int j = idx & 7;
            uint32_t sw = r * 128 + ((j ^ (r & 7)) << 4);
            cp16(bh0 + sw, baseh + (size_t)r * Kp + j * 8);
            cp16(bl0 + sw, basel + (size_t)r * Kp + j * 8);
        }
    }
    cp_commit();
}

template<int BN>
__global__ __launch_bounds__(256, 1) void gemm_mma(const __grid_constant__ GemmArgs g)
{
    constexpr int NT = BN / 32;        // n8-tiles per warp
    constexpr int NBL = BN / 64;       // B ldm_x4 groups per warp
    constexpr int WCOL = BN / 4;       // cols per warp
    constexpr int STAGE = 32768 + 2 * BN * 128;

    extern __shared__ __align__(128) char smem[];
    const uint32_t sbase = smem_u32(smem);
    const int tid = threadIdx.x;
    const int lane = tid & 31;
    const int warp = tid >> 5;
    const int wm = warp >> 2;
    const int wn = warp & 3;
    const int m0 = blockIdx.y * 128;
    const int n0 = blockIdx.x * BN;

    float acc[4][NT][4];
#pragma unroll
    for (int i = 0; i < 4; i++)
#pragma unroll
        for (int j = 0; j < NT; j++)
#pragma unroll
            for (int q = 0; q < 4; q++) acc[i][j][q] = 0.f;

    const int sx = lane & 7;
    const int arow = (lane & 7) + ((lane >> 3) & 1) * 8;
    const int khia = (lane >> 4) & 1;
    const int brow = (lane & 7) + ((lane >> 4) & 1) * 8;
    const int khib = (lane >> 3) & 1;

    const int T = g.totChunks;
    load_stage<BN>(g, 0, sbase, tid, m0, n0);

    for (int t = 0; t < T; t++) {
        if (t + 1 < T) {
            load_stage<BN>(g, t + 1, sbase + ((t + 1) & 1) * STAGE, tid, m0, n0);
            cp_wait1();
        } else {
            cp_wait0();
        }
        __syncthreads();

        const uint32_t Ah = sbase + (t & 1) * STAGE;
        const uint32_t Al = Ah + 16384;
        const uint32_t Bh = Ah + 32768;
        const uint32_t Bl = Bh + BN * 128;

#pragma unroll
        for (int ks = 0; ks < 4; ks++) {
            uint32_t ah[4][4], al[4][4], bh[NBL][4], bl[NBL][4];
            const uint32_t colA = (uint32_t)(((ks * 2 + khia) ^ sx) << 4);
            const uint32_t colB = (uint32_t)(((ks * 2 + khib) ^ sx) << 4);
#pragma unroll
            for (int mt = 0; mt < 4; mt++) {
                int row = wm * 64 + mt * 16 + arow;
                ldm_x4(ah[mt], Ah + row * 128 + colA);
                ldm_x4(al[mt], Al + row * 128 + colA);
            }
#pragma unroll
            for (int np = 0; np < NBL; np++) {
                int row = wn * WCOL + np * 16 + brow;
                ldm_x4(bh[np], Bh + row * 128 + colB);
                ldm_x4(bl[np], Bl + row * 128 + colB);
            }
#pragma unroll
            for (int mt = 0; mt < 4; mt++) {
#pragma unroll
                for (int nt = 0; nt < NT; nt++) {
                    const uint32_t* bhf = &bh[nt >> 1][(nt & 1) * 2];
                    const uint32_t* blf = &bl[nt >> 1][(nt & 1) * 2];
                    mma16816(acc[mt][nt], ah[mt], bhf);
                    mma16816(acc[mt][nt], ah[mt], blf);
                    mma16816(acc[mt][nt], al[mt], bhf);
                }
            }
        }
        __syncthreads();
    }

    // ---- epilogue ----
#pragma unroll
    for (int mt = 0; mt < 4; mt++) {
        int row0 = m0 + wm * 64 + mt * 16 + (lane >> 2);
#pragma unroll
        for (int nt = 0; nt < NT; nt++) {
            int col = n0 + wn * WCOL + nt * 8 + (lane & 3) * 2;
            if (col >= g.Nstore) continue;
            float b0 = 0.f, b1 = 0.f;
            if (g.bias) {
                b0 = g.bias[col];
                if (col + 1 < g.Nstore) b1 = g.bias[col + 1];
            }
#pragma unroll
            for (int rr = 0; rr < 2; rr++) {
                int r = row0 + rr * 8;
                if (r >= g.M) continue;
                float v0 = (acc[mt][nt][rr * 2 + 0] + b0) * g.ps;
                float v1 = (acc[mt][nt][rr * 2 + 1] + b1) * g.ps;
                if (g.act) {
                    v0 = v0 > 0.f ? v0 : 0.2f * v0;
                    v1 = v1 > 0.f ? v1 : 0.2f * v1;
                }
                if (g.D) {
                    float* dp = g.D + (size_t)r * g.ldd + col;
                    if (col + 1 < g.Nstore) *(float2*)dp = make_float2(v0, v1);
                    else *dp = v0;
                }
                if (g.Dh) {
                    __nv_bfloat162 hh, ll;
                    split2(v0, v1, hh, ll);
                    size_t po = (size_t)r * HDIM + col;
                    *(__nv_bfloat162*)(g.Dh + po) = hh;
                    *(__nv_bfloat162*)(g.Dl + po) = ll;
                }
            }
        }
    }
}

// ================= host orchestration =================
struct OpDesc {
    const __nv_bfloat16 *Ah, *Al, *Bh, *Bl;
    int Kp;
};

#define SMEM_128 (2 * (32768 + 2 * 128 * 128))
#define SMEM_256 (2 * (32768 + 2 * 256 * 128))

static void launch_gemm(const OpDesc* ops, int nops, int M, int Np, int Nstore,
                        int ldd, const float* bias, float ps, int act,
                        float* D, __nv_bfloat16* Dh, __nv_bfloat16* Dl)
{
    GemmArgs g;
    int T = 0;
    for (int o = 0; o < nops; o++) {
        g.Ah[o] = ops[o].Ah; g.Al[o] = ops[o].Al;
        g.Bh[o] = ops[o].Bh; g.Bl[o] = ops[o].Bl;
        g.Kp[o] = ops[o].Kp;
        T += ops[o].Kp / 64;
    }
    g.nops = nops; g.totChunks = T;
    g.M = M; g.Nstore = Nstore; g.ldd = ldd;
    g.bias = bias; g.ps = ps; g.act = act;
    g.D = D; g.Dh = Dh; g.Dl = Dl;
    if (Np % 256 == 0) {
        dim3 grid(Np / 256, (M + 127) / 128);
        gemm_mma<256><<<grid, 256, SMEM_256>>>(g);
    } else {
        dim3 grid(Np / 128, (M + 127) / 128);
        gemm_mma<128><<<grid, 256, SMEM_128>>>(g);
    }
}

extern "C" void kernel_launch(void* const* d_in, const int* in_sizes, int n_in,
                              void* d_out, int out_size)
{
    const float* x_window  = (const float*)d_in[0];
    const float* x_example = (const float*)d_in[1];
    const int*   e_near    = (const int*)d_in[2];
    const int*   e_close   = (const int*)d_in[3];
    const int*   e_refer   = (const int*)d_in[4];
    const float* W_win     = (const float*)d_in[5];
    const float* W_exp     = (const float*)d_in[6];
    const float* W_post    = (const float*)d_in[7];
    const float* Wl_near   = (const float*)d_in[9];
    const float* Wr_near   = (const float*)d_in[10];
    const float* b_near    = (const float*)d_in[11];
    const float* Wl_close  = (const float*)d_in[12];
    const float* Wr_close  = (const float*)d_in[13];
    const float* b_close   = (const float*)d_in[14];
    const float* Wl_refer  = (const float*)d_in[15];
    const float* Wr_refer  = (const float*)d_in[16];
    const float* b_refer   = (const float*)d_in[17];
    const float* w_pool    = (const float*)d_in[18];
    const float* W_lin     = (const float*)d_in[19];
    const float* b_lin     = (const float*)d_in[20];
    float* out = (float*)d_out;

    cudaFuncSetAttribute(gemm_mma<128>, cudaFuncAttributeMaxDynamicSharedMemorySize, SMEM_128);
    cudaFuncSetAttribute(gemm_mma<256>, cudaFuncAttributeMaxDynamicSharedMemorySize, SMEM_256);

    float *hw[2], *he[2], *score, *bsum;
    int *cnt, *off, *cur, *csrc;
    __nv_bfloat16 *wth, *wtl, *bigh, *bigl, *pth, *ptl;
    __nv_bfloat16 *phwh[2], *phwl[2], *pheh[2], *phel[2];
    __nv_bfloat16 *pa0h, *pa0l, *pa1h, *pa1l, *pa2h, *pa2l;
    cudaGetSymbolAddress((void**)&hw[0], g_hw0);
    cudaGetSymbolAddress((void**)&hw[1], g_hw1);
    cudaGetSymbolAddress((void**)&he[0], g_he0);
    cudaGetSymbolAddress((void**)&he[1], g_he1);
    cudaGetSymbolAddress((void**)&score, g_score);
    cudaGetSymbolAddress((void**)&bsum, g_bsum);
    cudaGetSymbolAddress((void**)&cnt, g_cnt);
    cudaGetSymbolAddress((void**)&off, g_off);
    cudaGetSymbolAddress((void**)&cur, g_cur);
    cudaGetSymbolAddress((void**)&csrc, g_csrc);
    cudaGetSymbolAddress((void**)&wth, g_wth);
    cudaGetSymbolAddress((void**)&wtl, g_wtl);
    cudaGetSymbolAddress((void**)&bigh, g_bigh);
    cudaGetSymbolAddress((void**)&bigl, g_bigl);
    cudaGetSymbolAddress((void**)&pth, g_pth);
    cudaGetSymbolAddress((void**)&ptl, g_ptl);
    cudaGetSymbolAddress((void**)&phwh[0], g_phw0h);
    cudaGetSymbolAddress((void**)&phwl[0], g_phw0l);
    cudaGetSymbolAddress((void**)&phwh[1], g_phw1h);
    cudaGetSymbolAddress((void**)&phwl[1], g_phw1l);
    cudaGetSymbolAddress((void**)&pheh[0], g_phe0h);
    cudaGetSymbolAddress((void**)&phel[0], g_phe0l);
    cudaGetSymbolAddress((void**)&pheh[1], g_phe1h);
    cudaGetSymbolAddress((void**)&phel[1], g_phe1l);
    cudaGetSymbolAddress((void**)&pa0h, g_pa0h);
    cudaGetSymbolAddress((void**)&pa0l, g_pa0l);
    cudaGetSymbolAddress((void**)&pa1h, g_pa1h);
    cudaGetSymbolAddress((void**)&pa1l, g_pa1l);
    cudaGetSymbolAddress((void**)&pa2h, g_pa2h);
    cudaGetSymbolAddress((void**)&pa2l, g_pa2l);

    const unsigned edge_blocks = (EDG + 255) / 256;

    // --- batched weight conversion ---
    {
        ConvBatch cb;
        for (int l = 0; l < NLAYERS; l++) {
            size_t s = (size_t)l * HDIM * HDIM;
            cb.W1[l * 5 + 0] = Wl_near + s;  cb.W2[l * 5 + 0] = nullptr;      cb.dstoff[l * 5 + 0] = WOFF_WLN(l);
            cb.W1[l * 5 + 1] = Wl_refer + s; cb.W2[l * 5 + 1] = nullptr;      cb.dstoff[l * 5 + 1] = WOFF_WLR(l);
            cb.W1[l * 5 + 2] = Wr_near + s;  cb.W2[l * 5 + 2] = Wr_refer + s; cb.dstoff[l * 5 + 2] = WOFF_WSUM(l);
            cb.W1[l * 5 + 3] = Wl_close + s; cb.W2[l * 5 + 3] = nullptr;      cb.dstoff[l * 5 + 3] = WOFF_WLC(l);
            cb.W1[l * 5 + 4] = Wr_close + s; cb.W2[l * 5 + 4] = nullptr;      cb.dstoff[l * 5 + 4] = WOFF_WRC(l);
        }
        cb.W1[20] = W_post; cb.W2[20] = nullptr; cb.dstoff[20] = WOFF_POST;
        dim3 blk(32, 8);
        dim3 gB(HDIM / 32, HDIM / 32, NBATCH);
        conv_w_batch<<<gB, blk>>>(cb, wth, wtl);

        dim3 gWIN(KP_WIN / 32, HDIM / 32);
        conv_w<<<gWIN, blk>>>(W_win, KWIN, HDIM, KP_WIN, wth + WOFF_WIN, wtl + WOFF_WIN);
        dim3 gEXP(128 / 32, HDIM / 32);
        conv_w<<<gEXP, blk>>>(W_exp, KEXP, HDIM, 128, wth + WOFF_EXP, wtl + WOFF_EXP);
        dim3 gLIN(HDIM / 32, 128 / 32);
        conv_w<<<gLIN, blk>>>(W_lin, HDIM, NOUT, HDIM, wth + WOFF_LIN, wtl + WOFF_LIN);
        bias_sum_all<<<(NLAYERS * HDIM + 255) / 256, 256>>>(b_near, b_refer, bsum);
    }

    // --- zero pad rows [NWIN, MP) of GEMM-written plane buffers ---
    {
        PadPtrs pp;
        pp.h[0] = pth;     pp.l[0] = ptl;
        pp.h[1] = phwh[0]; pp.l[1] = phwl[0];
        pp.h[2] = phwh[1]; pp.l[2] = phwl[1];
        pp.h[3] = pheh[0]; pp.l[3] = phel[0];
        pp.h[4] = pheh[1]; pp.l[4] = phel[1];
        int tot = 5 * (MP - NWIN) * HDIM;
        zero_pad_all<<<(tot + 255) / 256, 256>>>(pp);
    }

    // --- CSR build (relations: 0=near, 1=refer, 2=close) ---
    {
        EdgePtrs ep;
        ep.es[0] = e_near;  ep.ed[0] = e_near + EDG;
        ep.es[1] = e_refer; ep.ed[1] = e_refer + EDG;
        ep.es[2] = e_close; ep.ed[2] = e_close + EDG;
        zero_int<<<(3 * NWIN + 255) / 256, 256>>>(cnt, 3 * NWIN);
        dim3 ge(edge_blocks, 3);
        hist_all<<<ge, 256>>>(ep, cnt);
        scan_all<<<3, 1024>>>(cnt, off, cur);
        fill_all<<<ge, 256>>>(ep, cur, csrc);
    }

    // --- input projections: h = lrelu(lrelu(x@W)@W_post) ---
    {
        long long tot = (long long)MP * 128;
        conv_a<<<(unsigned)((tot + 255) / 256), 256>>>(x_example, NEX, KEXP, 128, tot, pa0h, pa0l);
        OpDesc op = { pa0h, pa0l, wth + WOFF_EXP, wtl + WOFF_EXP, 128 };
        launch_gemm(&op, 1, NEX, HDIM, HDIM, HDIM, nullptr, 1.f, 1, nullptr, pth, ptl);
        op = { pth, ptl, wth + WOFF_POST, wtl + WOFF_POST, HDIM };
        launch_gemm(&op, 1, NEX, HDIM, HDIM, HDIM, nullptr, 1.f, 1, he[0], pheh[0], phel[0]);

        tot = (long long)MP * KP_WIN;
        conv_a<<<(unsigned)((tot + 255) / 256), 256>>>(x_window, NWIN, KWIN, KP_WIN, tot, bigh, bigl);
        op = { bigh, bigl, wth + WOFF_WIN, wtl + WOFF_WIN, KP_WIN };
        launch_gemm(&op, 1, NWIN, HDIM, HDIM, HDIM, nullptr, 1.f, 1, nullptr, pth, ptl);
        op = { pth, ptl, wth + WOFF_POST, wtl + WOFF_POST, HDIM };
        launch_gemm(&op, 1, NWIN, HDIM, HDIM, HDIM, nullptr, 1.f, 1, hw[0], phwh[0], phwl[0]);
    }

    // --- SAGE layers ---
    int curb = 0;
    for (int l = 0; l < NLAYERS; l++) {
        int nxt = curb ^ 1;
        gather_mean<<<MP, 128>>>(hw[curb], off + 0 * (NWIN + 1), csrc + 0 * (size_t)EDG, NWIN, pa0h, pa0l);
        gather_mean<<<MP, 128>>>(he[curb], off + 1 * (NWIN + 1), csrc + 1 * (size_t)EDG, NWIN, pa1h, pa1l);
        gather_mean<<<MP, 128>>>(he[curb], off + 2 * (NWIN + 1), csrc + 2 * (size_t)EDG, NEX, pa2h, pa2l);

        OpDesc ops3[3] = {
            { pa0h, pa0l, wth + WOFF_WLN(l), wtl + WOFF_WLN(l), HDIM },
            { pa1h, pa1l, wth + WOFF_WLR(l), wtl + WOFF_WLR(l), HDIM },
            { phwh[curb], phwl[curb], wth + WOFF_WSUM(l), wtl + WOFF_WSUM(l), HDIM },
        };
        launch_gemm(ops3, 3, NWIN, HDIM, HDIM, HDIM, bsum + (size_t)l * HDIM, 0.5f, 1,
                    hw[nxt], phwh[nxt], phwl[nxt]);

        OpDesc ops2[2] = {
            { pa2h, pa2l, wth + WOFF_WLC(l), wtl + WOFF_WLC(l), HDIM },
            { pheh[curb], phel[curb], wth + WOFF_WRC(l), wtl + WOFF_WRC(l), HDIM },
        };
        launch_gemm(ops2, 2, NEX, HDIM, HDIM, HDIM, b_close + (size_t)l * HDIM, 1.f, 1,
                    he[nxt], pheh[nxt], phel[nxt]);
        curb = nxt;
    }

    // --- CSRA pooling ---
    gemv_score<<<(NEX + 7) / 8, 256>>>(he[curb], w_pool, score);
    pool_gather<<<MP, 128>>>(he[curb], hw[curb], score,
                             off + 1 * (NWIN + 1), csrc + 1 * (size_t)EDG, NWIN, pth, ptl);

    // out = planes @ W_lin + b_lin
    OpDesc opf = { pth, ptl, wth + WOFF_LIN, wtl + WOFF_LIN, HDIM };
    launch_gemm(&opf, 1, NWIN, 128, NOUT, NOUT, b_lin, 1.f, 0, out, nullptr, nullptr);
}

// round 6
// speedup vs baseline: 1.0449x; 1.0449x over previous
#include <cuda_runtime.h>
#include <cuda_bf16.h>
#include <float.h>
#include <math.h>
#include <stdint.h>

#define NWIN 30000
#define NEX  30000
#define EDG  480000
#define HDIM 512
#define NLAYERS 4
#define KWIN 1949
#define KEXP 100
#define NOUT 100
#define MP   30080
#define KP_WIN 1984

// ================= small fp32 scratch =================
__device__ float g_score[NEX];
__device__ float g_bsum[NLAYERS*HDIM];

// ================= CSR scratch =================
__device__ int g_cnt[3*NWIN];
__device__ int g_off[3*(NWIN+1)];
__device__ int g_cur[3*NWIN];
__device__ int g_csrc[3*EDG];

// ================= bf16 weight buffers [N][Kp], hi & lo =================
#define WOFF_STEP   (HDIM*HDIM)
#define WOFF_LAYER  (5*WOFF_STEP)
#define WOFF_WLN(l) ((l)*WOFF_LAYER + 0*WOFF_STEP)
#define WOFF_WLR(l) ((l)*WOFF_LAYER + 1*WOFF_STEP)
#define WOFF_WSUM(l)((l)*WOFF_LAYER + 2*WOFF_STEP)
#define WOFF_WLC(l) ((l)*WOFF_LAYER + 3*WOFF_STEP)
#define WOFF_WRC(l) ((l)*WOFF_LAYER + 4*WOFF_STEP)
#define WOFF_POST   (NLAYERS*WOFF_LAYER)
#define WOFF_WIN    (WOFF_POST + WOFF_STEP)
#define WOFF_EXP    (WOFF_WIN + HDIM*KP_WIN)
#define WOFF_LIN    (WOFF_EXP + HDIM*128)
#define WTOTAL      (WOFF_LIN + 128*HDIM)
__device__ __align__(256) __nv_bfloat16 g_wth[WTOTAL];
__device__ __align__(256) __nv_bfloat16 g_wtl[WTOTAL];

// ================= bf16 activation plane buffers =================
__device__ __align__(256) __nv_bfloat16 g_bigh[(size_t)MP*KP_WIN];
__device__ __align__(256) __nv_bfloat16 g_bigl[(size_t)MP*KP_WIN];
__device__ __align__(256) __nv_bfloat16 g_pth[(size_t)MP*HDIM];
__device__ __align__(256) __nv_bfloat16 g_ptl[(size_t)MP*HDIM];
__device__ __align__(256) __nv_bfloat16 g_phw0h[(size_t)MP*HDIM];
__device__ __align__(256) __nv_bfloat16 g_phw0l[(size_t)MP*HDIM];
__device__ __align__(256) __nv_bfloat16 g_phw1h[(size_t)MP*HDIM];
__device__ __align__(256) __nv_bfloat16 g_phw1l[(size_t)MP*HDIM];
__device__ __align__(256) __nv_bfloat16 g_phe0h[(size_t)MP*HDIM];
__device__ __align__(256) __nv_bfloat16 g_phe0l[(size_t)MP*HDIM];
__device__ __align__(256) __nv_bfloat16 g_phe1h[(size_t)MP*HDIM];
__device__ __align__(256) __nv_bfloat16 g_phe1l[(size_t)MP*HDIM];
__device__ __align__(256) __nv_bfloat16 g_pa0h[(size_t)MP*HDIM];
__device__ __align__(256) __nv_bfloat16 g_pa0l[(size_t)MP*HDIM];
__device__ __align__(256) __nv_bfloat16 g_pa1h[(size_t)MP*HDIM];
__device__ __align__(256) __nv_bfloat16 g_pa1l[(size_t)MP*HDIM];
__device__ __align__(256) __nv_bfloat16 g_pa2h[(size_t)MP*HDIM];
__device__ __align__(256) __nv_bfloat16 g_pa2l[(size_t)MP*HDIM];

// ================= helpers =================
__device__ __forceinline__ void split2(float v0, float v1, __nv_bfloat162& h, __nv_bfloat162& l)
{
    __nv_bfloat16 h0 = __float2bfloat16_rn(v0);
    __nv_bfloat16 h1 = __float2bfloat16_rn(v1);
    h.x = h0; h.y = h1;
    l.x = __float2bfloat16_rn(v0 - __bfloat162float(h0));
    l.y = __float2bfloat16_rn(v1 - __bfloat162float(h1));
}

// reconstruct 4 floats from hi/lo planes at element offset (8B loads each)
__device__ __forceinline__ float4 recon4(const __nv_bfloat16* __restrict__ h,
                                         const __nv_bfloat16* __restrict__ l,
                                         size_t off)
{
    __nv_bfloat162 h0 = *(const __nv_bfloat162*)(h + off);
    __nv_bfloat162 h1 = *(const __nv_bfloat162*)(h + off + 2);
    __nv_bfloat162 l0 = *(const __nv_bfloat162*)(l + off);
    __nv_bfloat162 l1 = *(const __nv_bfloat162*)(l + off + 2);
    return make_float4(__bfloat162float(h0.x) + __bfloat162float(l0.x),
                       __bfloat162float(h0.y) + __bfloat162float(l0.y),
                       __bfloat162float(h1.x) + __bfloat162float(l1.x),
                       __bfloat162float(h1.y) + __bfloat162float(l1.y));
}

// ================= batched HxH weight conversion =================
#define NBATCH 21
struct ConvBatch {
    const float* W1[NBATCH];
    const float* W2[NBATCH];
    int dstoff[NBATCH];
};

__global__ void conv_w_batch(const __grid_constant__ ConvBatch cb,
                             __nv_bfloat16* __restrict__ ohb,
                             __nv_bfloat16* __restrict__ olb)
{
    __shared__ float t[32][33];
    int z = blockIdx.z;
    const float* W = cb.W1[z];
    const float* W2 = cb.W2[z];
    __nv_bfloat16* oh = ohb + cb.dstoff[z];
    __nv_bfloat16* ol = olb + cb.dstoff[z];
    int k0 = blockIdx.x * 32, n0 = blockIdx.y * 32;
    int tx = threadIdx.x, ty = threadIdx.y;
#pragma unroll
    for (int i = 0; i < 4; i++) {
        int k = k0 + ty + i * 8, n = n0 + tx;
        float v = W[(size_t)k * HDIM + n];
        if (W2) v += W2[(size_t)k * HDIM + n];
        t[ty + i * 8][tx] = v;
    }
    __syncthreads();
#pragma unroll
    for (int i = 0; i < 4; i++) {
        int n = n0 + ty + i * 8, k = k0 + tx;
        float v = t[tx][ty + i * 8];
        __nv_bfloat16 hb = __float2bfloat16_rn(v);
        oh[(size_t)n * HDIM + k] = hb;
        ol[(size_t)n * HDIM + k] = __float2bfloat16_rn(v - __bfloat162float(hb));
    }
}

__global__ void conv_w(const float* __restrict__ W, int K, int N, int Kp,
                       __nv_bfloat16* __restrict__ oh, __nv_bfloat16* __restrict__ ol)
{
    __shared__ float t[32][33];
    int k0 = blockIdx.x * 32, n0 = blockIdx.y * 32;
    int tx = threadIdx.x, ty = threadIdx.y;
#pragma unroll
    for (int i = 0; i < 4; i++) {
        int k = k0 + ty + i * 8, n = n0 + tx;
        float v = 0.f;
        if (k < K && n < N) v = W[(size_t)k * N + n];
        t[ty + i * 8][tx] = v;
    }
    __syncthreads();
#pragma unroll
    for (int i = 0; i < 4; i++) {
        int n = n0 + ty + i * 8, k = k0 + tx;
        float v = t[tx][ty + i * 8];
        __nv_bfloat16 hb = __float2bfloat16_rn(v);
        oh[(size_t)n * Kp + k] = hb;
        ol[(size_t)n * Kp + k] = __float2bfloat16_rn(v - __bfloat162float(hb));
    }
}

__global__ void conv_a(const float* __restrict__ A, int M, int K, int Kp, long long total,
                       __nv_bfloat16* __restrict__ oh, __nv_bfloat16* __restrict__ ol)
{
    long long i = (long long)blockIdx.x * blockDim.x + threadIdx.x;
    if (i >= total) return;
    int m = (int)(i / Kp);
    int k = (int)(i % Kp);
    float v = 0.f;
    if (m < M && k < K) v = A[(size_t)m * K + k];
    __nv_bfloat16 hb = __float2bfloat16_rn(v);
    oh[i] = hb;
    ol[i] = __float2bfloat16_rn(v - __bfloat162float(hb));
}

__global__ void bias_sum_all(const float* a, const float* b, float* o)
{
    int i = blockIdx.x * blockDim.x + threadIdx.x;
    if (i < NLAYERS * HDIM) o[i] = a[i] + b[i];
}

__global__ void zero_int(int* p, int n)
{
    int i = blockIdx.x * blockDim.x + threadIdx.x;
    if (i < n) p[i] = 0;
}

struct PadPtrs { __nv_bfloat16* h[5]; __nv_bfloat16* l[5]; };
__global__ void zero_pad_all(const __grid_constant__ PadPtrs pp)
{
    int i = blockIdx.x * blockDim.x + threadIdx.x;
    const int per = (MP - NWIN) * HDIM;
    int z = i / per;
    if (z >= 5) return;
    int r = i - z * per;
    pp.h[z][(size_t)NWIN * HDIM + r] = __float2bfloat16_rn(0.f);
    pp.l[z][(size_t)NWIN * HDIM + r] = __float2bfloat16_rn(0.f);
}

// ================= CSR build =================
struct EdgePtrs { const int* es[3]; const int* ed[3]; };

__global__ void hist_all(const __grid_constant__ EdgePtrs ep, int* __restrict__ cnt)
{
    int r = blockIdx.y;
    int e = blockIdx.x * blockDim.x + threadIdx.x;
    if (e < EDG) atomicAdd(&cnt[r * NWIN + ep.ed[r][e]], 1);
}

__global__ void scan_all(const int* __restrict__ cnt, int* __restrict__ off,
                         int* __restrict__ cur)
{
    __shared__ int s[1024];
    int r = blockIdx.x;
    const int* c = cnt + r * NWIN;
    int* of = off + r * (NWIN + 1);
    int* cu = cur + r * NWIN;
    int t = threadIdx.x;
    int chunk = (NWIN + 1023) >> 10;
    int b = t * chunk, e = min(b + chunk, NWIN);
    int sum = 0;
    for (int i = b; i < e; i++) sum += c[i];
    s[t] = sum;
    __syncthreads();
    for (int d = 1; d < 1024; d <<= 1) {
        int v = (t >= d) ? s[t - d] : 0;
        __syncthreads();
        s[t] += v;
        __syncthreads();
    }
    int run = (t == 0) ? 0 : s[t - 1];
    for (int i = b; i < e; i++) {
        of[i] = run; cu[i] = run; run += c[i];
    }
    if (t == 0) of[NWIN] = s[1023];
}

__global__ void fill_all(const __grid_constant__ EdgePtrs ep, int* __restrict__ cur,
                         int* __restrict__ csrc)
{
    int r = blockIdx.y;
    int e = blockIdx.x * blockDim.x + threadIdx.x;
    if (e < EDG) {
        int p = atomicAdd(&cur[r * NWIN + ep.ed[r][e]], 1);
        csrc[(size_t)r * EDG + p] = ep.es[r][e];
    }
}

// ================= fused 3-relation gather-mean (reads planes) =================
struct GatherBatch {
    const __nv_bfloat16 *sh[3], *sl[3];
    const int *off[3], *csrc[3];
    int ndst[3];
    __nv_bfloat16 *oh[3], *ol[3];
};

__global__ void gather_all(const __grid_constant__ GatherBatch gb)
{
    int r = blockIdx.y;
    int d = blockIdx.x;
    int t = threadIdx.x;
    const __nv_bfloat16* sh = gb.sh[r];
    const __nv_bfloat16* sl = gb.sl[r];
    float4 acc = make_float4(0.f, 0.f, 0.f, 0.f);
    int deg = 0;
    if (d < gb.ndst[r]) {
        const int* off = gb.off[r];
        const int* csrc = gb.csrc[r];
        int s0 = off[d], s1 = off[d + 1];
        deg = s1 - s0;
        for (int e = s0; e < s1; e++) {
            float4 v = recon4(sh, sl, (size_t)csrc[e] * HDIM + t * 4);
            acc.x += v.x; acc.y += v.y; acc.z += v.z; acc.w += v.w;
        }
    }
    float inv = 1.f / (float)max(deg, 1);
    acc.x *= inv; acc.y *= inv; acc.z *= inv; acc.w *= inv;
    __nv_bfloat162 h0, l0, h1, l1;
    split2(acc.x, acc.y, h0, l0);
    split2(acc.z, acc.w, h1, l1);
    size_t o = (size_t)d * HDIM + t * 4;
    *(__nv_bfloat162*)(gb.oh[r] + o) = h0;
    *(__nv_bfloat162*)(gb.oh[r] + o + 2) = h1;
    *(__nv_bfloat162*)(gb.ol[r] + o) = l0;
    *(__nv_bfloat162*)(gb.ol[r] + o + 2) = l1;
}

// ================= CSR softmax pooling (reads planes) =================
__global__ void pool_gather(const __nv_bfloat16* __restrict__ heh,
                            const __nv_bfloat16* __restrict__ hel,
                            const __nv_bfloat16* __restrict__ hwh,
                            const __nv_bfloat16* __restrict__ hwl,
                            const float* __restrict__ score,
                            const int* __restrict__ off, const int* __restrict__ csrc,
                            int ndst,
                            __nv_bfloat16* __restrict__ oh, __nv_bfloat16* __restrict__ ol)
{
    __shared__ float red[128];
    int d = blockIdx.x;
    int t = threadIdx.x;
    float4 res = make_float4(0.f, 0.f, 0.f, 0.f);
    if (d < ndst) {
        int s0 = off[d], s1 = off[d + 1];
        float m = -FLT_MAX;
        for (int e = s0 + t; e < s1; e += 128) m = fmaxf(m, score[csrc[e]]);
        red[t] = m; __syncthreads();
        for (int w = 64; w; w >>= 1) {
            if (t < w) red[t] = fmaxf(red[t], red[t + w]);
            __syncthreads();
        }
        float smax = red[0];
        __syncthreads();
        float z = 0.f;
        for (int e = s0 + t; e < s1; e += 128) z += expf(score[csrc[e]] - smax);
        red[t] = z; __syncthreads();
        for (int w = 64; w; w >>= 1) {
            if (t < w) red[t] += red[t + w];
            __syncthreads();
        }
        float invz = 1.f / fmaxf(red[0], 1e-12f);
        float4 acc = make_float4(0.f, 0.f, 0.f, 0.f);
        for (int e = s0; e < s1; e++) {
            int sidx = csrc[e];
            float w = expf(score[sidx] - smax) * invz;
            float4 v = recon4(heh, hel, (size_t)sidx * HDIM + t * 4);
            acc.x += w * v.x; acc.y += w * v.y; acc.z += w * v.z; acc.w += w * v.w;
        }
        float4 h = recon4(hwh, hwl, (size_t)d * HDIM + t * 4);
        res.x = h.x + 0.5f * acc.x;
        res.y = h.y + 0.5f * acc.y;
        res.z = h.z + 0.5f * acc.z;
        res.w = h.w + 0.5f * acc.w;
    }
    __nv_bfloat162 h0, l0, h1, l1;
    split2(res.x, res.y, h0, l0);
    split2(res.z, res.w, h1, l1);
    size_t o = (size_t)d * HDIM + t * 4;
    *(__nv_bfloat162*)(oh + o) = h0;
    *(__nv_bfloat162*)(oh + o + 2) = h1;
    *(__nv_bfloat162*)(ol + o) = l0;
    *(__nv_bfloat162*)(ol + o + 2) = l1;
}

__global__ void gemv_score(const __nv_bfloat16* __restrict__ heh,
                           const __nv_bfloat16* __restrict__ hel,
                           const float* __restrict__ w, float* __restrict__ sc)
{
    int row = blockIdx.x * 8 + (threadIdx.x >> 5);
    if (row >= NEX) return;
    int lane = threadIdx.x & 31;
    float s = 0.f;
#pragma unroll
    for (int k = lane * 4; k < HDIM; k += 128) {
        float4 v = recon4(heh, hel, (size_t)row * HDIM + k);
        s += v.x * w[k] + v.y * w[k + 1] + v.z * w[k + 2] + v.w * w[k + 3];
    }
#pragma unroll
    for (int o = 16; o; o >>= 1) s += __shfl_down_sync(0xFFFFFFFFu, s, o);
    if (lane == 0) sc[row] = s;
}

// ================= mma.sync bf16 GEMM (3-pass split, BN=128, 3-stage) ==========
struct GemmArgs {
    const __nv_bfloat16 *Ah[3], *Al[3], *Bh[3], *Bl[3];
    int Kp[3];
    int nops, totChunks;
    int M, Nstore, ldd;
    const float* bias;
    float ps;
    int act;
    float* D;
    __nv_bfloat16 *Dh, *Dl;
};

#define STAGE_BYTES 65536
#define GEMM_SMEM   (3 * STAGE_BYTES)

__device__ __forceinline__ uint32_t smem_u32(const void* p) {
    uint32_t a;
    asm("{ .reg .u64 t; cvta.to.shared.u64 t, %1; cvt.u32.u64 %0, t; }" : "=r"(a) : "l"(p));
    return a;
}
__device__ __forceinline__ void cp16(uint32_t dst, const void* src) {
    asm volatile("cp.async.cg.shared.global [%0], [%1], 16;" :: "r"(dst), "l"(src));
}
__device__ __forceinline__ void cp_commit() { asm volatile("cp.async.commit_group;"); }
__device__ __forceinline__ void cp_wait0() { asm volatile("cp.async.wait_group 0;"); }
__device__ __forceinline__ void cp_wait1() { asm volatile("cp.async.wait_group 1;"); }
__device__ __forceinline__ void cp_wait2() { asm volatile("cp.async.wait_group 2;"); }

__device__ __forceinline__ void ldm_x4(uint32_t* r, uint32_t addr) {
    asm volatile("ldmatrix.sync.aligned.m8n8.x4.shared.b16 {%0,%1,%2,%3}, [%4];"
                 : "=r"(r[0]), "=r"(r[1]), "=r"(r[2]), "=r"(r[3]) : "r"(addr));
}
__device__ __forceinline__ void mma16816(float* c, const uint32_t* a, const uint32_t* b) {
    asm volatile("mma.sync.aligned.m16n8k16.row.col.f32.bf16.bf16.f32 "
                 "{%0,%1,%2,%3},{%4,%5,%6,%7},{%8,%9},{%0,%1,%2,%3};"
                 : "+f"(c[0]), "+f"(c[1]), "+f"(c[2]), "+f"(c[3])
                 : "r"(a[0]), "r"(a[1]), "r"(a[2]), "r"(a[3]), "r"(b[0]), "r"(b[1]));
}

__device__ __forceinline__ void map_oc(const GemmArgs& g, int t, int& o, int& c) {
    o = 0;
    int rem = t;
    while (o < g.nops - 1 && rem >= (g.Kp[o] >> 6)) { rem -= (g.Kp[o] >> 6); o++; }
    c = rem;
}

__device__ __forceinline__ void load_stage(const GemmArgs& g, int t, uint32_t sb,
                                           int tid, int m0, int n0)
{
    int o, c;
    map_oc(g, t, o, c);
    const int Kp = g.Kp[o];
    const int k0 = c << 6;
    {
        const __nv_bfloat16* baseh = g.Ah[o] + (size_t)m0 * Kp + k0;
        const __nv_bfloat16* basel = g.Al[o] + (size_t)m0 * Kp + k0;
#pragma unroll
        for (int it = 0; it < 4; it++) {
            int idx = it * 256 + tid;
            int r = idx >> 3;
            int j = idx & 7;
            uint32_t sw = r * 128 + ((j ^ (r & 7)) << 4);
            cp16(sb + sw, baseh + (size_t)r * Kp + j * 8);
            cp16(sb + 16384 + sw, basel + (size_t)r * Kp + j * 8);
        }
    }
    {
        const __nv_bfloat16* baseh = g.Bh[o] + (size_t)n0 * Kp + k0;
        const __nv_bfloat16* basel = g.Bl[o] + (size_t)n0 * Kp + k0;
#pragma unroll
        for (int it = 0; it < 4; it++) {
            int idx = it * 256 + tid;
            int r = idx >> 3;
            int j = idx & 7;
            uint32_t sw = r * 128 + ((j ^ (r & 7)) << 4);
            cp16(sb + 32768 + sw, baseh + (size_t)r * Kp + j * 8);
            cp16(sb + 49152 + sw, basel + (size_t)r * Kp + j * 8);
        }
    }
    cp_commit();
}

__global__ __launch_bounds__(256, 1) void gemm_mma(const __grid_constant__ GemmArgs g)
{
    extern __shared__ __align__(128) char smem[];
    const uint32_t sbase = smem_u32(smem);
    const int tid = threadIdx.x;
    const int lane = tid & 31;
    const int warp = tid >> 5;
    const int wm = warp >> 2;
    const int wn = warp & 3;
    const int m0 = blockIdx.y * 128;
    const int n0 = blockIdx.x * 128;

    float acc[4][4][4];
#pragma unroll
    for (int i = 0; i < 4; i++)
#pragma unroll
        for (int j = 0; j < 4; j++)
#pragma unroll
            for (int q = 0; q < 4; q++) acc[i][j][q] = 0.f;

    const int sx = lane & 7;
    const int arow = (lane & 7) + ((lane >> 3) & 1) * 8;
    const int khia = (lane >> 4) & 1;
    const int brow = (lane & 7) + ((lane >> 4) & 1) * 8;
    const int khib = (lane >> 3) & 1;

    const int T = g.totChunks;
    load_stage(g, 0, sbase, tid, m0, n0);
    if (T > 1) load_stage(g, 1, sbase + STAGE_BYTES, tid, m0, n0);

    for (int t = 0; t < T; t++) {
        if (t + 2 < T) {
            load_stage(g, t + 2, sbase + ((t + 2) % 3) * STAGE_BYTES, tid, m0, n0);
            cp_wait2();
        } else if (t + 1 < T) {
            cp_wait1();
        } else {
            cp_wait0();
        }
        __syncthreads();

        const uint32_t Ah = sbase + (t % 3) * STAGE_BYTES;
        const uint32_t Al = Ah + 16384;
        const uint32_t Bh = Ah + 32768;
        const uint32_t Bl = Ah + 49152;

#pragma unroll
        for (int ks = 0; ks < 4; ks++) {
            uint32_t ah[4][4], al[4][4], bh[2][4], bl[2][4];
            const uint32_t colA = (uint32_t)(((ks * 2 + khia) ^ sx) << 4);
            const uint32_t colB = (uint32_t)(((ks * 2 + khib) ^ sx) << 4);
#pragma unroll
            for (int mt = 0; mt < 4; mt++) {
                int row = wm * 64 + mt * 16 + arow;
                ldm_x4(ah[mt], Ah + row * 128 + colA);
                ldm_x4(al[mt], Al + row * 128 + colA);
            }
#pragma unroll
            for (int np = 0; np < 2; np++) {
                int row = wn * 32 + np * 16 + brow;
                ldm_x4(bh[np], Bh + row * 128 + colB);
                ldm_x4(bl[np], Bl + row * 128 + colB);
            }
#pragma unroll
            for (int mt = 0; mt < 4; mt++) {
#pragma unroll
                for (int nt = 0; nt < 4; nt++) {
                    const uint32_t* bhf = &bh[nt >> 1][(nt & 1) * 2];
                    const uint32_t* blf = &bl[nt >> 1][(nt & 1) * 2];
                    mma16816(acc[mt][nt], ah[mt], bhf);
                    mma16816(acc[mt][nt], ah[mt], blf);
                    mma16816(acc[mt][nt], al[mt], bhf);
                }
            }
        }
        __syncthreads();
    }

    // ---- epilogue ----
#pragma unroll
    for (int mt = 0; mt < 4; mt++) {
        int row0 = m0 + wm * 64 + mt * 16 + (lane >> 2);
#pragma unroll
        for (int nt = 0; nt < 4; nt++) {
            int col = n0 + wn * 32 + nt * 8 + (lane & 3) * 2;
            if (col >= g.Nstore) continue;
            float b0 = 0.f, b1 = 0.f;
            if (g.bias) {
                b0 = g.bias[col];
                if (col + 1 < g.Nstore) b1 = g.bias[col + 1];
            }
#pragma unroll
            for (int rr = 0; rr < 2; rr++) {
                int r = row0 + rr * 8;
                if (r >= g.M) continue;
                float v0 = (acc[mt][nt][rr * 2 + 0] + b0) * g.ps;
                float v1 = (acc[mt][nt][rr * 2 + 1] + b1) * g.ps;
                if (g.act) {
                    v0 = v0 > 0.f ? v0 : 0.2f * v0;
                    v1 = v1 > 0.f ? v1 : 0.2f * v1;
                }
                if (g.D) {
                    float* dp = g.D + (size_t)r * g.ldd + col;
                    if (col + 1 < g.Nstore) *(float2*)dp = make_float2(v0, v1);
                    else *dp = v0;
                }
                if (g.Dh) {
                    __nv_bfloat162 hh, ll;
                    split2(v0, v1, hh, ll);
                    size_t po = (size_t)r * HDIM + col;
                    *(__nv_bfloat162*)(g.Dh + po) = hh;
                    *(__nv_bfloat162*)(g.Dl + po) = ll;
                }
            }
        }
    }
}

// ================= host orchestration =================
struct OpDesc {
    const __nv_bfloat16 *Ah, *Al, *Bh, *Bl;
    int Kp;
};

static void launch_gemm(const OpDesc* ops, int nops, int M, int Np, int Nstore,
                        int ldd, const float* bias, float ps, int act,
                        float* D, __nv_bfloat16* Dh, __nv_bfloat16* Dl)
{
    GemmArgs g;
    int T = 0;
    for (int o = 0; o < nops; o++) {
        g.Ah[o] = ops[o].Ah; g.Al[o] = ops[o].Al;
        g.Bh[o] = ops[o].Bh; g.Bl[o] = ops[o].Bl;
        g.Kp[o] = ops[o].Kp;
        T += ops[o].Kp / 64;
    }
    g.nops = nops; g.totChunks = T;
    g.M = M; g.Nstore = Nstore; g.ldd = ldd;
    g.bias = bias; g.ps = ps; g.act = act;
    g.D = D; g.Dh = Dh; g.Dl = Dl;
    dim3 grid(Np / 128, (M + 127) / 128);
    gemm_mma<<<grid, 256, GEMM_SMEM>>>(g);
}

extern "C" void kernel_launch(void* const* d_in, const int* in_sizes, int n_in,
                              void* d_out, int out_size)
{
    const float* x_window  = (const float*)d_in[0];
    const float* x_example = (const float*)d_in[1];
    const int*   e_near    = (const int*)d_in[2];
    const int*   e_close   = (const int*)d_in[3];
    const int*   e_refer   = (const int*)d_in[4];
    const float* W_win     = (const float*)d_in[5];
    const float* W_exp     = (const float*)d_in[6];
    const float* W_post    = (const float*)d_in[7];
    const float* Wl_near   = (const float*)d_in[9];
    const float* Wr_near   = (const float*)d_in[10];
    const float* b_near    = (const float*)d_in[11];
    const float* Wl_close  = (const float*)d_in[12];
    const float* Wr_close  = (const float*)d_in[13];
    const float* b_close   = (const float*)d_in[14];
    const float* Wl_refer  = (const float*)d_in[15];
    const float* Wr_refer  = (const float*)d_in[16];
    const float* b_refer   = (const float*)d_in[17];
    const float* w_pool    = (const float*)d_in[18];
    const float* W_lin     = (const float*)d_in[19];
    const float* b_lin     = (const float*)d_in[20];
    float* out = (float*)d_out;

    cudaFuncSetAttribute(gemm_mma, cudaFuncAttributeMaxDynamicSharedMemorySize, GEMM_SMEM);

    float *score, *bsum;
    int *cnt, *off, *cur, *csrc;
    __nv_bfloat16 *wth, *wtl, *bigh, *bigl, *pth, *ptl;
    __nv_bfloat16 *phwh[2], *phwl[2], *pheh[2], *phel[2];
    __nv_bfloat16 *pa0h, *pa0l, *pa1h, *pa1l, *pa2h, *pa2l;
    cudaGetSymbolAddress((void**)&score, g_score);
    cudaGetSymbolAddress((void**)&bsum, g_bsum);
    cudaGetSymbolAddress((void**)&cnt, g_cnt);
    cudaGetSymbolAddress((void**)&off, g_off);
    cudaGetSymbolAddress((void**)&cur, g_cur);
    cudaGetSymbolAddress((void**)&csrc, g_csrc);
    cudaGetSymbolAddress((void**)&wth, g_wth);
    cudaGetSymbolAddress((void**)&wtl, g_wtl);
    cudaGetSymbolAddress((void**)&bigh, g_bigh);
    cudaGetSymbolAddress((void**)&bigl, g_bigl);
    cudaGetSymbolAddress((void**)&pth, g_pth);
    cudaGetSymbolAddress((void**)&ptl, g_ptl);
    cudaGetSymbolAddress((void**)&phwh[0], g_phw0h);
    cudaGetSymbolAddress((void**)&phwl[0], g_phw0l);
    cudaGetSymbolAddress((void**)&phwh[1], g_phw1h);
    cudaGetSymbolAddress((void**)&phwl[1], g_phw1l);
    cudaGetSymbolAddress((void**)&pheh[0], g_phe0h);
    cudaGetSymbolAddress((void**)&phel[0], g_phe0l);
    cudaGetSymbolAddress((void**)&pheh[1], g_phe1h);
    cudaGetSymbolAddress((void**)&phel[1], g_phe1l);
    cudaGetSymbolAddress((void**)&pa0h, g_pa0h);
    cudaGetSymbolAddress((void**)&pa0l, g_pa0l);
    cudaGetSymbolAddress((void**)&pa1h, g_pa1h);
    cudaGetSymbolAddress((void**)&pa1l, g_pa1l);
    cudaGetSymbolAddress((void**)&pa2h, g_pa2h);
    cudaGetSymbolAddress((void**)&pa2l, g_pa2l);

    const unsigned edge_blocks = (EDG + 255) / 256;

    // --- batched weight conversion ---
    {
        ConvBatch cb;
        for (int l = 0; l < NLAYERS; l++) {
            size_t s = (size_t)l * HDIM * HDIM;
            cb.W1[l * 5 + 0] = Wl_near + s;  cb.W2[l * 5 + 0] = nullptr;      cb.dstoff[l * 5 + 0] = WOFF_WLN(l);
            cb.W1[l * 5 + 1] = Wl_refer + s; cb.W2[l * 5 + 1] = nullptr;      cb.dstoff[l * 5 + 1] = WOFF_WLR(l);
            cb.W1[l * 5 + 2] = Wr_near + s;  cb.W2[l * 5 + 2] = Wr_refer + s; cb.dstoff[l * 5 + 2] = WOFF_WSUM(l);
            cb.W1[l * 5 + 3] = Wl_close + s; cb.W2[l * 5 + 3] = nullptr;      cb.dstoff[l * 5 + 3] = WOFF_WLC(l);
            cb.W1[l * 5 + 4] = Wr_close + s; cb.W2[l * 5 + 4] = nullptr;      cb.dstoff[l * 5 + 4] = WOFF_WRC(l);
        }
        cb.W1[20] = W_post; cb.W2[20] = nullptr; cb.dstoff[20] = WOFF_POST;
        dim3 blk(32, 8);
        dim3 gB(HDIM / 32, HDIM / 32, NBATCH);
        conv_w_batch<<<gB, blk>>>(cb, wth, wtl);

        dim3 gWIN(KP_WIN / 32, HDIM / 32);
        conv_w<<<gWIN, blk>>>(W_win, KWIN, HDIM, KP_WIN, wth + WOFF_WIN, wtl + WOFF_WIN);
        dim3 gEXP(128 / 32, HDIM / 32);
        conv_w<<<gEXP, blk>>>(W_exp, KEXP, HDIM, 128, wth + WOFF_EXP, wtl + WOFF_EXP);
        dim3 gLIN(HDIM / 32, 128 / 32);
        conv_w<<<gLIN, blk>>>(W_lin, HDIM, NOUT, HDIM, wth + WOFF_LIN, wtl + WOFF_LIN);
        bias_sum_all<<<(NLAYERS * HDIM + 255) / 256, 256>>>(b_near, b_refer, bsum);
    }

    // --- zero pad rows [NWIN, MP) of GEMM-written plane buffers ---
    {
        PadPtrs pp;
        pp.h[0] = pth;     pp.l[0] = ptl;
        pp.h[1] = phwh[0]; pp.l[1] = phwl[0];
        pp.h[2] = phwh[1]; pp.l[2] = phwl[1];
        pp.h[3] = pheh[0]; pp.l[3] = phel[0];
        pp.h[4] = pheh[1]; pp.l[4] = phel[1];
        int tot = 5 * (MP - NWIN) * HDIM;
        zero_pad_all<<<(tot + 255) / 256, 256>>>(pp);
    }

    // --- CSR build ---
    {
        EdgePtrs ep;
        ep.es[0] = e_near;  ep.ed[0] = e_near + EDG;
        ep.es[1] = e_refer; ep.ed[1] = e_refer + EDG;
        ep.es[2] = e_close; ep.ed[2] = e_close + EDG;
        zero_int<<<(3 * NWIN + 255) / 256, 256>>>(cnt, 3 * NWIN);
        dim3 ge(edge_blocks, 3);
        hist_all<<<ge, 256>>>(ep, cnt);
        scan_all<<<3, 1024>>>(cnt, off, cur);
        fill_all<<<ge, 256>>>(ep, cur, csrc);
    }

    // --- input projections ---
    {
        long long tot = (long long)MP * 128;
        conv_a<<<(unsigned)((tot + 255) / 256), 256>>>(x_example, NEX, KEXP, 128, tot, pa0h, pa0l);
        OpDesc op = { pa0h, pa0l, wth + WOFF_EXP, wtl + WOFF_EXP, 128 };
        launch_gemm(&op, 1, NEX, HDIM, HDIM, HDIM, nullptr, 1.f, 1, nullptr, pth, ptl);
        op = { pth, ptl, wth + WOFF_POST, wtl + WOFF_POST, HDIM };
        launch_gemm(&op, 1, NEX, HDIM, HDIM, HDIM, nullptr, 1.f, 1, nullptr, pheh[0], phel[0]);

        tot = (long long)MP * KP_WIN;
        conv_a<<<(unsigned)((tot + 255) / 256), 256>>>(x_window, NWIN, KWIN, KP_WIN, tot, bigh, bigl);
        OpDesc op2 = { bigh, bigl, wth + WOFF_WIN, wtl + WOFF_WIN, KP_WIN };
        launch_gemm(&op2, 1, NWIN, HDIM, HDIM, HDIM, nullptr, 1.f, 1, nullptr, pth, ptl);
        op2 = { pth, ptl, wth + WOFF_POST, wtl + WOFF_POST, HDIM };
        launch_gemm(&op2, 1, NWIN, HDIM, HDIM, HDIM, nullptr, 1.f, 1, nullptr, phwh[0], phwl[0]);
    }

    // --- SAGE layers ---
    int curb = 0;
    for (int l = 0; l < NLAYERS; l++) {
        int nxt = curb ^ 1;
        GatherBatch gb;
        gb.sh[0] = phwh[curb]; gb.sl[0] = phwl[curb];
        gb.sh[1] = pheh[curb]; gb.sl[1] = phel[curb];
        gb.sh[2] = pheh[curb]; gb.sl[2] = phel[curb];
        gb.off[0] = off + 0 * (NWIN + 1); gb.csrc[0] = csrc + 0 * (size_t)EDG; gb.ndst[0] = NWIN;
        gb.off[1] = off + 1 * (NWIN + 1); gb.csrc[1] = csrc + 1 * (size_t)EDG; gb.ndst[1] = NWIN;
        gb.off[2] = off + 2 * (NWIN + 1); gb.csrc[2] = csrc + 2 * (size_t)EDG; gb.ndst[2] = NEX;
        gb.oh[0] = pa0h; gb.ol[0] = pa0l;
        gb.oh[1] = pa1h; gb.ol[1] = pa1l;
        gb.oh[2] = pa2h; gb.ol[2] = pa2l;
        dim3 gg(MP, 3);
        gather_all<<<gg, 128>>>(gb);

        OpDesc ops3[3] = {
            { pa0h, pa0l, wth + WOFF_WLN(l), wtl + WOFF_WLN(l), HDIM },
            { pa1h, pa1l, wth + WOFF_WLR(l), wtl + WOFF_WLR(l), HDIM },
            { phwh[curb], phwl[curb], wth + WOFF_WSUM(l), wtl + WOFF_WSUM(l), HDIM },
        };
        launch_gemm(ops3, 3, NWIN, HDIM, HDIM, HDIM, bsum + (size_t)l * HDIM, 0.5f, 1,
                    nullptr, phwh[nxt], phwl[nxt]);

        OpDesc ops2[2] = {
            { pa2h, pa2l, wth + WOFF_WLC(l), wtl + WOFF_WLC(l), HDIM },
            { pheh[curb], phel[curb], wth + WOFF_WRC(l), wtl + WOFF_WRC(l), HDIM },
        };
        launch_gemm(ops2, 2, NEX, HDIM, HDIM, HDIM, b_close + (size_t)l * HDIM, 1.f, 1,
                    nullptr, pheh[nxt], phel[nxt]);
        curb = nxt;
    }

    // --- CSRA pooling ---
    gemv_score<<<(NEX + 7) / 8, 256>>>(pheh[curb], phel[curb], w_pool, score);
    pool_gather<<<MP, 128>>>(pheh[curb], phel[curb], phwh[curb], phwl[curb], score,
                             off + 1 * (NWIN + 1), csrc + 1 * (size_t)EDG, NWIN, pth, ptl);

    // out = planes @ W_lin + b_lin
    OpDesc opf = { pth, ptl, wth + WOFF_LIN, wtl + WOFF_LIN, HDIM };
    launch_gemm(&opf, 1, NWIN, 128, NOUT, NOUT, b_lin, 1.f, 0, out, nullptr, nullptr);
}

// round 7
// speedup vs baseline: 1.0571x; 1.0117x over previous
#include <cuda_runtime.h>
#include <cuda_bf16.h>
#include <float.h>
#include <math.h>
#include <stdint.h>

#define NWIN 30000
#define NEX  30000
#define EDG  480000
#define HDIM 512
#define NLAYERS 4
#define KWIN 1949
#define KEXP 100
#define NOUT 100
#define MP   30080
#define KP_WIN 1984

// ================= small fp32 scratch =================
__device__ float g_score[NEX];
__device__ float g_bsum[NLAYERS*HDIM];

// ================= CSR scratch =================
__device__ int g_cnt[3*NWIN];
__device__ int g_off[3*(NWIN+1)];
__device__ int g_cur[3*NWIN];
__device__ int g_csrc[3*EDG];

// ================= bf16 weight buffers [N][Kp], hi & lo =================
#define WOFF_STEP   (HDIM*HDIM)
#define WOFF_LAYER  (5*WOFF_STEP)
#define WOFF_WLN(l) ((l)*WOFF_LAYER + 0*WOFF_STEP)
#define WOFF_WLR(l) ((l)*WOFF_LAYER + 1*WOFF_STEP)
#define WOFF_WSUM(l)((l)*WOFF_LAYER + 2*WOFF_STEP)
#define WOFF_WLC(l) ((l)*WOFF_LAYER + 3*WOFF_STEP)
#define WOFF_WRC(l) ((l)*WOFF_LAYER + 4*WOFF_STEP)
#define WOFF_POST   (NLAYERS*WOFF_LAYER)
#define WOFF_WIN    (WOFF_POST + WOFF_STEP)
#define WOFF_EXP    (WOFF_WIN + HDIM*KP_WIN)
#define WOFF_LIN    (WOFF_EXP + HDIM*128)
#define WTOTAL      (WOFF_LIN + 128*HDIM)
__device__ __align__(256) __nv_bfloat16 g_wth[WTOTAL];
__device__ __align__(256) __nv_bfloat16 g_wtl[WTOTAL];

// ================= bf16 activation plane buffers =================
__device__ __align__(256) __nv_bfloat16 g_bigh[(size_t)MP*KP_WIN];
__device__ __align__(256) __nv_bfloat16 g_bigl[(size_t)MP*KP_WIN];
__device__ __align__(256) __nv_bfloat16 g_pth[(size_t)MP*HDIM];
__device__ __align__(256) __nv_bfloat16 g_ptl[(size_t)MP*HDIM];
__device__ __align__(256) __nv_bfloat16 g_phw0h[(size_t)MP*HDIM];
__device__ __align__(256) __nv_bfloat16 g_phw0l[(size_t)MP*HDIM];
__device__ __align__(256) __nv_bfloat16 g_phw1h[(size_t)MP*HDIM];
__device__ __align__(256) __nv_bfloat16 g_phw1l[(size_t)MP*HDIM];
__device__ __align__(256) __nv_bfloat16 g_phe0h[(size_t)MP*HDIM];
__device__ __align__(256) __nv_bfloat16 g_phe0l[(size_t)MP*HDIM];
__device__ __align__(256) __nv_bfloat16 g_phe1h[(size_t)MP*HDIM];
__device__ __align__(256) __nv_bfloat16 g_phe1l[(size_t)MP*HDIM];
__device__ __align__(256) __nv_bfloat16 g_pa0h[(size_t)MP*HDIM];
__device__ __align__(256) __nv_bfloat16 g_pa0l[(size_t)MP*HDIM];
__device__ __align__(256) __nv_bfloat16 g_pa1h[(size_t)MP*HDIM];
__device__ __align__(256) __nv_bfloat16 g_pa1l[(size_t)MP*HDIM];
__device__ __align__(256) __nv_bfloat16 g_pa2h[(size_t)MP*HDIM];
__device__ __align__(256) __nv_bfloat16 g_pa2l[(size_t)MP*HDIM];

// ================= helpers =================
__device__ __forceinline__ void split2(float v0, float v1, __nv_bfloat162& h, __nv_bfloat162& l)
{
    __nv_bfloat16 h0 = __float2bfloat16_rn(v0);
    __nv_bfloat16 h1 = __float2bfloat16_rn(v1);
    h.x = h0; h.y = h1;
    l.x = __float2bfloat16_rn(v0 - __bfloat162float(h0));
    l.y = __float2bfloat16_rn(v1 - __bfloat162float(h1));
}

__device__ __forceinline__ float4 recon4(const __nv_bfloat16* __restrict__ h,
                                         const __nv_bfloat16* __restrict__ l,
                                         size_t off)
{
    __nv_bfloat162 h0 = *(const __nv_bfloat162*)(h + off);
    __nv_bfloat162 h1 = *(const __nv_bfloat162*)(h + off + 2);
    __nv_bfloat162 l0 = *(const __nv_bfloat162*)(l + off);
    __nv_bfloat162 l1 = *(const __nv_bfloat162*)(l + off + 2);
    return make_float4(__bfloat162float(h0.x) + __bfloat162float(l0.x),
                       __bfloat162float(h0.y) + __bfloat162float(l0.y),
                       __bfloat162float(h1.x) + __bfloat162float(l1.x),
                       __bfloat162float(h1.y) + __bfloat162float(l1.y));
}

// write 8 fp32 values as hi/lo bf16 planes (16B each)
__device__ __forceinline__ void split_store8(float* v, __nv_bfloat16* oh, __nv_bfloat16* ol,
                                             size_t off)
{
    __nv_bfloat162 hh[4], ll[4];
#pragma unroll
    for (int j = 0; j < 4; j++) split2(v[j * 2], v[j * 2 + 1], hh[j], ll[j]);
    *(uint4*)(oh + off) = *(uint4*)hh;
    *(uint4*)(ol + off) = *(uint4*)ll;
}

// ================= batched HxH weight conversion =================
#define NBATCH 21
struct ConvBatch {
    const float* W1[NBATCH];
    const float* W2[NBATCH];
    int dstoff[NBATCH];
};

__global__ void conv_w_batch(const __grid_constant__ ConvBatch cb,
                             __nv_bfloat16* __restrict__ ohb,
                             __nv_bfloat16* __restrict__ olb)
{
    __shared__ float t[32][33];
    int z = blockIdx.z;
    const float* W = cb.W1[z];
    const float* W2 = cb.W2[z];
    __nv_bfloat16* oh = ohb + cb.dstoff[z];
    __nv_bfloat16* ol = olb + cb.dstoff[z];
    int k0 = blockIdx.x * 32, n0 = blockIdx.y * 32;
    int tx = threadIdx.x, ty = threadIdx.y;
#pragma unroll
    for (int i = 0; i < 4; i++) {
        int k = k0 + ty + i * 8, n = n0 + tx;
        float v = W[(size_t)k * HDIM + n];
        if (W2) v += W2[(size_t)k * HDIM + n];
        t[ty + i * 8][tx] = v;
    }
    __syncthreads();
#pragma unroll
    for (int i = 0; i < 4; i++) {
        int n = n0 + ty + i * 8, k = k0 + tx;
        float v = t[tx][ty + i * 8];
        __nv_bfloat16 hb = __float2bfloat16_rn(v);
        oh[(size_t)n * HDIM + k] = hb;
        ol[(size_t)n * HDIM + k] = __float2bfloat16_rn(v - __bfloat162float(hb));
    }
}

__global__ void conv_w(const float* __restrict__ W, int K, int N, int Kp,
                       __nv_bfloat16* __restrict__ oh, __nv_bfloat16* __restrict__ ol)
{
    __shared__ float t[32][33];
    int k0 = blockIdx.x * 32, n0 = blockIdx.y * 32;
    int tx = threadIdx.x, ty = threadIdx.y;
#pragma unroll
    for (int i = 0; i < 4; i++) {
        int k = k0 + ty + i * 8, n = n0 + tx;
        float v = 0.f;
        if (k < K && n < N) v = W[(size_t)k * N + n];
        t[ty + i * 8][tx] = v;
    }
    __syncthreads();
#pragma unroll
    for (int i = 0; i < 4; i++) {
        int n = n0 + ty + i * 8, k = k0 + tx;
        float v = t[tx][ty + i * 8];
        __nv_bfloat16 hb = __float2bfloat16_rn(v);
        oh[(size_t)n * Kp + k] = hb;
        ol[(size_t)n * Kp + k] = __float2bfloat16_rn(v - __bfloat162float(hb));
    }
}

__global__ void conv_a(const float* __restrict__ A, int M, int K, int Kp, long long total,
                       __nv_bfloat16* __restrict__ oh, __nv_bfloat16* __restrict__ ol)
{
    long long i = (long long)blockIdx.x * blockDim.x + threadIdx.x;
    if (i >= total) return;
    int m = (int)(i / Kp);
    int k = (int)(i % Kp);
    float v = 0.f;
    if (m < M && k < K) v = A[(size_t)m * K + k];
    __nv_bfloat16 hb = __float2bfloat16_rn(v);
    oh[i] = hb;
    ol[i] = __float2bfloat16_rn(v - __bfloat162float(hb));
}

__global__ void bias_sum_all(const float* a, const float* b, float* o)
{
    int i = blockIdx.x * blockDim.x + threadIdx.x;
    if (i < NLAYERS * HDIM) o[i] = a[i] + b[i];
}

__global__ void zero_int(int* p, int n)
{
    int i = blockIdx.x * blockDim.x + threadIdx.x;
    if (i < n) p[i] = 0;
}

#define NPAD 8
struct PadPtrs { __nv_bfloat16* h[NPAD]; __nv_bfloat16* l[NPAD]; };
__global__ void zero_pad_all(const __grid_constant__ PadPtrs pp)
{
    int i = blockIdx.x * blockDim.x + threadIdx.x;
    const int per = (MP - NWIN) * HDIM;
    int z = i / per;
    if (z >= NPAD) return;
    int r = i - z * per;
    pp.h[z][(size_t)NWIN * HDIM + r] = __float2bfloat16_rn(0.f);
    pp.l[z][(size_t)NWIN * HDIM + r] = __float2bfloat16_rn(0.f);
}

// ================= CSR build =================
struct EdgePtrs { const int* es[3]; const int* ed[3]; };

__global__ void hist_all(const __grid_constant__ EdgePtrs ep, int* __restrict__ cnt)
{
    int r = blockIdx.y;
    int e = blockIdx.x * blockDim.x + threadIdx.x;
    if (e < EDG) atomicAdd(&cnt[r * NWIN + ep.ed[r][e]], 1);
}

__global__ void scan_all(const int* __restrict__ cnt, int* __restrict__ off,
                         int* __restrict__ cur)
{
    __shared__ int s[1024];
    int r = blockIdx.x;
    const int* c = cnt + r * NWIN;
    int* of = off + r * (NWIN + 1);
    int* cu = cur + r * NWIN;
    int t = threadIdx.x;
    int chunk = (NWIN + 1023) >> 10;
    int b = t * chunk, e = min(b + chunk, NWIN);
    int sum = 0;
    for (int i = b; i < e; i++) sum += c[i];
    s[t] = sum;
    __syncthreads();
    for (int d = 1; d < 1024; d <<= 1) {
        int v = (t >= d) ? s[t - d] : 0;
        __syncthreads();
        s[t] += v;
        __syncthreads();
    }
    int run = (t == 0) ? 0 : s[t - 1];
    for (int i = b; i < e; i++) {
        of[i] = run; cu[i] = run; run += c[i];
    }
    if (t == 0) of[NWIN] = s[1023];
}

__global__ void fill_all(const __grid_constant__ EdgePtrs ep, int* __restrict__ cur,
                         int* __restrict__ csrc)
{
    int r = blockIdx.y;
    int e = blockIdx.x * blockDim.x + threadIdx.x;
    if (e < EDG) {
        int p = atomicAdd(&cur[r * NWIN + ep.ed[r][e]], 1);
        csrc[(size_t)r * EDG + p] = ep.es[r][e];
    }
}

// ================= fused 3-relation gather-mean (hi/lo thread split) =================
struct GatherBatch {
    const __nv_bfloat16 *sh[3], *sl[3];
    const int *off[3], *csrc[3];
    int ndst[3];
    __nv_bfloat16 *oh[3], *ol[3];
};

__global__ void gather_all(const __grid_constant__ GatherBatch gb)
{
    __shared__ float sm[512];
    int r = blockIdx.y;
    int d = blockIdx.x;
    int t = threadIdx.x;
    const bool isLo = t >= 64;
    const int c = (t & 63) * 8;          // 8 bf16 = 16B per thread
    const __nv_bfloat16* src = isLo ? gb.sl[r] : gb.sh[r];

    float acc[8];
#pragma unroll
    for (int j = 0; j < 8; j++) acc[j] = 0.f;
    int deg = 0;
    if (d < gb.ndst[r]) {
        const int* off = gb.off[r];
        const int* cs = gb.csrc[r];
        int s0 = off[d], s1 = off[d + 1];
        deg = s1 - s0;
        for (int e = s0; e < s1; e++) {
            uint4 q = *(const uint4*)(src + (size_t)cs[e] * HDIM + c);
            const __nv_bfloat162* b2 = (const __nv_bfloat162*)&q;
#pragma unroll
            for (int j = 0; j < 4; j++) {
                acc[j * 2 + 0] += __bfloat162float(b2[j].x);
                acc[j * 2 + 1] += __bfloat162float(b2[j].y);
            }
        }
    }
    if (isLo) {
#pragma unroll
        for (int j = 0; j < 8; j++) sm[(t - 64) * 8 + j] = acc[j];
    }
    __syncthreads();
    if (!isLo) {
        float inv = 1.f / (float)max(deg, 1);
        float v[8];
#pragma unroll
        for (int j = 0; j < 8; j++) v[j] = (acc[j] + sm[t * 8 + j]) * inv;
        split_store8(v, gb.oh[r], gb.ol[r], (size_t)d * HDIM + c);
    }
}

// ================= CSR softmax pooling (hi/lo thread split) =================
__global__ void pool_gather(const __nv_bfloat16* __restrict__ heh,
                            const __nv_bfloat16* __restrict__ hel,
                            const __nv_bfloat16* __restrict__ hwh,
                            const __nv_bfloat16* __restrict__ hwl,
                            const float* __restrict__ score,
                            const int* __restrict__ off, const int* __restrict__ csrc,
                            int ndst,
                            __nv_bfloat16* __restrict__ oh, __nv_bfloat16* __restrict__ ol)
{
    __shared__ float red[128];
    __shared__ float sm[512];
    int d = blockIdx.x;
    int t = threadIdx.x;
    int s0 = 0, s1 = 0;
    if (d < ndst) { s0 = off[d]; s1 = off[d + 1]; }

    float m = -FLT_MAX;
    for (int e = s0 + t; e < s1; e += 128) m = fmaxf(m, score[csrc[e]]);
    red[t] = m; __syncthreads();
    for (int w = 64; w; w >>= 1) {
        if (t < w) red[t] = fmaxf(red[t], red[t + w]);
        __syncthreads();
    }
    float smax = red[0];
    __syncthreads();
    float z = 0.f;
    for (int e = s0 + t; e < s1; e += 128) z += expf(score[csrc[e]] - smax);
    red[t] = z; __syncthreads();
    for (int w = 64; w; w >>= 1) {
        if (t < w) red[t] += red[t + w];
        __syncthreads();
    }
    float invz = 1.f / fmaxf(red[0], 1e-12f);

    const bool isLo = t >= 64;
    const int c = (t & 63) * 8;
    const __nv_bfloat16* src = isLo ? hel : heh;
    float acc[8];
#pragma unroll
    for (int j = 0; j < 8; j++) acc[j] = 0.f;
    for (int e = s0; e < s1; e++) {
        int sidx = csrc[e];
        float w = expf(score[sidx] - smax) * invz;
        uint4 q = *(const uint4*)(src + (size_t)sidx * HDIM + c);
        const __nv_bfloat162* b2 = (const __nv_bfloat162*)&q;
#pragma unroll
        for (int j = 0; j < 4; j++) {
            acc[j * 2 + 0] += w * __bfloat162float(b2[j].x);
            acc[j * 2 + 1] += w * __bfloat162float(b2[j].y);
        }
    }
    if (isLo) {
#pragma unroll
        for (int j = 0; j < 8; j++) sm[(t - 64) * 8 + j] = acc[j];
    }
    __syncthreads();
    if (!isLo) {
        size_t o = (size_t)d * HDIM + c;
        uint4 qh = *(const uint4*)(hwh + o);
        uint4 ql = *(const uint4*)(hwl + o);
        const __nv_bfloat162* bh = (const __nv_bfloat162*)&qh;
        const __nv_bfloat162* bl = (const __nv_bfloat162*)&ql;
        float v[8];
#pragma unroll
        for (int j = 0; j < 4; j++) {
            v[j * 2 + 0] = __bfloat162float(bh[j].x) + __bfloat162float(bl[j].x)
                         + 0.5f * (acc[j * 2 + 0] + sm[t * 8 + j * 2 + 0]);
            v[j * 2 + 1] = __bfloat162float(bh[j].y) + __bfloat162float(bl[j].y)
                         + 0.5f * (acc[j * 2 + 1] + sm[t * 8 + j * 2 + 1]);
        }
        split_store8(v, oh, ol, o);
    }
}

__global__ void gemv_score(const __nv_bfloat16* __restrict__ heh,
                           const __nv_bfloat16* __restrict__ hel,
                           const float* __restrict__ w, float* __restrict__ sc)
{
    int row = blockIdx.x * 8 + (threadIdx.x >> 5);
    if (row >= NEX) return;
    int lane = threadIdx.x & 31;
    float s = 0.f;
#pragma unroll
    for (int k = lane * 4; k < HDIM; k += 128) {
        float4 v = recon4(heh, hel, (size_t)row * HDIM + k);
        s += v.x * w[k] + v.y * w[k + 1] + v.z * w[k + 2] + v.w * w[k + 3];
    }
#pragma unroll
    for (int o = 16; o; o >>= 1) s += __shfl_down_sync(0xFFFFFFFFu, s, o);
    if (lane == 0) sc[row] = s;
}

// ================= mma.sync bf16 GEMM (3-pass split, BN=128, 2-stage) ==========
struct GemmArgs {
    const __nv_bfloat16 *Ah[3], *Al[3], *Bh[3], *Bl[3];
    int Kp[3];
    int nops, totChunks;
    int M, Nstore, ldd;
    const float* bias;
    float ps;
    int act;
    float* D;
    __nv_bfloat16 *Dh, *Dl;
};
struct GemmPair { GemmArgs g[2]; };

#define STAGE_BYTES 65536
#define GEMM_SMEM   (2 * STAGE_BYTES)

__device__ __forceinline__ uint32_t smem_u32(const void* p) {
    uint32_t a;
    asm("{ .reg .u64 t; cvta.to.shared.u64 t, %1; cvt.u32.u64 %0, t; }" : "=r"(a) : "l"(p));
    return a;
}
__device__ __forceinline__ void cp16(uint32_t dst, const void* src) {
    asm volatile("cp.async.cg.shared.global [%0], [%1], 16;" :: "r"(dst), "l"(src));
}
__device__ __forceinline__ void cp_commit() { asm volatile("cp.async.commit_group;"); }
__device__ __forceinline__ void cp_wait0() { asm volatile("cp.async.wait_group 0;"); }
__device__ __forceinline__ void cp_wait1() { asm volatile("cp.async.wait_group 1;"); }

__device__ __forceinline__ void ldm_x4(uint32_t* r, uint32_t addr) {
    asm volatile("ldmatrix.sync.aligned.m8n8.x4.shared.b16 {%0,%1,%2,%3}, [%4];"
                 : "=r"(r[0]), "=r"(r[1]), "=r"(r[2]), "=r"(r[3]) : "r"(addr));
}
__device__ __forceinline__ void mma16816(float* c, const uint32_t* a, const uint32_t* b) {
    asm volatile("mma.sync.aligned.m16n8k16.row.col.f32.bf16.bf16.f32 "
                 "{%0,%1,%2,%3},{%4,%5,%6,%7},{%8,%9},{%0,%1,%2,%3};"
                 : "+f"(c[0]), "+f"(c[1]), "+f"(c[2]), "+f"(c[3])
                 : "r"(a[0]), "r"(a[1]), "r"(a[2]), "r"(a[3]), "r"(b[0]), "r"(b[1]));
}

__device__ __forceinline__ void map_oc(const GemmArgs& g, int t, int& o, int& c) {
    o = 0;
    int rem = t;
    while (o < g.nops - 1 && rem >= (g.Kp[o] >> 6)) { rem -= (g.Kp[o] >> 6); o++; }
    c = rem;
}

__device__ __forceinline__ void load_stage(const GemmArgs& g, int t, uint32_t sb,
                                           int tid, int m0, int n0)
{
    int o, c;
    map_oc(g, t, o, c);
    const int Kp = g.Kp[o];
    const int k0 = c << 6;
    {
        const __nv_bfloat16* baseh = g.Ah[o] + (size_t)m0 * Kp + k0;
        const __nv_bfloat16* basel = g.Al[o] + (size_t)m0 * Kp + k0;
#pragma unroll
        for (int it = 0; it < 4; it++) {
            int idx = it * 256 + tid;
            int r = idx >> 3;
            int j = idx & 7;
            uint32_t sw = r * 128 + ((j ^ (r & 7)) << 4);
            cp16(sb + sw, baseh + (size_t)r * Kp + j * 8);
            cp16(sb + 16384 + sw, basel + (size_t)r * Kp + j * 8);
        }
    }
    {
        const __nv_bfloat16* baseh = g.Bh[o] + (size_t)n0 * Kp + k0;
        const __nv_bfloat16* basel = g.Bl[o] + (size_t)n0 * Kp + k0;
#pragma unroll
        for (int it = 0; it < 4; it++) {
            int idx = it * 256 + tid;
            int r = idx >> 3;
            int j = idx & 7;
            uint32_t sw = r * 128 + ((j ^ (r & 7)) << 4);
            cp16(sb + 32768 + sw, baseh + (size_t)r * Kp + j * 8);
            cp16(sb + 49152 + sw, basel + (size_t)r * Kp + j * 8);
        }
    }
    cp_commit();
}

__device__ __forceinline__ void gemm_body(const GemmArgs& g, char* smem)
{
    const uint32_t sbase = smem_u32(smem);
    const int tid = threadIdx.x;
    const int lane = tid & 31;
    const int warp = tid >> 5;
    const int wm = warp >> 2;
    const int wn = warp & 3;
    const int m0 = blockIdx.y * 128;
    const int n0 = blockIdx.x * 128;

    float acc[4][4][4];
#pragma unroll
    for (int i = 0; i < 4; i++)
#pragma unroll
        for (int j = 0; j < 4; j++)
#pragma unroll
            for (int q = 0; q < 4; q++) acc[i][j][q] = 0.f;

    const int sx = lane & 7;
    const int arow = (lane & 7) + ((lane >> 3) & 1) * 8;
    const int khia = (lane >> 4) & 1;
    const int brow = (lane & 7) + ((lane >> 4) & 1) * 8;
    const int khib = (lane >> 3) & 1;

    const int T = g.totChunks;
    load_stage(g, 0, sbase, tid, m0, n0);

    for (int t = 0; t < T; t++) {
        if (t + 1 < T) {
            load_stage(g, t + 1, sbase + ((t + 1) & 1) * STAGE_BYTES, tid, m0, n0);
            cp_wait1();
        } else {
            cp_wait0();
        }
        __syncthreads();

        const uint32_t Ah = sbase + (t & 1) * STAGE_BYTES;
        const uint32_t Al = Ah + 16384;
        const uint32_t Bh = Ah + 32768;
        const uint32_t Bl = Ah + 49152;

#pragma unroll
        for (int ks = 0; ks < 4; ks++) {
            uint32_t ah[4][4], al[4][4], bh[2][4], bl[2][4];
            const uint32_t colA = (uint32_t)(((ks * 2 + khia) ^ sx) << 4);
            const uint32_t colB = (uint32_t)(((ks * 2 + khib) ^ sx) << 4);
#pragma unroll
            for (int mt = 0; mt < 4; mt++) {
                int row = wm * 64 + mt * 16 + arow;
                ldm_x4(ah[mt], Ah + row * 128 + colA);
                ldm_x4(al[mt], Al + row * 128 + colA);
            }
#pragma unroll
            for (int np = 0; np < 2; np++) {
                int row = wn * 32 + np * 16 + brow;
                ldm_x4(bh[np], Bh + row * 128 + colB);
                ldm_x4(bl[np], Bl + row * 128 + colB);
            }
#pragma unroll
            for (int mt = 0; mt < 4; mt++) {
#pragma unroll
                for (int nt = 0; nt < 4; nt++) {
                    const uint32_t* bhf = &bh[nt >> 1][(nt & 1) * 2];
                    const uint32_t* blf = &bl[nt >> 1][(nt & 1) * 2];
                    mma16816(acc[mt][nt], ah[mt], bhf);
                    mma16816(acc[mt][nt], ah[mt], blf);
                    mma16816(acc[mt][nt], al[mt], bhf);
                }
            }
        }
        __syncthreads();
    }

    // ---- epilogue ----
#pragma unroll
    for (int mt = 0; mt < 4; mt++) {
        int row0 = m0 + wm * 64 + mt * 16 + (lane >> 2);
#pragma unroll
        for (int nt = 0; nt < 4; nt++) {
            int col = n0 + wn * 32 + nt * 8 + (lane & 3) * 2;
            if (col >= g.Nstore) continue;
            float b0 = 0.f, b1 = 0.f;
            if (g.bias) {
                b0 = g.bias[col];
                if (col + 1 < g.Nstore) b1 = g.bias[col + 1];
            }
#pragma unroll
            for (int rr = 0; rr < 2; rr++) {
                int r = row0 + rr * 8;
                if (r >= g.M) continue;
                float v0 = (acc[mt][nt][rr * 2 + 0] + b0) * g.ps;
                float v1 = (acc[mt][nt][rr * 2 + 1] + b1) * g.ps;
                if (g.act) {
                    v0 = v0 > 0.f ? v0 : 0.2f * v0;
                    v1 = v1 > 0.f ? v1 : 0.2f * v1;
                }
                if (g.D) {
                    float* dp = g.D + (size_t)r * g.ldd + col;
                    if (col + 1 < g.Nstore) *(float2*)dp = make_float2(v0, v1);
                    else *dp = v0;
                }
                if (g.Dh) {
                    __nv_bfloat162 hh, ll;
                    split2(v0, v1, hh, ll);
                    size_t po = (size_t)r * HDIM + col;
                    *(__nv_bfloat162*)(g.Dh + po) = hh;
                    *(__nv_bfloat162*)(g.Dl + po) = ll;
                }
            }
        }
    }
}

__global__ __launch_bounds__(256, 1) void gemm_mma(const __grid_constant__ GemmArgs g)
{
    extern __shared__ __align__(128) char smem[];
    gemm_body(g, smem);
}

__global__ __launch_bounds__(256, 1) void gemm_mma_pair(const __grid_constant__ GemmPair p)
{
    extern __shared__ __align__(128) char smem[];
    gemm_body(p.g[blockIdx.z], smem);
}

// ================= host orchestration =================
struct OpDesc {
    const __nv_bfloat16 *Ah, *Al, *Bh, *Bl;
    int Kp;
};

static void fill_args(GemmArgs& g, const OpDesc* ops, int nops, int M, int Nstore,
                      int ldd, const float* bias, float ps, int act,
                      float* D, __nv_bfloat16* Dh, __nv_bfloat16* Dl)
{
    int T = 0;
    for (int o = 0; o < nops; o++) {
        g.Ah[o] = ops[o].Ah; g.Al[o] = ops[o].Al;
        g.Bh[o] = ops[o].Bh; g.Bl[o] = ops[o].Bl;
        g.Kp[o] = ops[o].Kp;
        T += ops[o].Kp / 64;
    }
    g.nops = nops; g.totChunks = T;
    g.M = M; g.Nstore = Nstore; g.ldd = ldd;
    g.bias = bias; g.ps = ps; g.act = act;
    g.D = D; g.Dh = Dh; g.Dl = Dl;
}

extern "C" void kernel_launch(void* const* d_in, const int* in_sizes, int n_in,
                              void* d_out, int out_size)
{
    const float* x_window  = (const float*)d_in[0];
    const float* x_example = (const float*)d_in[1];
    const int*   e_near    = (const int*)d_in[2];
    const int*   e_close   = (const int*)d_in[3];
    const int*   e_refer   = (const int*)d_in[4];
    const float* W_win     = (const float*)d_in[5];
    const float* W_exp     = (const float*)d_in[6];
    const float* W_post    = (const float*)d_in[7];
    const float* Wl_near   = (const float*)d_in[9];
    const float* Wr_near   = (const float*)d_in[10];
    const float* b_near    = (const float*)d_in[11];
    const float* Wl_close  = (const float*)d_in[12];
    const float* Wr_close  = (const float*)d_in[13];
    const float* b_close   = (const float*)d_in[14];
    const float* Wl_refer  = (const float*)d_in[15];
    const float* Wr_refer  = (const float*)d_in[16];
    const float* b_refer   = (const float*)d_in[17];
    const float* w_pool    = (const float*)d_in[18];
    const float* W_lin     = (const float*)d_in[19];
    const float* b_lin     = (const float*)d_in[20];
    float* out = (float*)d_out;

    cudaFuncSetAttribute(gemm_mma, cudaFuncAttributeMaxDynamicSharedMemorySize, GEMM_SMEM);
    cudaFuncSetAttribute(gemm_mma_pair, cudaFuncAttributeMaxDynamicSharedMemorySize, GEMM_SMEM);

    float *score, *bsum;
    int *cnt, *off, *cur, *csrc;
    __nv_bfloat16 *wth, *wtl, *bigh, *bigl, *pth, *ptl;
    __nv_bfloat16 *phwh[2], *phwl[2], *pheh[2], *phel[2];
    __nv_bfloat16 *pa0h, *pa0l, *pa1h, *pa1l, *pa2h, *pa2l;
    cudaGetSymbolAddress((void**)&score, g_score);
    cudaGetSymbolAddress((void**)&bsum, g_bsum);
    cudaGetSymbolAddress((void**)&cnt, g_cnt);
    cudaGetSymbolAddress((void**)&off, g_off);
    cudaGetSymbolAddress((void**)&cur, g_cur);
    cudaGetSymbolAddress((void**)&csrc, g_csrc);
    cudaGetSymbolAddress((void**)&wth, g_wth);
    cudaGetSymbolAddress((void**)&wtl, g_wtl);
    cudaGetSymbolAddress((void**)&bigh, g_bigh);
    cudaGetSymbolAddress((void**)&bigl, g_bigl);
    cudaGetSymbolAddress((void**)&pth, g_pth);
    cudaGetSymbolAddress((void**)&ptl, g_ptl);
    cudaGetSymbolAddress((void**)&phwh[0], g_phw0h);
    cudaGetSymbolAddress((void**)&phwl[0], g_phw0l);
    cudaGetSymbolAddress((void**)&phwh[1], g_phw1h);
    cudaGetSymbolAddress((void**)&phwl[1], g_phw1l);
    cudaGetSymbolAddress((void**)&pheh[0], g_phe0h);
    cudaGetSymbolAddress((void**)&phel[0], g_phe0l);
    cudaGetSymbolAddress((void**)&pheh[1], g_phe1h);
    cudaGetSymbolAddress((void**)&phel[1], g_phe1l);
    cudaGetSymbolAddress((void**)&pa0h, g_pa0h);
    cudaGetSymbolAddress((void**)&pa0l, g_pa0l);
    cudaGetSymbolAddress((void**)&pa1h, g_pa1h);
    cudaGetSymbolAddress((void**)&pa1l, g_pa1l);
    cudaGetSymbolAddress((void**)&pa2h, g_pa2h);
    cudaGetSymbolAddress((void**)&pa2l, g_pa2l);

    const unsigned edge_blocks = (EDG + 255) / 256;

    // --- batched weight conversion ---
    {
        ConvBatch cb;
        for (int l = 0; l < NLAYERS; l++) {
            size_t s = (size_t)l * HDIM * HDIM;
            cb.W1[l * 5 + 0] = Wl_near + s;  cb.W2[l * 5 + 0] = nullptr;      cb.dstoff[l * 5 + 0] = WOFF_WLN(l);
            cb.W1[l * 5 + 1] = Wl_refer + s; cb.W2[l * 5 + 1] = nullptr;      cb.dstoff[l * 5 + 1] = WOFF_WLR(l);
            cb.W1[l * 5 + 2] = Wr_near + s;  cb.W2[l * 5 + 2] = Wr_refer + s; cb.dstoff[l * 5 + 2] = WOFF_WSUM(l);
            cb.W1[l * 5 + 3] = Wl_close + s; cb.W2[l * 5 + 3] = nullptr;      cb.dstoff[l * 5 + 3] = WOFF_WLC(l);
            cb.W1[l * 5 + 4] = Wr_close + s; cb.W2[l * 5 + 4] = nullptr;      cb.dstoff[l * 5 + 4] = WOFF_WRC(l);
        }
        cb.W1[20] = W_post; cb.W2[20] = nullptr; cb.dstoff[20] = WOFF_POST;
        dim3 blk(32, 8);
        dim3 gB(HDIM / 32, HDIM / 32, NBATCH);
        conv_w_batch<<<gB, blk>>>(cb, wth, wtl);

        dim3 gWIN(KP_WIN / 32, HDIM / 32);
        conv_w<<<gWIN, blk>>>(W_win, KWIN, HDIM, KP_WIN, wth + WOFF_WIN, wtl + WOFF_WIN);
        dim3 gEXP(128 / 32, HDIM / 32);
        conv_w<<<gEXP, blk>>>(W_exp, KEXP, HDIM, 128, wth + WOFF_EXP, wtl + WOFF_EXP);
        dim3 gLIN(HDIM / 32, 128 / 32);
        conv_w<<<gLIN, blk>>>(W_lin, HDIM, NOUT, HDIM, wth + WOFF_LIN, wtl + WOFF_LIN);
        bias_sum_all<<<(NLAYERS * HDIM + 255) / 256, 256>>>(b_near, b_refer, bsum);
    }

    // --- zero pad rows [NWIN, MP) of plane buffers ---
    {
        PadPtrs pp;
        pp.h[0] = pth;     pp.l[0] = ptl;
        pp.h[1] = phwh[0]; pp.l[1] = phwl[0];
        pp.h[2] = phwh[1]; pp.l[2] = phwl[1];
        pp.h[3] = pheh[0]; pp.l[3] = phel[0];
        pp.h[4] = pheh[1]; pp.l[4] = phel[1];
        pp.h[5] = pa0h;    pp.l[5] = pa0l;
        pp.h[6] = pa1h;    pp.l[6] = pa1l;
        pp.h[7] = pa2h;    pp.l[7] = pa2l;
        int tot = NPAD * (MP - NWIN) * HDIM;
        zero_pad_all<<<(tot + 255) / 256, 256>>>(pp);
    }

    // --- CSR build ---
    {
        EdgePtrs ep;
        ep.es[0] = e_near;  ep.ed[0] = e_near + EDG;
        ep.es[1] = e_refer; ep.ed[1] = e_refer + EDG;
        ep.es[2] = e_close; ep.ed[2] = e_close + EDG;
        zero_int<<<(3 * NWIN + 255) / 256, 256>>>(cnt, 3 * NWIN);
        dim3 ge(edge_blocks, 3);
        hist_all<<<ge, 256>>>(ep, cnt);
        scan_all<<<3, 1024>>>(cnt, off, cur);
        fill_all<<<ge, 256>>>(ep, cur, csrc);
    }

    // --- input projections (paired) ---
    {
        long long tot = (long long)MP * 128;
        conv_a<<<(unsigned)((tot + 255) / 256), 256>>>(x_example, NEX, KEXP, 128, tot, pa0h, pa0l);
        tot = (long long)MP * KP_WIN;
        conv_a<<<(unsigned)((tot + 255) / 256), 256>>>(x_window, NWIN, KWIN, KP_WIN, tot, bigh, bigl);

        GemmPair pr;
        OpDesc opw = { bigh, bigl, wth + WOFF_WIN, wtl + WOFF_WIN, KP_WIN };
        OpDesc ope = { pa0h, pa0l, wth + WOFF_EXP, wtl + WOFF_EXP, 128 };
        fill_args(pr.g[0], &opw, 1, NWIN, HDIM, HDIM, nullptr, 1.f, 1, nullptr, pth, ptl);
        fill_args(pr.g[1], &ope, 1, NEX, HDIM, HDIM, nullptr, 1.f, 1, nullptr, pa1h, pa1l);
        gemm_mma_pair<<<dim3(4, 235, 2), 256, GEMM_SMEM>>>(pr);

        OpDesc opw2 = { pth, ptl, wth + WOFF_POST, wtl + WOFF_POST, HDIM };
        OpDesc ope2 = { pa1h, pa1l, wth + WOFF_POST, wtl + WOFF_POST, HDIM };
        fill_args(pr.g[0], &opw2, 1, NWIN, HDIM, HDIM, nullptr, 1.f, 1, nullptr, phwh[0], phwl[0]);
        fill_args(pr.g[1], &ope2, 1, NEX, HDIM, HDIM, nullptr, 1.f, 1, nullptr, pheh[0], phel[0]);
        gemm_mma_pair<<<dim3(4, 235, 2), 256, GEMM_SMEM>>>(pr);
    }

    // --- SAGE layers ---
    int curb = 0;
    for (int l = 0; l < NLAYERS; l++) {
        int nxt = curb ^ 1;
        GatherBatch gb;
        gb.sh[0] = phwh[curb]; gb.sl[0] = phwl[curb];
        gb.sh[1] = pheh[curb]; gb.sl[1] = phel[curb];
        gb.sh[2] = pheh[curb]; gb.sl[2] = phel[curb];
        gb.off[0] = off + 0 * (NWIN + 1); gb.csrc[0] = csrc + 0 * (size_t)EDG; gb.ndst[0] = NWIN;
        gb.off[1] = off + 1 * (NWIN + 1); gb.csrc[1] = csrc + 1 * (size_t)EDG; gb.ndst[1] = NWIN;
        gb.off[2] = off + 2 * (NWIN + 1); gb.csrc[2] = csrc + 2 * (size_t)EDG; gb.ndst[2] = NEX;
        gb.oh[0] = pa0h; gb.ol[0] = pa0l;
        gb.oh[1] = pa1h; gb.ol[1] = pa1l;
        gb.oh[2] = pa2h; gb.ol[2] = pa2l;
        gather_all<<<dim3(MP, 3), 128>>>(gb);

        GemmPair pr;
        OpDesc ops3[3] = {
            { pa0h, pa0l, wth + WOFF_WLN(l), wtl + WOFF_WLN(l), HDIM },
            { pa1h, pa1l, wth + WOFF_WLR(l), wtl + WOFF_WLR(l), HDIM },
            { phwh[curb], phwl[curb], wth + WOFF_WSUM(l), wtl + WOFF_WSUM(l), HDIM },
        };
        OpDesc ops2[2] = {
            { pa2h, pa2l, wth + WOFF_WLC(l), wtl + WOFF_WLC(l), HDIM },
            { pheh[curb], phel[curb], wth + WOFF_WRC(l), wtl + WOFF_WRC(l), HDIM },
        };
        fill_args(pr.g[0], ops3, 3, NWIN, HDIM, HDIM, bsum + (size_t)l * HDIM, 0.5f, 1,
                  nullptr, phwh[nxt], phwl[nxt]);
        fill_args(pr.g[1], ops2, 2, NEX, HDIM, HDIM, b_close + (size_t)l * HDIM, 1.f, 1,
                  nullptr, pheh[nxt], phel[nxt]);
        gemm_mma_pair<<<dim3(4, 235, 2), 256, GEMM_SMEM>>>(pr);
        curb = nxt;
    }

    // --- CSRA pooling ---
    gemv_score<<<(NEX + 7) / 8, 256>>>(pheh[curb], phel[curb], w_pool, score);
    pool_gather<<<MP, 128>>>(pheh[curb], phel[curb], phwh[curb], phwl[curb], score,
                             off + 1 * (NWIN + 1), csrc + 1 * (size_t)EDG, NWIN, pth, ptl);

    // out = planes @ W_lin + b_lin
    GemmArgs gf;
    OpDesc opf = { pth, ptl, wth + WOFF_LIN, wtl + WOFF_LIN, HDIM };
    fill_args(gf, &opf, 1, NWIN, NOUT, NOUT, b_lin, 1.f, 0, out, nullptr, nullptr);
    gemm_mma<<<dim3(1, 235), 256, GEMM_SMEM>>>(gf);
}

// round 8
// speedup vs baseline: 1.0901x; 1.0312x over previous
#include <cuda_runtime.h>
#include <cuda_bf16.h>
#include <float.h>
#include <math.h>
#include <stdint.h>

#define NWIN 30000
#define NEX  30000
#define EDG  480000
#define HDIM 512
#define NLAYERS 4
#define KWIN 1949
#define KEXP 100
#define NOUT 100
#define MP   30080
#define KP_WIN 1984

// ================= small fp32 scratch =================
__device__ float g_score[NEX];
__device__ float g_bsum[NLAYERS*HDIM];

// ================= CSR scratch =================
__device__ int g_cnt[3*NWIN];
__device__ int g_off[3*(NWIN+1)];
__device__ int g_cur[3*NWIN];
__device__ int g_csrc[3*EDG];

// ================= bf16 weight buffers [N][Kp], hi & lo =================
#define WOFF_STEP   (HDIM*HDIM)
#define WOFF_LAYER  (5*WOFF_STEP)
#define WOFF_WLN(l) ((l)*WOFF_LAYER + 0*WOFF_STEP)
#define WOFF_WLR(l) ((l)*WOFF_LAYER + 1*WOFF_STEP)
#define WOFF_WSUM(l)((l)*WOFF_LAYER + 2*WOFF_STEP)
#define WOFF_WLC(l) ((l)*WOFF_LAYER + 3*WOFF_STEP)
#define WOFF_WRC(l) ((l)*WOFF_LAYER + 4*WOFF_STEP)
#define WOFF_POST   (NLAYERS*WOFF_LAYER)
#define WOFF_WIN    (WOFF_POST + WOFF_STEP)
#define WOFF_EXP    (WOFF_WIN + HDIM*KP_WIN)
#define WOFF_LIN    (WOFF_EXP + HDIM*128)
#define WTOTAL      (WOFF_LIN + 128*HDIM)
__device__ __align__(256) __nv_bfloat16 g_wth[WTOTAL];
__device__ __align__(256) __nv_bfloat16 g_wtl[WTOTAL];

// ================= bf16 activation plane buffers =================
__device__ __align__(256) __nv_bfloat16 g_bigh[(size_t)MP*KP_WIN];
__device__ __align__(256) __nv_bfloat16 g_bigl[(size_t)MP*KP_WIN];
__device__ __align__(256) __nv_bfloat16 g_pth[(size_t)MP*HDIM];
__device__ __align__(256) __nv_bfloat16 g_ptl[(size_t)MP*HDIM];
__device__ __align__(256) __nv_bfloat16 g_phw0h[(size_t)MP*HDIM];
__device__ __align__(256) __nv_bfloat16 g_phw0l[(size_t)MP*HDIM];
__device__ __align__(256) __nv_bfloat16 g_phw1h[(size_t)MP*HDIM];
__device__ __align__(256) __nv_bfloat16 g_phw1l[(size_t)MP*HDIM];
__device__ __align__(256) __nv_bfloat16 g_phe0h[(size_t)MP*HDIM];
__device__ __align__(256) __nv_bfloat16 g_phe0l[(size_t)MP*HDIM];
__device__ __align__(256) __nv_bfloat16 g_phe1h[(size_t)MP*HDIM];
__device__ __align__(256) __nv_bfloat16 g_phe1l[(size_t)MP*HDIM];
__device__ __align__(256) __nv_bfloat16 g_pa0h[(size_t)MP*HDIM];
__device__ __align__(256) __nv_bfloat16 g_pa0l[(size_t)MP*HDIM];
__device__ __align__(256) __nv_bfloat16 g_pa1h[(size_t)MP*HDIM];
__device__ __align__(256) __nv_bfloat16 g_pa1l[(size_t)MP*HDIM];
__device__ __align__(256) __nv_bfloat16 g_pa2h[(size_t)MP*HDIM];
__device__ __align__(256) __nv_bfloat16 g_pa2l[(size_t)MP*HDIM];

// ================= helpers =================
__device__ __forceinline__ void split2(float v0, float v1, __nv_bfloat162& h, __nv_bfloat162& l)
{
    __nv_bfloat16 h0 = __float2bfloat16_rn(v0);
    __nv_bfloat16 h1 = __float2bfloat16_rn(v1);
    h.x = h0; h.y = h1;
    l.x = __float2bfloat16_rn(v0 - __bfloat162float(h0));
    l.y = __float2bfloat16_rn(v1 - __bfloat162float(h1));
}

__device__ __forceinline__ float4 recon4(const __nv_bfloat16* __restrict__ h,
                                         const __nv_bfloat16* __restrict__ l,
                                         size_t off)
{
    __nv_bfloat162 h0 = *(const __nv_bfloat162*)(h + off);
    __nv_bfloat162 h1 = *(const __nv_bfloat162*)(h + off + 2);
    __nv_bfloat162 l0 = *(const __nv_bfloat162*)(l + off);
    __nv_bfloat162 l1 = *(const __nv_bfloat162*)(l + off + 2);
    return make_float4(__bfloat162float(h0.x) + __bfloat162float(l0.x),
                       __bfloat162float(h0.y) + __bfloat162float(l0.y),
                       __bfloat162float(h1.x) + __bfloat162float(l1.x),
                       __bfloat162float(h1.y) + __bfloat162float(l1.y));
}

__device__ __forceinline__ void split_store8(float* v, __nv_bfloat16* oh, __nv_bfloat16* ol,
                                             size_t off)
{
    __nv_bfloat162 hh[4], ll[4];
#pragma unroll
    for (int j = 0; j < 4; j++) split2(v[j * 2], v[j * 2 + 1], hh[j], ll[j]);
    *(uint4*)(oh + off) = *(uint4*)hh;
    *(uint4*)(ol + off) = *(uint4*)ll;
}

// ================= batched HxH weight conversion =================
#define NBATCH 21
struct ConvBatch {
    const float* W1[NBATCH];
    const float* W2[NBATCH];
    int dstoff[NBATCH];
};

__global__ void conv_w_batch(const __grid_constant__ ConvBatch cb,
                             __nv_bfloat16* __restrict__ ohb,
                             __nv_bfloat16* __restrict__ olb)
{
    __shared__ float t[32][33];
    int z = blockIdx.z;
    const float* W = cb.W1[z];
    const float* W2 = cb.W2[z];
    __nv_bfloat16* oh = ohb + cb.dstoff[z];
    __nv_bfloat16* ol = olb + cb.dstoff[z];
    int k0 = blockIdx.x * 32, n0 = blockIdx.y * 32;
    int tx = threadIdx.x, ty = threadIdx.y;
#pragma unroll
    for (int i = 0; i < 4; i++) {
        int k = k0 + ty + i * 8, n = n0 + tx;
        float v = W[(size_t)k * HDIM + n];
        if (W2) v += W2[(size_t)k * HDIM + n];
        t[ty + i * 8][tx] = v;
    }
    __syncthreads();
#pragma unroll
    for (int i = 0; i < 4; i++) {
        int n = n0 + ty + i * 8, k = k0 + tx;
        float v = t[tx][ty + i * 8];
        __nv_bfloat16 hb = __float2bfloat16_rn(v);
        oh[(size_t)n * HDIM + k] = hb;
        ol[(size_t)n * HDIM + k] = __float2bfloat16_rn(v - __bfloat162float(hb));
    }
}

__global__ void conv_w(const float* __restrict__ W, int K, int N, int Kp,
                       __nv_bfloat16* __restrict__ oh, __nv_bfloat16* __restrict__ ol)
{
    __shared__ float t[32][33];
    int k0 = blockIdx.x * 32, n0 = blockIdx.y * 32;
    int tx = threadIdx.x, ty = threadIdx.y;
#pragma unroll
    for (int i = 0; i < 4; i++) {
        int k = k0 + ty + i * 8, n = n0 + tx;
        float v = 0.f;
        if (k < K && n < N) v = W[(size_t)k * N + n];
        t[ty + i * 8][tx] = v;
    }
    __syncthreads();
#pragma unroll
    for (int i = 0; i < 4; i++) {
        int n = n0 + ty + i * 8, k = k0 + tx;
        float v = t[tx][ty + i * 8];
        __nv_bfloat16 hb = __float2bfloat16_rn(v);
        oh[(size_t)n * Kp + k] = hb;
        ol[(size_t)n * Kp + k] = __float2bfloat16_rn(v - __bfloat162float(hb));
    }
}

__global__ void conv_a(const float* __restrict__ A, int M, int K, int Kp, long long total,
                       __nv_bfloat16* __restrict__ oh, __nv_bfloat16* __restrict__ ol)
{
    long long i = (long long)blockIdx.x * blockDim.x + threadIdx.x;
    if (i >= total) return;
    int m = (int)(i / Kp);
    int k = (int)(i % Kp);
    float v = 0.f;
    if (m < M && k < K) v = A[(size_t)m * K + k];
    __nv_bfloat16 hb = __float2bfloat16_rn(v);
    oh[i] = hb;
    ol[i] = __float2bfloat16_rn(v - __bfloat162float(hb));
}

__global__ void bias_sum_all(const float* a, const float* b, float* o)
{
    int i = blockIdx.x * blockDim.x + threadIdx.x;
    if (i < NLAYERS * HDIM) o[i] = a[i] + b[i];
}

__global__ void zero_int(int* p, int n)
{
    int i = blockIdx.x * blockDim.x + threadIdx.x;
    if (i < n) p[i] = 0;
}

#define NPAD 8
struct PadPtrs { __nv_bfloat16* h[NPAD]; __nv_bfloat16* l[NPAD]; };
__global__ void zero_pad_all(const __grid_constant__ PadPtrs pp)
{
    int i = blockIdx.x * blockDim.x + threadIdx.x;
    const int per = (MP - NWIN) * HDIM;
    int z = i / per;
    if (z >= NPAD) return;
    int r = i - z * per;
    pp.h[z][(size_t)NWIN * HDIM + r] = __float2bfloat16_rn(0.f);
    pp.l[z][(size_t)NWIN * HDIM + r] = __float2bfloat16_rn(0.f);
}

// ================= CSR build =================
struct EdgePtrs { const int* es[3]; const int* ed[3]; };

__global__ void hist_all(const __grid_constant__ EdgePtrs ep, int* __restrict__ cnt)
{
    int r = blockIdx.y;
    int e = blockIdx.x * blockDim.x + threadIdx.x;
    if (e < EDG) atomicAdd(&cnt[r * NWIN + ep.ed[r][e]], 1);
}

__global__ void scan_all(const int* __restrict__ cnt, int* __restrict__ off,
                         int* __restrict__ cur)
{
    __shared__ int s[1024];
    int r = blockIdx.x;
    const int* c = cnt + r * NWIN;
    int* of = off + r * (NWIN + 1);
    int* cu = cur + r * NWIN;
    int t = threadIdx.x;
    int chunk = (NWIN + 1023) >> 10;
    int b = t * chunk, e = min(b + chunk, NWIN);
    int sum = 0;
    for (int i = b; i < e; i++) sum += c[i];
    s[t] = sum;
    __syncthreads();
    for (int d = 1; d < 1024; d <<= 1) {
        int v = (t >= d) ? s[t - d] : 0;
        __syncthreads();
        s[t] += v;
        __syncthreads();
    }
    int run = (t == 0) ? 0 : s[t - 1];
    for (int i = b; i < e; i++) {
        of[i] = run; cu[i] = run; run += c[i];
    }
    if (t == 0) of[NWIN] = s[1023];
}

__global__ void fill_all(const __grid_constant__ EdgePtrs ep, int* __restrict__ cur,
                         int* __restrict__ csrc)
{
    int r = blockIdx.y;
    int e = blockIdx.x * blockDim.x + threadIdx.x;
    if (e < EDG) {
        int p = atomicAdd(&cur[r * NWIN + ep.ed[r][e]], 1);
        csrc[(size_t)r * EDG + p] = ep.es[r][e];
    }
}

// ================= fused 3-relation gather-mean (hi/lo thread split) =================
struct GatherBatch {
    const __nv_bfloat16 *sh[3], *sl[3];
    const int *off[3], *csrc[3];
    int ndst[3];
    __nv_bfloat16 *oh[3], *ol[3];
};

__global__ void gather_all(const __grid_constant__ GatherBatch gb)
{
    __shared__ float sm[512];
    int r = blockIdx.y;
    int d = blockIdx.x;
    int t = threadIdx.x;
    const bool isLo = t >= 64;
    const int c = (t & 63) * 8;
    const __nv_bfloat16* src = isLo ? gb.sl[r] : gb.sh[r];

    float acc[8];
#pragma unroll
    for (int j = 0; j < 8; j++) acc[j] = 0.f;
    int deg = 0;
    if (d < gb.ndst[r]) {
        const int* off = gb.off[r];
        const int* cs = gb.csrc[r];
        int s0 = off[d], s1 = off[d + 1];
        deg = s1 - s0;
        for (int e = s0; e < s1; e++) {
            uint4 q = *(const uint4*)(src + (size_t)cs[e] * HDIM + c);
            const __nv_bfloat162* b2 = (const __nv_bfloat162*)&q;
#pragma unroll
            for (int j = 0; j < 4; j++) {
                acc[j * 2 + 0] += __bfloat162float(b2[j].x);
                acc[j * 2 + 1] += __bfloat162float(b2[j].y);
            }
        }
    }
    if (isLo) {
#pragma unroll
        for (int j = 0; j < 8; j++) sm[(t - 64) * 8 + j] = acc[j];
    }
    __syncthreads();
    if (!isLo) {
        float inv = 1.f / (float)max(deg, 1);
        float v[8];
#pragma unroll
        for (int j = 0; j < 8; j++) v[j] = (acc[j] + sm[t * 8 + j]) * inv;
        split_store8(v, gb.oh[r], gb.ol[r], (size_t)d * HDIM + c);
    }
}

// ================= CSR softmax pooling (hi/lo thread split) =================
__global__ void pool_gather(const __nv_bfloat16* __restrict__ heh,
                            const __nv_bfloat16* __restrict__ hel,
                            const __nv_bfloat16* __restrict__ hwh,
                            const __nv_bfloat16* __restrict__ hwl,
                            const float* __restrict__ score,
                            const int* __restrict__ off, const int* __restrict__ csrc,
                            int ndst,
                            __nv_bfloat16* __restrict__ oh, __nv_bfloat16* __restrict__ ol)
{
    __shared__ float red[128];
    __shared__ float sm[512];
    int d = blockIdx.x;
    int t = threadIdx.x;
    int s0 = 0, s1 = 0;
    if (d < ndst) { s0 = off[d]; s1 = off[d + 1]; }

    float m = -FLT_MAX;
    for (int e = s0 + t; e < s1; e += 128) m = fmaxf(m, score[csrc[e]]);
    red[t] = m; __syncthreads();
    for (int w = 64; w; w >>= 1) {
        if (t < w) red[t] = fmaxf(red[t], red[t + w]);
        __syncthreads();
    }
    float smax = red[0];
    __syncthreads();
    float z = 0.f;
    for (int e = s0 + t; e < s1; e += 128) z += expf(score[csrc[e]] - smax);
    red[t] = z; __syncthreads();
    for (int w = 64; w; w >>= 1) {
        if (t < w) red[t] += red[t + w];
        __syncthreads();
    }
    float invz = 1.f / fmaxf(red[0], 1e-12f);

    const bool isLo = t >= 64;
    const int c = (t & 63) * 8;
    const __nv_bfloat16* src = isLo ? hel : heh;
    float acc[8];
#pragma unroll
    for (int j = 0; j < 8; j++) acc[j] = 0.f;
    for (int e = s0; e < s1; e++) {
        int sidx = csrc[e];
        float w = expf(score[sidx] - smax) * invz;
        uint4 q = *(const uint4*)(src + (size_t)sidx * HDIM + c);
        const __nv_bfloat162* b2 = (const __nv_bfloat162*)&q;
#pragma unroll
        for (int j = 0; j < 4; j++) {
            acc[j * 2 + 0] += w * __bfloat162float(b2[j].x);
            acc[j * 2 + 1] += w * __bfloat162float(b2[j].y);
        }
    }
    if (isLo) {
#pragma unroll
        for (int j = 0; j < 8; j++) sm[(t - 64) * 8 + j] = acc[j];
    }
    __syncthreads();
    if (!isLo) {
        size_t o = (size_t)d * HDIM + c;
        uint4 qh = *(const uint4*)(hwh + o);
        uint4 ql = *(const uint4*)(hwl + o);
        const __nv_bfloat162* bh = (const __nv_bfloat162*)&qh;
        const __nv_bfloat162* bl = (const __nv_bfloat162*)&ql;
        float v[8];
#pragma unroll
        for (int j = 0; j < 4; j++) {
            v[j * 2 + 0] = __bfloat162float(bh[j].x) + __bfloat162float(bl[j].x)
                         + 0.5f * (acc[j * 2 + 0] + sm[t * 8 + j * 2 + 0]);
            v[j * 2 + 1] = __bfloat162float(bh[j].y) + __bfloat162float(bl[j].y)
                         + 0.5f * (acc[j * 2 + 1] + sm[t * 8 + j * 2 + 1]);
        }
        split_store8(v, oh, ol, o);
    }
}

__global__ void gemv_score(const __nv_bfloat16* __restrict__ heh,
                           const __nv_bfloat16* __restrict__ hel,
                           const float* __restrict__ w, float* __restrict__ sc)
{
    int row = blockIdx.x * 8 + (threadIdx.x >> 5);
    if (row >= NEX) return;
    int lane = threadIdx.x & 31;
    float s = 0.f;
#pragma unroll
    for (int k = lane * 4; k < HDIM; k += 128) {
        float4 v = recon4(heh, hel, (size_t)row * HDIM + k);
        s += v.x * w[k] + v.y * w[k + 1] + v.z * w[k + 2] + v.w * w[k + 3];
    }
#pragma unroll
    for (int o = 16; o; o >>= 1) s += __shfl_down_sync(0xFFFFFFFFu, s, o);
    if (lane == 0) sc[row] = s;
}

// ================= GEMM common =================
struct GemmArgs {
    const __nv_bfloat16 *Ah[3], *Al[3], *Bh[3], *Bl[3];
    int Kp[3];
    int nops, totChunks;
    int M, Nstore, ldd;
    const float* bias;
    float ps;
    int act;
    float* D;
    __nv_bfloat16 *Dh, *Dl;
};
struct GemmPair { GemmArgs g[2]; };

__device__ __forceinline__ uint32_t smem_u32(const void* p) {
    uint32_t a;
    asm("{ .reg .u64 t; cvta.to.shared.u64 t, %1; cvt.u32.u64 %0, t; }" : "=r"(a) : "l"(p));
    return a;
}
__device__ __forceinline__ void cp16(uint32_t dst, const void* src) {
    asm volatile("cp.async.cg.shared.global [%0], [%1], 16;" :: "r"(dst), "l"(src));
}
__device__ __forceinline__ void cp_commit() { asm volatile("cp.async.commit_group;"); }
__device__ __forceinline__ void cp_wait0() { asm volatile("cp.async.wait_group 0;"); }
__device__ __forceinline__ void cp_wait1() { asm volatile("cp.async.wait_group 1;"); }

__device__ __forceinline__ void ldm_x4(uint32_t* r, uint32_t addr) {
    asm volatile("ldmatrix.sync.aligned.m8n8.x4.shared.b16 {%0,%1,%2,%3}, [%4];"
                 : "=r"(r[0]), "=r"(r[1]), "=r"(r[2]), "=r"(r[3]) : "r"(addr));
}
__device__ __forceinline__ void mma16816(float* c, const uint32_t* a, const uint32_t* b) {
    asm volatile("mma.sync.aligned.m16n8k16.row.col.f32.bf16.bf16.f32 "
                 "{%0,%1,%2,%3},{%4,%5,%6,%7},{%8,%9},{%0,%1,%2,%3};"
                 : "+f"(c[0]), "+f"(c[1]), "+f"(c[2]), "+f"(c[3])
                 : "r"(a[0]), "r"(a[1]), "r"(a[2]), "r"(a[3]), "r"(b[0]), "r"(b[1]));
}

__device__ __forceinline__ void map_oc(const GemmArgs& g, int t, int& o, int& c) {
    o = 0;
    int rem = t;
    while (o < g.nops - 1 && rem >= (g.Kp[o] >> 6)) { rem -= (g.Kp[o] >> 6); o++; }
    c = rem;
}

// epilogue for one (mt,nt) fragment
__device__ __forceinline__ void epi_frag(const GemmArgs& g, const float* a4,
                                         int row0, int col)
{
    if (col >= g.Nstore) return;
    float b0 = 0.f, b1 = 0.f;
    if (g.bias) {
        b0 = g.bias[col];
        if (col + 1 < g.Nstore) b1 = g.bias[col + 1];
    }
#pragma unroll
    for (int rr = 0; rr < 2; rr++) {
        int r = row0 + rr * 8;
        if (r >= g.M) continue;
        float v0 = (a4[rr * 2 + 0] + b0) * g.ps;
        float v1 = (a4[rr * 2 + 1] + b1) * g.ps;
        if (g.act) {
            v0 = v0 > 0.f ? v0 : 0.2f * v0;
            v1 = v1 > 0.f ? v1 : 0.2f * v1;
        }
        if (g.D) {
            float* dp = g.D + (size_t)r * g.ldd + col;
            if (col + 1 < g.Nstore) *(float2*)dp = make_float2(v0, v1);
            else *dp = v0;
        }
        if (g.Dh) {
            __nv_bfloat162 hh, ll;
            split2(v0, v1, hh, ll);
            size_t po = (size_t)r * HDIM + col;
            *(__nv_bfloat162*)(g.Dh + po) = hh;
            *(__nv_bfloat162*)(g.Dl + po) = ll;
        }
    }
}

// ================= 512-thread 128x256 GEMM =================
#define STAGE2      98304      // Ah16K Al16K Bh32K Bl32K
#define GEMM_SMEM2  (2 * STAGE2)

__device__ __forceinline__ void load_stage512(const GemmArgs& g, int t, uint32_t sb,
                                              int tid, int m0, int n0)
{
    int o, c;
    map_oc(g, t, o, c);
    const int Kp = g.Kp[o];
    const int k0 = c << 6;
    {
        const __nv_bfloat16* bh_ = g.Ah[o] + (size_t)m0 * Kp + k0;
        const __nv_bfloat16* bl_ = g.Al[o] + (size_t)m0 * Kp + k0;
#pragma unroll
        for (int it = 0; it < 2; it++) {
            int idx = it * 512 + tid;
            int r = idx >> 3;
            int j = idx & 7;
            uint32_t sw = r * 128 + ((j ^ (r & 7)) << 4);
            cp16(sb + sw, bh_ + (size_t)r * Kp + j * 8);
            cp16(sb + 16384 + sw, bl_ + (size_t)r * Kp + j * 8);
        }
    }
    {
        const __nv_bfloat16* bh_ = g.Bh[o] + (size_t)n0 * Kp + k0;
        const __nv_bfloat16* bl_ = g.Bl[o] + (size_t)n0 * Kp + k0;
#pragma unroll
        for (int it = 0; it < 4; it++) {
            int idx = it * 512 + tid;
            int r = idx >> 3;
            int j = idx & 7;
            uint32_t sw = r * 128 + ((j ^ (r & 7)) << 4);
            cp16(sb + 32768 + sw, bh_ + (size_t)r * Kp + j * 8);
            cp16(sb + 65536 + sw, bl_ + (size_t)r * Kp + j * 8);
        }
    }
    cp_commit();
}

__device__ __forceinline__ void gemm_body512(const GemmArgs& g, char* smem)
{
    const uint32_t sbase = smem_u32(smem);
    const int tid = threadIdx.x;
    const int lane = tid & 31;
    const int warp = tid >> 5;
    const int wm = warp >> 2;        // 0..3 (32-row strips)
    const int wn = warp & 3;         // 0..3 (64-col strips)
    const int m0 = blockIdx.y * 128;
    const int n0 = blockIdx.x * 256;

    float acc[2][8][4];
#pragma unroll
    for (int i = 0; i < 2; i++)
#pragma unroll
        for (int j = 0; j < 8; j++)
#pragma unroll
            for (int q = 0; q < 4; q++) acc[i][j][q] = 0.f;

    const int sx = lane & 7;
    const int arow = (lane & 7) + ((lane >> 3) & 1) * 8;
    const int khia = (lane >> 4) & 1;
    const int brow = (lane & 7) + ((lane >> 4) & 1) * 8;
    const int khib = (lane >> 3) & 1;

    const int T = g.totChunks;
    load_stage512(g, 0, sbase, tid, m0, n0);

    for (int t = 0; t < T; t++) {
        if (t + 1 < T) {
            load_stage512(g, t + 1, sbase + ((t + 1) & 1) * STAGE2, tid, m0, n0);
            cp_wait1();
        } else {
            cp_wait0();
        }
        __syncthreads();

        const uint32_t Ah = sbase + (t & 1) * STAGE2;
        const uint32_t Al = Ah + 16384;
        const uint32_t Bh = Ah + 32768;
        const uint32_t Bl = Ah + 65536;

#pragma unroll
        for (int ks = 0; ks < 4; ks++) {
            const uint32_t colA = (uint32_t)(((ks * 2 + khia) ^ sx) << 4);
            const uint32_t colB = (uint32_t)(((ks * 2 + khib) ^ sx) << 4);
            uint32_t ah[2][4], al[2][4];
#pragma unroll
            for (int mt = 0; mt < 2; mt++) {
                int row = wm * 32 + mt * 16 + arow;
                ldm_x4(ah[mt], Ah + row * 128 + colA);
                ldm_x4(al[mt], Al + row * 128 + colA);
            }
#pragma unroll
            for (int half = 0; half < 2; half++) {
                uint32_t bh[2][4], bl[2][4];
#pragma unroll
                for (int np = 0; np < 2; np++) {
                    int row = wn * 64 + half * 32 + np * 16 + brow;
                    ldm_x4(bh[np], Bh + row * 128 + colB);
                    ldm_x4(bl[np], Bl + row * 128 + colB);
                }
#pragma unroll
                for (int mt = 0; mt < 2; mt++) {
#pragma unroll
                    for (int nt = 0; nt < 4; nt++) {
                        const uint32_t* bhf = &bh[nt >> 1][(nt & 1) * 2];
                        const uint32_t* blf = &bl[nt >> 1][(nt & 1) * 2];
                        float* a_ = acc[mt][half * 4 + nt];
                        mma16816(a_, ah[mt], bhf);
                        mma16816(a_, ah[mt], blf);
                        mma16816(a_, al[mt], bhf);
                    }
                }
            }
        }
        __syncthreads();
    }

#pragma unroll
    for (int mt = 0; mt < 2; mt++) {
        int row0 = m0 + wm * 32 + mt * 16 + (lane >> 2);
#pragma unroll
        for (int nt = 0; nt < 8; nt++) {
            int col = n0 + wn * 64 + nt * 8 + (lane & 3) * 2;
            epi_frag(g, acc[mt][nt], row0, col);
        }
    }
}

__global__ __launch_bounds__(512, 1) void gemm512(const __grid_constant__ GemmArgs g)
{
    extern __shared__ __align__(128) char smem[];
    gemm_body512(g, smem);
}

__global__ __launch_bounds__(512, 1) void gemm512_pair(const __grid_constant__ GemmPair p)
{
    extern __shared__ __align__(128) char smem[];
    gemm_body512(p.g[blockIdx.z], smem);
}

// ================= 256-thread 128x128 GEMM (final small N) =================
#define STAGE_BYTES 65536
#define GEMM_SMEM   (2 * STAGE_BYTES)

__device__ __forceinline__ void load_stage(const GemmArgs& g, int t, uint32_t sb,
                                           int tid, int m0, int n0)
{
    int o, c;
    map_oc(g, t, o, c);
    const int Kp = g.Kp[o];
    const int k0 = c << 6;
    {
        const __nv_bfloat16* baseh = g.Ah[o] + (size_t)m0 * Kp + k0;
        const __nv_bfloat16* basel = g.Al[o] + (size_t)m0 * Kp + k0;
#pragma unroll
        for (int it = 0; it < 4; it++) {
            int idx = it * 256 + tid;
            int r = idx >> 3;
            int j = idx & 7;
            uint32_t sw = r * 128 + ((j ^ (r & 7)) << 4);
            cp16(sb + sw, baseh + (size_t)r * Kp + j * 8);
            cp16(sb + 16384 + sw, basel + (size_t)r * Kp + j * 8);
        }
    }
    {
        const __nv_bfloat16* baseh = g.Bh[o] + (size_t)n0 * Kp + k0;
        const __nv_bfloat16* basel = g.Bl[o] + (size_t)n0 * Kp + k0;
#pragma unroll
        for (int it = 0; it < 4; it++) {
            int idx = it * 256 + tid;
            int r = idx >> 3;
            int j = idx & 7;
            uint32_t sw = r * 128 + ((j ^ (r & 7)) << 4);
            cp16(sb + 32768 + sw, baseh + (size_t)r * Kp + j * 8);
            cp16(sb + 49152 + sw, basel + (size_t)r * Kp + j * 8);
        }
    }
    cp_commit();
}

__global__ __launch_bounds__(256, 1) void gemm_mma(const __grid_constant__ GemmArgs g)
{
    extern __shared__ __align__(128) char smem[];
    const uint32_t sbase = smem_u32(smem);
    const int tid = threadIdx.x;
    const int lane = tid & 31;
    const int warp = tid >> 5;
    const int wm = warp >> 2;
    const int wn = warp & 3;
    const int m0 = blockIdx.y * 128;
    const int n0 = blockIdx.x * 128;

    float acc[4][4][4];
#pragma unroll
    for (int i = 0; i < 4; i++)
#pragma unroll
        for (int j = 0; j < 4; j++)
#pragma unroll
            for (int q = 0; q < 4; q++) acc[i][j][q] = 0.f;

    const int sx = lane & 7;
    const int arow = (lane & 7) + ((lane >> 3) & 1) * 8;
    const int khia = (lane >> 4) & 1;
    const int brow = (lane & 7) + ((lane >> 4) & 1) * 8;
    const int khib = (lane >> 3) & 1;

    const int T = g.totChunks;
    load_stage(g, 0, sbase, tid, m0, n0);

    for (int t = 0; t < T; t++) {
        if (t + 1 < T) {
            load_stage(g, t + 1, sbase + ((t + 1) & 1) * STAGE_BYTES, tid, m0, n0);
            cp_wait1();
        } else {
            cp_wait0();
        }
        __syncthreads();

        const uint32_t Ah = sbase + (t & 1) * STAGE_BYTES;
        const uint32_t Al = Ah + 16384;
        const uint32_t Bh = Ah + 32768;
        const uint32_t Bl = Ah + 49152;

#pragma unroll
        for (int ks = 0; ks < 4; ks++) {
            uint32_t ah[4][4], al[4][4], bh[2][4], bl[2][4];
            const uint32_t colA = (uint32_t)(((ks * 2 + khia) ^ sx) << 4);
            const uint32_t colB = (uint32_t)(((ks * 2 + khib) ^ sx) << 4);
#pragma unroll
            for (int mt = 0; mt < 4; mt++) {
                int row = wm * 64 + mt * 16 + arow;
                ldm_x4(ah[mt], Ah + row * 128 + colA);
                ldm_x4(al[mt], Al + row * 128 + colA);
            }
#pragma unroll
            for (int np = 0; np < 2; np++) {
                int row = wn * 32 + np * 16 + brow;
                ldm_x4(bh[np], Bh + row * 128 + colB);
                ldm_x4(bl[np], Bl + row * 128 + colB);
            }
#pragma unroll
            for (int mt = 0; mt < 4; mt++) {
#pragma unroll
                for (int nt = 0; nt < 4; nt++) {
                    const uint32_t* bhf = &bh[nt >> 1][(nt & 1) * 2];
                    const uint32_t* blf = &bl[nt >> 1][(nt & 1) * 2];
                    mma16816(acc[mt][nt], ah[mt], bhf);
                    mma16816(acc[mt][nt], ah[mt], blf);
                    mma16816(acc[mt][nt], al[mt], bhf);
                }
            }
        }
        __syncthreads();
    }

#pragma unroll
    for (int mt = 0; mt < 4; mt++) {
        int row0 = m0 + wm * 64 + mt * 16 + (lane >> 2);
#pragma unroll
        for (int nt = 0; nt < 4; nt++) {
            int col = n0 + wn * 32 + nt * 8 + (lane & 3) * 2;
            epi_frag(g, acc[mt][nt], row0, col);
        }
    }
}

// ================= host orchestration =================
struct OpDesc {
    const __nv_bfloat16 *Ah, *Al, *Bh, *Bl;
    int Kp;
};

static void fill_args(GemmArgs& g, const OpDesc* ops, int nops, int M, int Nstore,
                      int ldd, const float* bias, float ps, int act,
                      float* D, __nv_bfloat16* Dh, __nv_bfloat16* Dl)
{
    int T = 0;
    for (int o = 0; o < nops; o++) {
        g.Ah[o] = ops[o].Ah; g.Al[o] = ops[o].Al;
        g.Bh[o] = ops[o].Bh; g.Bl[o] = ops[o].Bl;
        g.Kp[o] = ops[o].Kp;
        T += ops[o].Kp / 64;
    }
    g.nops = nops; g.totChunks = T;
    g.M = M; g.Nstore = Nstore; g.ldd = ldd;
    g.bias = bias; g.ps = ps; g.act = act;
    g.D = D; g.Dh = Dh; g.Dl = Dl;
}

extern "C" void kernel_launch(void* const* d_in, const int* in_sizes, int n_in,
                              void* d_out, int out_size)
{
    const float* x_window  = (const float*)d_in[0];
    const float* x_example = (const float*)d_in[1];
    const int*   e_near    = (const int*)d_in[2];
    const int*   e_close   = (const int*)d_in[3];
    const int*   e_refer   = (const int*)d_in[4];
    const float* W_win     = (const float*)d_in[5];
    const float* W_exp     = (const float*)d_in[6];
    const float* W_post    = (const float*)d_in[7];
    const float* Wl_near   = (const float*)d_in[9];
    const float* Wr_near   = (const float*)d_in[10];
    const float* b_near    = (const float*)d_in[11];
    const float* Wl_close  = (const float*)d_in[12];
    const float* Wr_close  = (const float*)d_in[13];
    const float* b_close   = (const float*)d_in[14];
    const float* Wl_refer  = (const float*)d_in[15];
    const float* Wr_refer  = (const float*)d_in[16];
    const float* b_refer   = (const float*)d_in[17];
    const float* w_pool    = (const float*)d_in[18];
    const float* W_lin     = (const float*)d_in[19];
    const float* b_lin     = (const float*)d_in[20];
    float* out = (float*)d_out;

    cudaFuncSetAttribute(gemm_mma, cudaFuncAttributeMaxDynamicSharedMemorySize, GEMM_SMEM);
    cudaFuncSetAttribute(gemm512, cudaFuncAttributeMaxDynamicSharedMemorySize, GEMM_SMEM2);
    cudaFuncSetAttribute(gemm512_pair, cudaFuncAttributeMaxDynamicSharedMemorySize, GEMM_SMEM2);

    float *score, *bsum;
    int *cnt, *off, *cur, *csrc;
    __nv_bfloat16 *wth, *wtl, *bigh, *bigl, *pth, *ptl;
    __nv_bfloat16 *phwh[2], *phwl[2], *pheh[2], *phel[2];
    __nv_bfloat16 *pa0h, *pa0l, *pa1h, *pa1l, *pa2h, *pa2l;
    cudaGetSymbolAddress((void**)&score, g_score);
    cudaGetSymbolAddress((void**)&bsum, g_bsum);
    cudaGetSymbolAddress((void**)&cnt, g_cnt);
    cudaGetSymbolAddress((void**)&off, g_off);
    cudaGetSymbolAddress((void**)&cur, g_cur);
    cudaGetSymbolAddress((void**)&csrc, g_csrc);
    cudaGetSymbolAddress((void**)&wth, g_wth);
    cudaGetSymbolAddress((void**)&wtl, g_wtl);
    cudaGetSymbolAddress((void**)&bigh, g_bigh);
    cudaGetSymbolAddress((void**)&bigl, g_bigl);
    cudaGetSymbolAddress((void**)&pth, g_pth);
    cudaGetSymbolAddress((void**)&ptl, g_ptl);
    cudaGetSymbolAddress((void**)&phwh[0], g_phw0h);
    cudaGetSymbolAddress((void**)&phwl[0], g_phw0l);
    cudaGetSymbolAddress((void**)&phwh[1], g_phw1h);
    cudaGetSymbolAddress((void**)&phwl[1], g_phw1l);
    cudaGetSymbolAddress((void**)&pheh[0], g_phe0h);
    cudaGetSymbolAddress((void**)&phel[0], g_phe0l);
    cudaGetSymbolAddress((void**)&pheh[1], g_phe1h);
    cudaGetSymbolAddress((void**)&phel[1], g_phe1l);
    cudaGetSymbolAddress((void**)&pa0h, g_pa0h);
    cudaGetSymbolAddress((void**)&pa0l, g_pa0l);
    cudaGetSymbolAddress((void**)&pa1h, g_pa1h);
    cudaGetSymbolAddress((void**)&pa1l, g_pa1l);
    cudaGetSymbolAddress((void**)&pa2h, g_pa2h);
    cudaGetSymbolAddress((void**)&pa2l, g_pa2l);

    const unsigned edge_blocks = (EDG + 255) / 256;

    // --- batched weight conversion ---
    {
        ConvBatch cb;
        for (int l = 0; l < NLAYERS; l++) {
            size_t s = (size_t)l * HDIM * HDIM;
            cb.W1[l * 5 + 0] = Wl_near + s;  cb.W2[l * 5 + 0] = nullptr;      cb.dstoff[l * 5 + 0] = WOFF_WLN(l);
            cb.W1[l * 5 + 1] = Wl_refer + s; cb.W2[l * 5 + 1] = nullptr;      cb.dstoff[l * 5 + 1] = WOFF_WLR(l);
            cb.W1[l * 5 + 2] = Wr_near + s;  cb.W2[l * 5 + 2] = Wr_refer + s; cb.dstoff[l * 5 + 2] = WOFF_WSUM(l);
            cb.W1[l * 5 + 3] = Wl_close + s; cb.W2[l * 5 + 3] = nullptr;      cb.dstoff[l * 5 + 3] = WOFF_WLC(l);
            cb.W1[l * 5 + 4] = Wr_close + s; cb.W2[l * 5 + 4] = nullptr;      cb.dstoff[l * 5 + 4] = WOFF_WRC(l);
        }
        cb.W1[20] = W_post; cb.W2[20] = nullptr; cb.dstoff[20] = WOFF_POST;
        dim3 blk(32, 8);
        dim3 gB(HDIM / 32, HDIM / 32, NBATCH);
        conv_w_batch<<<gB, blk>>>(cb, wth, wtl);

        dim3 gWIN(KP_WIN / 32, HDIM / 32);
        conv_w<<<gWIN, blk>>>(W_win, KWIN, HDIM, KP_WIN, wth + WOFF_WIN, wtl + WOFF_WIN);
        dim3 gEXP(128 / 32, HDIM / 32);
        conv_w<<<gEXP, blk>>>(W_exp, KEXP, HDIM, 128, wth + WOFF_EXP, wtl + WOFF_EXP);
        dim3 gLIN(HDIM / 32, 128 / 32);
        conv_w<<<gLIN, blk>>>(W_lin, HDIM, NOUT, HDIM, wth + WOFF_LIN, wtl + WOFF_LIN);
        bias_sum_all<<<(NLAYERS * HDIM + 255) / 256, 256>>>(b_near, b_refer, bsum);
    }

    // --- zero pad rows [NWIN, MP) of plane buffers ---
    {
        PadPtrs pp;
        pp.h[0] = pth;     pp.l[0] = ptl;
        pp.h[1] = phwh[0]; pp.l[1] = phwl[0];
        pp.h[2] = phwh[1]; pp.l[2] = phwl[1];
        pp.h[3] = pheh[0]; pp.l[3] = phel[0];
        pp.h[4] = pheh[1]; pp.l[4] = phel[1];
        pp.h[5] = pa0h;    pp.l[5] = pa0l;
        pp.h[6] = pa1h;    pp.l[6] = pa1l;
        pp.h[7] = pa2h;    pp.l[7] = pa2l;
        int tot = NPAD * (MP - NWIN) * HDIM;
        zero_pad_all<<<(tot + 255) / 256, 256>>>(pp);
    }

    // --- CSR build ---
    {
        EdgePtrs ep;
        ep.es[0] = e_near;  ep.ed[0] = e_near + EDG;
        ep.es[1] = e_refer; ep.ed[1] = e_refer + EDG;
        ep.es[2] = e_close; ep.ed[2] = e_close + EDG;
        zero_int<<<(3 * NWIN + 255) / 256, 256>>>(cnt, 3 * NWIN);
        dim3 ge(edge_blocks, 3);
        hist_all<<<ge, 256>>>(ep, cnt);
        scan_all<<<3, 1024>>>(cnt, off, cur);
        fill_all<<<ge, 256>>>(ep, cur, csrc);
    }

    // --- input projections (paired, 512-thread GEMM) ---
    {
        long long tot = (long long)MP * 128;
        conv_a<<<(unsigned)((tot + 255) / 256), 256>>>(x_example, NEX, KEXP, 128, tot, pa0h, pa0l);
        tot = (long long)MP * KP_WIN;
        conv_a<<<(unsigned)((tot + 255) / 256), 256>>>(x_window, NWIN, KWIN, KP_WIN, tot, bigh, bigl);

        GemmPair pr;
        OpDesc opw = { bigh, bigl, wth + WOFF_WIN, wtl + WOFF_WIN, KP_WIN };
        OpDesc ope = { pa0h, pa0l, wth + WOFF_EXP, wtl + WOFF_EXP, 128 };
        fill_args(pr.g[0], &opw, 1, NWIN, HDIM, HDIM, nullptr, 1.f, 1, nullptr, pth, ptl);
        fill_args(pr.g[1], &ope, 1, NEX, HDIM, HDIM, nullptr, 1.f, 1, nullptr, pa1h, pa1l);
        gemm512_pair<<<dim3(2, 235, 2), 512, GEMM_SMEM2>>>(pr);

        OpDesc opw2 = { pth, ptl, wth + WOFF_POST, wtl + WOFF_POST, HDIM };
        OpDesc ope2 = { pa1h, pa1l, wth + WOFF_POST, wtl + WOFF_POST, HDIM };
        fill_args(pr.g[0], &opw2, 1, NWIN, HDIM, HDIM, nullptr, 1.f, 1, nullptr, phwh[0], phwl[0]);
        fill_args(pr.g[1], &ope2, 1, NEX, HDIM, HDIM, nullptr, 1.f, 1, nullptr, pheh[0], phel[0]);
        gemm512_pair<<<dim3(2, 235, 2), 512, GEMM_SMEM2>>>(pr);
    }

    // --- SAGE layers ---
    int curb = 0;
    for (int l = 0; l < NLAYERS; l++) {
        int nxt = curb ^ 1;
        GatherBatch gb;
        gb.sh[0] = phwh[curb]; gb.sl[0] = phwl[curb];
        gb.sh[1] = pheh[curb]; gb.sl[1] = phel[curb];
        gb.sh[2] = pheh[curb]; gb.sl[2] = phel[curb];
        gb.off[0] = off + 0 * (NWIN + 1); gb.csrc[0] = csrc + 0 * (size_t)EDG; gb.ndst[0] = NWIN;
        gb.off[1] = off + 1 * (NWIN + 1); gb.csrc[1] = csrc + 1 * (size_t)EDG; gb.ndst[1] = NWIN;
        gb.off[2] = off + 2 * (NWIN + 1); gb.csrc[2] = csrc + 2 * (size_t)EDG; gb.ndst[2] = NEX;
        gb.oh[0] = pa0h; gb.ol[0] = pa0l;
        gb.oh[1] = pa1h; gb.ol[1] = pa1l;
        gb.oh[2] = pa2h; gb.ol[2] = pa2l;
        gather_all<<<dim3(MP, 3), 128>>>(gb);

        GemmPair pr;
        OpDesc ops3[3] = {
            { pa0h, pa0l, wth + WOFF_WLN(l), wtl + WOFF_WLN(l), HDIM },
            { pa1h, pa1l, wth + WOFF_WLR(l), wtl + WOFF_WLR(l), HDIM },
            { phwh[curb], phwl[curb], wth + WOFF_WSUM(l), wtl + WOFF_WSUM(l), HDIM },
        };
        OpDesc ops2[2] = {
            { pa2h, pa2l, wth + WOFF_WLC(l), wtl + WOFF_WLC(l), HDIM },
            { pheh[curb], phel[curb], wth + WOFF_WRC(l), wtl + WOFF_WRC(l), HDIM },
        };
        fill_args(pr.g[0], ops3, 3, NWIN, HDIM, HDIM, bsum + (size_t)l * HDIM, 0.5f, 1,
                  nullptr, phwh[nxt], phwl[nxt]);
        fill_args(pr.g[1], ops2, 2, NEX, HDIM, HDIM, b_close + (size_t)l * HDIM, 1.f, 1,
                  nullptr, pheh[nxt], phel[nxt]);
        gemm512_pair<<<dim3(2, 235, 2), 512, GEMM_SMEM2>>>(pr);
        curb = nxt;
    }

    // --- CSRA pooling ---
    gemv_score<<<(NEX + 7) / 8, 256>>>(pheh[curb], phel[curb], w_pool, score);
    pool_gather<<<MP, 128>>>(pheh[curb], phel[curb], phwh[curb], phwl[curb], score,
                             off + 1 * (NWIN + 1), csrc + 1 * (size_t)EDG, NWIN, pth, ptl);

    // out = planes @ W_lin + b_lin (128-wide kernel)
    GemmArgs gf;
    OpDesc opf = { pth, ptl, wth + WOFF_LIN, wtl + WOFF_LIN, HDIM };
    fill_args(gf, &opf, 1, NWIN, NOUT, NOUT, b_lin, 1.f, 0, out, nullptr, nullptr);
    gemm_mma<<<dim3(1, 235), 256, GEMM_SMEM>>>(gf);
}

// round 9
// speedup vs baseline: 1.1751x; 1.0779x over previous
#include <cuda_runtime.h>
#include <cuda_bf16.h>
#include <float.h>
#include <math.h>
#include <stdint.h>

#define NWIN 30000
#define NEX  30000
#define EDG  480000
#define HDIM 512
#define NLAYERS 4
#define KWIN 1949
#define KEXP 100
#define NOUT 100
#define MP   30080
#define KP_WIN 1984

// ================= small fp32 scratch =================
__device__ float g_score[NEX];
__device__ float g_bsum[NLAYERS*HDIM];
__device__ __align__(256) float g_lin0[NWIN*NOUT];   // hw @ W_lin + b_lin
__device__ __align__(256) float g_lin1[NEX*NOUT];    // he @ W_lin

// ================= CSR scratch =================
__device__ int g_cnt[3*NWIN];
__device__ int g_off[3*(NWIN+1)];
__device__ int g_cur[3*NWIN];
__device__ int g_csrc[3*EDG];

// ================= bf16 weight buffers [N][Kp], hi & lo =================
#define WOFF_STEP   (HDIM*HDIM)
#define WOFF_LAYER  (5*WOFF_STEP)
#define WOFF_WLN(l) ((l)*WOFF_LAYER + 0*WOFF_STEP)
#define WOFF_WLR(l) ((l)*WOFF_LAYER + 1*WOFF_STEP)
#define WOFF_WSUM(l)((l)*WOFF_LAYER + 2*WOFF_STEP)
#define WOFF_WLC(l) ((l)*WOFF_LAYER + 3*WOFF_STEP)
#define WOFF_WRC(l) ((l)*WOFF_LAYER + 4*WOFF_STEP)
#define WOFF_POST   (NLAYERS*WOFF_LAYER)
#define WOFF_WIN    (WOFF_POST + WOFF_STEP)
#define WOFF_EXP    (WOFF_WIN + HDIM*KP_WIN)
#define WOFF_LIN    (WOFF_EXP + HDIM*128)
#define WTOTAL      (WOFF_LIN + 128*HDIM)
__device__ __align__(256) __nv_bfloat16 g_wth[WTOTAL];
__device__ __align__(256) __nv_bfloat16 g_wtl[WTOTAL];

// ================= bf16 activation plane buffers =================
__device__ __align__(256) __nv_bfloat16 g_bigh[(size_t)MP*KP_WIN];
__device__ __align__(256) __nv_bfloat16 g_bigl[(size_t)MP*KP_WIN];
__device__ __align__(256) __nv_bfloat16 g_pth[(size_t)MP*HDIM];
__device__ __align__(256) __nv_bfloat16 g_ptl[(size_t)MP*HDIM];
__device__ __align__(256) __nv_bfloat16 g_phw0h[(size_t)MP*HDIM];
__device__ __align__(256) __nv_bfloat16 g_phw0l[(size_t)MP*HDIM];
__device__ __align__(256) __nv_bfloat16 g_phw1h[(size_t)MP*HDIM];
__device__ __align__(256) __nv_bfloat16 g_phw1l[(size_t)MP*HDIM];
__device__ __align__(256) __nv_bfloat16 g_phe0h[(size_t)MP*HDIM];
__device__ __align__(256) __nv_bfloat16 g_phe0l[(size_t)MP*HDIM];
__device__ __align__(256) __nv_bfloat16 g_phe1h[(size_t)MP*HDIM];
__device__ __align__(256) __nv_bfloat16 g_phe1l[(size_t)MP*HDIM];
__device__ __align__(256) __nv_bfloat16 g_pa0h[(size_t)MP*HDIM];
__device__ __align__(256) __nv_bfloat16 g_pa0l[(size_t)MP*HDIM];
__device__ __align__(256) __nv_bfloat16 g_pa1h[(size_t)MP*HDIM];
__device__ __align__(256) __nv_bfloat16 g_pa1l[(size_t)MP*HDIM];
__device__ __align__(256) __nv_bfloat16 g_pa2h[(size_t)MP*HDIM];
__device__ __align__(256) __nv_bfloat16 g_pa2l[(size_t)MP*HDIM];

// ================= helpers =================
__device__ __forceinline__ void split2(float v0, float v1, __nv_bfloat162& h, __nv_bfloat162& l)
{
    __nv_bfloat16 h0 = __float2bfloat16_rn(v0);
    __nv_bfloat16 h1 = __float2bfloat16_rn(v1);
    h.x = h0; h.y = h1;
    l.x = __float2bfloat16_rn(v0 - __bfloat162float(h0));
    l.y = __float2bfloat16_rn(v1 - __bfloat162float(h1));
}

__device__ __forceinline__ float4 recon4(const __nv_bfloat16* __restrict__ h,
                                         const __nv_bfloat16* __restrict__ l,
                                         size_t off)
{
    __nv_bfloat162 h0 = *(const __nv_bfloat162*)(h + off);
    __nv_bfloat162 h1 = *(const __nv_bfloat162*)(h + off + 2);
    __nv_bfloat162 l0 = *(const __nv_bfloat162*)(l + off);
    __nv_bfloat162 l1 = *(const __nv_bfloat162*)(l + off + 2);
    return make_float4(__bfloat162float(h0.x) + __bfloat162float(l0.x),
                       __bfloat162float(h0.y) + __bfloat162float(l0.y),
                       __bfloat162float(h1.x) + __bfloat162float(l1.x),
                       __bfloat162float(h1.y) + __bfloat162float(l1.y));
}

__device__ __forceinline__ void split_store8(float* v, __nv_bfloat16* oh, __nv_bfloat16* ol,
                                             size_t off)
{
    __nv_bfloat162 hh[4], ll[4];
#pragma unroll
    for (int j = 0; j < 4; j++) split2(v[j * 2], v[j * 2 + 1], hh[j], ll[j]);
    *(uint4*)(oh + off) = *(uint4*)hh;
    *(uint4*)(ol + off) = *(uint4*)ll;
}

__device__ __forceinline__ void acc8(float* acc, uint4 q)
{
    const __nv_bfloat162* b2 = (const __nv_bfloat162*)&q;
#pragma unroll
    for (int j = 0; j < 4; j++) {
        acc[j * 2 + 0] += __bfloat162float(b2[j].x);
        acc[j * 2 + 1] += __bfloat162float(b2[j].y);
    }
}

// ================= batched HxH weight conversion =================
#define NBATCH 21
struct ConvBatch {
    const float* W1[NBATCH];
    const float* W2[NBATCH];
    int dstoff[NBATCH];
};

__global__ void conv_w_batch(const __grid_constant__ ConvBatch cb,
                             __nv_bfloat16* __restrict__ ohb,
                             __nv_bfloat16* __restrict__ olb)
{
    __shared__ float t[32][33];
    int z = blockIdx.z;
    const float* W = cb.W1[z];
    const float* W2 = cb.W2[z];
    __nv_bfloat16* oh = ohb + cb.dstoff[z];
    __nv_bfloat16* ol = olb + cb.dstoff[z];
    int k0 = blockIdx.x * 32, n0 = blockIdx.y * 32;
    int tx = threadIdx.x, ty = threadIdx.y;
#pragma unroll
    for (int i = 0; i < 4; i++) {
        int k = k0 + ty + i * 8, n = n0 + tx;
        float v = W[(size_t)k * HDIM + n];
        if (W2) v += W2[(size_t)k * HDIM + n];
        t[ty + i * 8][tx] = v;
    }
    __syncthreads();
#pragma unroll
    for (int i = 0; i < 4; i++) {
        int n = n0 + ty + i * 8, k = k0 + tx;
        float v = t[tx][ty + i * 8];
        __nv_bfloat16 hb = __float2bfloat16_rn(v);
        oh[(size_t)n * HDIM + k] = hb;
        ol[(size_t)n * HDIM + k] = __float2bfloat16_rn(v - __bfloat162float(hb));
    }
}

__global__ void conv_w(const float* __restrict__ W, int K, int N, int Kp,
                       __nv_bfloat16* __restrict__ oh, __nv_bfloat16* __restrict__ ol)
{
    __shared__ float t[32][33];
    int k0 = blockIdx.x * 32, n0 = blockIdx.y * 32;
    int tx = threadIdx.x, ty = threadIdx.y;
#pragma unroll
    for (int i = 0; i < 4; i++) {
        int k = k0 + ty + i * 8, n = n0 + tx;
        float v = 0.f;
        if (k < K && n < N) v = W[(size_t)k * N + n];
        t[ty + i * 8][tx] = v;
    }
    __syncthreads();
#pragma unroll
    for (int i = 0; i < 4; i++) {
        int n = n0 + ty + i * 8, k = k0 + tx;
        float v = t[tx][ty + i * 8];
        __nv_bfloat16 hb = __float2bfloat16_rn(v);
        oh[(size_t)n * Kp + k] = hb;
        ol[(size_t)n * Kp + k] = __float2bfloat16_rn(v - __bfloat162float(hb));
    }
}

__global__ void conv_a(const float* __restrict__ A, int M, int K, int Kp, long long total,
                       __nv_bfloat16* __restrict__ oh, __nv_bfloat16* __restrict__ ol)
{
    long long i = (long long)blockIdx.x * blockDim.x + threadIdx.x;
    if (i >= total) return;
    int m = (int)(i / Kp);
    int k = (int)(i % Kp);
    float v = 0.f;
    if (m < M && k < K) v = A[(size_t)m * K + k];
    __nv_bfloat16 hb = __float2bfloat16_rn(v);
    oh[i] = hb;
    ol[i] = __float2bfloat16_rn(v - __bfloat162float(hb));
}

__global__ void bias_sum_all(const float* a, const float* b, float* o)
{
    int i = blockIdx.x * blockDim.x + threadIdx.x;
    if (i < NLAYERS * HDIM) o[i] = a[i] + b[i];
}

__global__ void zero_int(int* p, int n)
{
    int i = blockIdx.x * blockDim.x + threadIdx.x;
    if (i < n) p[i] = 0;
}

#define NPAD 8
struct PadPtrs { __nv_bfloat16* h[NPAD]; __nv_bfloat16* l[NPAD]; };
__global__ void zero_pad_all(const __grid_constant__ PadPtrs pp)
{
    int i = blockIdx.x * blockDim.x + threadIdx.x;
    const int per = (MP - NWIN) * HDIM;
    int z = i / per;
    if (z >= NPAD) return;
    int r = i - z * per;
    pp.h[z][(size_t)NWIN * HDIM + r] = __float2bfloat16_rn(0.f);
    pp.l[z][(size_t)NWIN * HDIM + r] = __float2bfloat16_rn(0.f);
}

// ================= CSR build =================
struct EdgePtrs { const int* es[3]; const int* ed[3]; };

__global__ void hist_all(const __grid_constant__ EdgePtrs ep, int* __restrict__ cnt)
{
    int r = blockIdx.y;
    int e = blockIdx.x * blockDim.x + threadIdx.x;
    if (e < EDG) atomicAdd(&cnt[r * NWIN + ep.ed[r][e]], 1);
}

__global__ void scan_all(const int* __restrict__ cnt, int* __restrict__ off,
                         int* __restrict__ cur)
{
    __shared__ int s[1024];
    int r = blockIdx.x;
    const int* c = cnt + r * NWIN;
    int* of = off + r * (NWIN + 1);
    int* cu = cur + r * NWIN;
    int t = threadIdx.x;
    int chunk = (NWIN + 1023) >> 10;
    int b = t * chunk, e = min(b + chunk, NWIN);
    int sum = 0;
    for (int i = b; i < e; i++) sum += c[i];
    s[t] = sum;
    __syncthreads();
    for (int d = 1; d < 1024; d <<= 1) {
        int v = (t >= d) ? s[t - d] : 0;
        __syncthreads();
        s[t] += v;
        __syncthreads();
    }
    int run = (t == 0) ? 0 : s[t - 1];
    for (int i = b; i < e; i++) {
        of[i] = run; cu[i] = run; run += c[i];
    }
    if (t == 0) of[NWIN] = s[1023];
}

__global__ void fill_all(const __grid_constant__ EdgePtrs ep, int* __restrict__ cur,
                         int* __restrict__ csrc)
{
    int r = blockIdx.y;
    int e = blockIdx.x * blockDim.x + threadIdx.x;
    if (e < EDG) {
        int p = atomicAdd(&cur[r * NWIN + ep.ed[r][e]], 1);
        csrc[(size_t)r * EDG + p] = ep.es[r][e];
    }
}

// ================= fused 3-relation gather-mean (hi/lo split, 4-way MLP) =========
struct GatherBatch {
    const __nv_bfloat16 *sh[3], *sl[3];
    const int *off[3], *csrc[3];
    int ndst[3];
    __nv_bfloat16 *oh[3], *ol[3];
};

__global__ void gather_all(const __grid_constant__ GatherBatch gb)
{
    __shared__ float sm[512];
    int r = blockIdx.y;
    int d = blockIdx.x;
    int t = threadIdx.x;
    const bool isLo = t >= 64;
    const int c = (t & 63) * 8;
    const __nv_bfloat16* src = isLo ? gb.sl[r] : gb.sh[r];

    float acc[8];
#pragma unroll
    for (int j = 0; j < 8; j++) acc[j] = 0.f;
    int deg = 0;
    if (d < gb.ndst[r]) {
        const int* off = gb.off[r];
        const int* cs = gb.csrc[r];
        int s0 = off[d], s1 = off[d + 1];
        deg = s1 - s0;
        int e = s0;
        for (; e + 4 <= s1; e += 4) {
            int i0 = cs[e], i1 = cs[e + 1], i2 = cs[e + 2], i3 = cs[e + 3];
            uint4 q0 = *(const uint4*)(src + (size_t)i0 * HDIM + c);
            uint4 q1 = *(const uint4*)(src + (size_t)i1 * HDIM + c);
            uint4 q2 = *(const uint4*)(src + (size_t)i2 * HDIM + c);
            uint4 q3 = *(const uint4*)(src + (size_t)i3 * HDIM + c);
            acc8(acc, q0); acc8(acc, q1); acc8(acc, q2); acc8(acc, q3);
        }
        for (; e < s1; e++) {
            uint4 q = *(const uint4*)(src + (size_t)cs[e] * HDIM + c);
            acc8(acc, q);
        }
    }
    if (isLo) {
#pragma unroll
        for (int j = 0; j < 8; j++) sm[(t - 64) * 8 + j] = acc[j];
    }
    __syncthreads();
    if (!isLo) {
        float inv = 1.f / (float)max(deg, 1);
        float v[8];
#pragma unroll
        for (int j = 0; j < 8; j++) v[j] = (acc[j] + sm[t * 8 + j]) * inv;
        split_store8(v, gb.oh[r], gb.ol[r], (size_t)d * HDIM + c);
    }
}

// ================= low-dim CSRA pooling: out = hwlin + 0.5*sum att*helin[src] ======
__global__ void pool_small(const float* __restrict__ helin,
                           const float* __restrict__ hwlin,
                           const float* __restrict__ score,
                           const int* __restrict__ off, const int* __restrict__ csrc,
                           float* __restrict__ out)
{
    __shared__ float red[128];
    __shared__ float wts[128];
    __shared__ int   idx[128];
    int d = blockIdx.x;
    int t = threadIdx.x;
    if (d >= NWIN) return;
    int s0 = off[d], s1 = off[d + 1];

    float m = -FLT_MAX;
    for (int e = s0 + t; e < s1; e += 128) m = fmaxf(m, score[csrc[e]]);
    red[t] = m; __syncthreads();
    for (int w = 64; w; w >>= 1) {
        if (t < w) red[t] = fmaxf(red[t], red[t + w]);
        __syncthreads();
    }
    float smax = red[0];
    __syncthreads();
    float z = 0.f;
    for (int e = s0 + t; e < s1; e += 128) z += expf(score[csrc[e]] - smax);
    red[t] = z; __syncthreads();
    for (int w = 64; w; w >>= 1) {
        if (t < w) red[t] += red[t + w];
        __syncthreads();
    }
    float invz = 1.f / fmaxf(red[0], 1e-12f);
    __syncthreads();

    float acc = 0.f;
    for (int base = s0; base < s1; base += 128) {
        int e = base + t;
        if (e < s1) {
            int si = csrc[e];
            idx[t] = si;
            wts[t] = expf(score[si] - smax) * invz;
        }
        __syncthreads();
        int cnt = min(128, s1 - base);
        if (t < NOUT) {
            for (int j = 0; j < cnt; j++)
                acc += wts[j] * helin[(size_t)idx[j] * NOUT + t];
        }
        __syncthreads();
    }
    if (t < NOUT)
        out[(size_t)d * NOUT + t] = hwlin[(size_t)d * NOUT + t] + 0.5f * acc;
}

__global__ void gemv_score(const __nv_bfloat16* __restrict__ heh,
                           const __nv_bfloat16* __restrict__ hel,
                           const float* __restrict__ w, float* __restrict__ sc)
{
    int row = blockIdx.x * 8 + (threadIdx.x >> 5);
    if (row >= NEX) return;
    int lane = threadIdx.x & 31;
    float s = 0.f;
#pragma unroll
    for (int k = lane * 4; k < HDIM; k += 128) {
        float4 v = recon4(heh, hel, (size_t)row * HDIM + k);
        s += v.x * w[k] + v.y * w[k + 1] + v.z * w[k + 2] + v.w * w[k + 3];
    }
#pragma unroll
    for (int o = 16; o; o >>= 1) s += __shfl_down_sync(0xFFFFFFFFu, s, o);
    if (lane == 0) sc[row] = s;
}

// ================= GEMM common =================
struct GemmArgs {
    const __nv_bfloat16 *Ah[3], *Al[3], *Bh[3], *Bl[3];
    int Kp[3];
    int nops, totChunks;
    int M, Nstore, ldd;
    const float* bias;
    float ps;
    int act;
    float* D;
    __nv_bfloat16 *Dh, *Dl;
};
struct GemmPair { GemmArgs g[2]; };

__device__ __forceinline__ uint32_t smem_u32(const void* p) {
    uint32_t a;
    asm("{ .reg .u64 t; cvta.to.shared.u64 t, %1; cvt.u32.u64 %0, t; }" : "=r"(a) : "l"(p));
    return a;
}
__device__ __forceinline__ void cp16(uint32_t dst, const void* src) {
    asm volatile("cp.async.cg.shared.global [%0], [%1], 16;" :: "r"(dst), "l"(src));
}
__device__ __forceinline__ void cp_commit() { asm volatile("cp.async.commit_group;"); }
__device__ __forceinline__ void cp_wait0() { asm volatile("cp.async.wait_group 0;"); }
__device__ __forceinline__ void cp_wait1() { asm volatile("cp.async.wait_group 1;"); }

__device__ __forceinline__ void ldm_x4(uint32_t* r, uint32_t addr) {
    asm volatile("ldmatrix.sync.aligned.m8n8.x4.shared.b16 {%0,%1,%2,%3}, [%4];"
                 : "=r"(r[0]), "=r"(r[1]), "=r"(r[2]), "=r"(r[3]) : "r"(addr));
}
__device__ __forceinline__ void mma16816(float* c, const uint32_t* a, const uint32_t* b) {
    asm volatile("mma.sync.aligned.m16n8k16.row.col.f32.bf16.bf16.f32 "
                 "{%0,%1,%2,%3},{%4,%5,%6,%7},{%8,%9},{%0,%1,%2,%3};"
                 : "+f"(c[0]), "+f"(c[1]), "+f"(c[2]), "+f"(c[3])
                 : "r"(a[0]), "r"(a[1]), "r"(a[2]), "r"(a[3]), "r"(b[0]), "r"(b[1]));
}

__device__ __forceinline__ void map_oc(const GemmArgs& g, int t, int& o, int& c) {
    o = 0;
    int rem = t;
    while (o < g.nops - 1 && rem >= (g.Kp[o] >> 6)) { rem -= (g.Kp[o] >> 6); o++; }
    c = rem;
}

__device__ __forceinline__ void epi_frag(const GemmArgs& g, const float* a4,
                                         int row0, int col)
{
    if (col >= g.Nstore) return;
    float b0 = 0.f, b1 = 0.f;
    if (g.bias) {
        b0 = g.bias[col];
        if (col + 1 < g.Nstore) b1 = g.bias[col + 1];
    }
#pragma unroll
    for (int rr = 0; rr < 2; rr++) {
        int r = row0 + rr * 8;
        if (r >= g.M) continue;
        float v0 = (a4[rr * 2 + 0] + b0) * g.ps;
        float v1 = (a4[rr * 2 + 1] + b1) * g.ps;
        if (g.act) {
            v0 = v0 > 0.f ? v0 : 0.2f * v0;
            v1 = v1 > 0.f ? v1 : 0.2f * v1;
        }
        if (g.D) {
            float* dp = g.D + (size_t)r * g.ldd + col;
            if (col + 1 < g.Nstore) *(float2*)dp = make_float2(v0, v1);
            else *dp = v0;
        }
        if (g.Dh) {
            __nv_bfloat162 hh, ll;
            split2(v0, v1, hh, ll);
            size_t po = (size_t)r * HDIM + col;
            *(__nv_bfloat162*)(g.Dh + po) = hh;
            *(__nv_bfloat162*)(g.Dl + po) = ll;
        }
    }
}

// ================= 512-thread 128x256 GEMM =================
#define STAGE2      98304
#define GEMM_SMEM2  (2 * STAGE2)

__device__ __forceinline__ void load_stage512(const GemmArgs& g, int t, uint32_t sb,
                                              int tid, int m0, int n0)
{
    int o, c;
    map_oc(g, t, o, c);
    const int Kp = g.Kp[o];
    const int k0 = c << 6;
    {
        const __nv_bfloat16* bh_ = g.Ah[o] + (size_t)m0 * Kp + k0;
        const __nv_bfloat16* bl_ = g.Al[o] + (size_t)m0 * Kp + k0;
#pragma unroll
        for (int it = 0; it < 2; it++) {
            int idx = it * 512 + tid;
            int r = idx >> 3;
            int j = idx & 7;
            uint32_t sw = r * 128 + ((j ^ (r & 7)) << 4);
            cp16(sb + sw, bh_ + (size_t)r * Kp + j * 8);
            cp16(sb + 16384 + sw, bl_ + (size_t)r * Kp + j * 8);
        }
    }
    {
        const __nv_bfloat16* bh_ = g.Bh[o] + (size_t)n0 * Kp + k0;
        const __nv_bfloat16* bl_ = g.Bl[o] + (size_t)n0 * Kp + k0;
#pragma unroll
        for (int it = 0; it < 4; it++) {
            int idx = it * 512 + tid;
            int r = idx >> 3;
            int j = idx & 7;
            uint32_t sw = r * 128 + ((j ^ (r & 7)) << 4);
            cp16(sb + 32768 + sw, bh_ + (size_t)r * Kp + j * 8);
            cp16(sb + 65536 + sw, bl_ + (size_t)r * Kp + j * 8);
        }
    }
    cp_commit();
}

__device__ __forceinline__ void gemm_body512(const GemmArgs& g, char* smem)
{
    const uint32_t sbase = smem_u32(smem);
    const int tid = threadIdx.x;
    const int lane = tid & 31;
    const int warp = tid >> 5;
    const int wm = warp >> 2;
    const int wn = warp & 3;
    const int m0 = blockIdx.y * 128;
    const int n0 = blockIdx.x * 256;

    float acc[2][8][4];
#pragma unroll
    for (int i = 0; i < 2; i++)
#pragma unroll
        for (int j = 0; j < 8; j++)
#pragma unroll
            for (int q = 0; q < 4; q++) acc[i][j][q] = 0.f;

    const int sx = lane & 7;
    const int arow = (lane & 7) + ((lane >> 3) & 1) * 8;
    const int khia = (lane >> 4) & 1;
    const int brow = (lane & 7) + ((lane >> 4) & 1) * 8;
    const int khib = (lane >> 3) & 1;

    const int T = g.totChunks;
    load_stage512(g, 0, sbase, tid, m0, n0);

    for (int t = 0; t < T; t++) {
        if (t + 1 < T) {
            load_stage512(g, t + 1, sbase + ((t + 1) & 1) * STAGE2, tid, m0, n0);
            cp_wait1();
        } else {
            cp_wait0();
        }
        __syncthreads();

        const uint32_t Ah = sbase + (t & 1) * STAGE2;
        const uint32_t Al = Ah + 16384;
        const uint32_t Bh = Ah + 32768;
        const uint32_t Bl = Ah + 65536;

#pragma unroll
        for (int ks = 0; ks < 4; ks++) {
            const uint32_t colA = (uint32_t)(((ks * 2 + khia) ^ sx) << 4);
            const uint32_t colB = (uint32_t)(((ks * 2 + khib) ^ sx) << 4);
            uint32_t ah[2][4], al[2][4];
#pragma unroll
            for (int mt = 0; mt < 2; mt++) {
                int row = wm * 32 + mt * 16 + arow;
                ldm_x4(ah[mt], Ah + row * 128 + colA);
                ldm_x4(al[mt], Al + row * 128 + colA);
            }
#pragma unroll
            for (int half = 0; half < 2; half++) {
                uint32_t bh[2][4], bl[2][4];
#pragma unroll
                for (int np = 0; np < 2; np++) {
                    int row = wn * 64 + half * 32 + np * 16 + brow;
                    ldm_x4(bh[np], Bh + row * 128 + colB);
                    ldm_x4(bl[np], Bl + row * 128 + colB);
                }
#pragma unroll
                for (int mt = 0; mt < 2; mt++) {
#pragma unroll
                    for (int nt = 0; nt < 4; nt++) {
                        const uint32_t* bhf = &bh[nt >> 1][(nt & 1) * 2];
                        const uint32_t* blf = &bl[nt >> 1][(nt & 1) * 2];
                        float* a_ = acc[mt][half * 4 + nt];
                        mma16816(a_, ah[mt], bhf);
                        mma16816(a_, ah[mt], blf);
                        mma16816(a_, al[mt], bhf);
                    }
                }
            }
        }
        __syncthreads();
    }

#pragma unroll
    for (int mt = 0; mt < 2; mt++) {
        int row0 = m0 + wm * 32 + mt * 16 + (lane >> 2);
#pragma unroll
        for (int nt = 0; nt < 8; nt++) {
            int col = n0 + wn * 64 + nt * 8 + (lane & 3) * 2;
            epi_frag(g, acc[mt][nt], row0, col);
        }
    }
}

__global__ __launch_bounds__(512, 1) void gemm512_pair(const __grid_constant__ GemmPair p)
{
    extern __shared__ __align__(128) char smem[];
    gemm_body512(p.g[blockIdx.z], smem);
}

// ================= 256-thread 128x128 GEMM =================
#define STAGE_BYTES 65536
#define GEMM_SMEM   (2 * STAGE_BYTES)

__device__ __forceinline__ void load_stage(const GemmArgs& g, int t, uint32_t sb,
                                           int tid, int m0, int n0)
{
    int o, c;
    map_oc(g, t, o, c);
    const int Kp = g.Kp[o];
    const int k0 = c << 6;
    {
        const __nv_bfloat16* baseh = g.Ah[o] + (size_t)m0 * Kp + k0;
        const __nv_bfloat16* basel = g.Al[o] + (size_t)m0 * Kp + k0;
#pragma unroll
        for (int it = 0; it < 4; it++) {
            int idx = it * 256 + tid;
            int r = idx >> 3;
            int j = idx & 7;
            uint32_t sw = r * 128 + ((j ^ (r & 7)) << 4);
            cp16(sb + sw, baseh + (size_t)r * Kp + j * 8);
            cp16(sb + 16384 + sw, basel + (size_t)r * Kp + j * 8);
        }
    }
    {
        const __nv_bfloat16* baseh = g.Bh[o] + (size_t)n0 * Kp + k0;
        const __nv_bfloat16* basel = g.Bl[o] + (size_t)n0 * Kp + k0;
#pragma unroll
        for (int it = 0; it < 4; it++) {
            int idx = it * 256 + tid;
            int r = idx >> 3;
            int j = idx & 7;
            uint32_t sw = r * 128 + ((j ^ (r & 7)) << 4);
            cp16(sb + 32768 + sw, baseh + (size_t)r * Kp + j * 8);
            cp16(sb + 49152 + sw, basel + (size_t)r * Kp + j * 8);
        }
    }
    cp_commit();
}

__device__ __forceinline__ void gemm_body128(const GemmArgs& g, char* smem)
{
    const uint32_t sbase = smem_u32(smem);
    const int tid = threadIdx.x;
    const int lane = tid & 31;
    const int warp = tid >> 5;
    const int wm = warp >> 2;
    const int wn = warp & 3;
    const int m0 = blockIdx.y * 128;
    const int n0 = blockIdx.x * 128;

    float acc[4][4][4];
#pragma unroll
    for (int i = 0; i < 4; i++)
#pragma unroll
        for (int j = 0; j < 4; j++)
#pragma unroll
            for (int q = 0; q < 4; q++) acc[i][j][q] = 0.f;

    const int sx = lane & 7;
    const int arow = (lane & 7) + ((lane >> 3) & 1) * 8;
    const int khia = (lane >> 4) & 1;
    const int brow = (lane & 7) + ((lane >> 4) & 1) * 8;
    const int khib = (lane >> 3) & 1;

    const int T = g.totChunks;
    load_stage(g, 0, sbase, tid, m0, n0);

    for (int t = 0; t < T; t++) {
        if (t + 1 < T) {
            load_stage(g, t + 1, sbase + ((t + 1) & 1) * STAGE_BYTES, tid, m0, n0);
            cp_wait1();
        } else {
            cp_wait0();
        }
        __syncthreads();

        const uint32_t Ah = sbase + (t & 1) * STAGE_BYTES;
        const uint32_t Al = Ah + 16384;
        const uint32_t Bh = Ah + 32768;
        const uint32_t Bl = Ah + 49152;

#pragma unroll
        for (int ks = 0; ks < 4; ks++) {
            uint32_t ah[4][4], al[4][4], bh[2][4], bl[2][4];
            const uint32_t colA = (uint32_t)(((ks * 2 + khia) ^ sx) << 4);
            const uint32_t colB = (uint32_t)(((ks * 2 + khib) ^ sx) << 4);
#pragma unroll
            for (int mt = 0; mt < 4; mt++) {
                int row = wm * 64 + mt * 16 + arow;
                ldm_x4(ah[mt], Ah + row * 128 + colA);
                ldm_x4(al[mt], Al + row * 128 + colA);
            }
#pragma unroll
            for (int np = 0; np < 2; np++) {
                int row = wn * 32 + np * 16 + brow;
                ldm_x4(bh[np], Bh + row * 128 + colB);
                ldm_x4(bl[np], Bl + row * 128 + colB);
            }
#pragma unroll
            for (int mt = 0; mt < 4; mt++) {
#pragma unroll
                for (int nt = 0; nt < 4; nt++) {
                    const uint32_t* bhf = &bh[nt >> 1][(nt & 1) * 2];
                    const uint32_t* blf = &bl[nt >> 1][(nt & 1) * 2];
                    mma16816(acc[mt][nt], ah[mt], bhf);
                    mma16816(acc[mt][nt], ah[mt], blf);
                    mma16816(acc[mt][nt], al[mt], bhf);
                }
            }
        }
        __syncthreads();
    }

#pragma unroll
    for (int mt = 0; mt < 4; mt++) {
        int row0 = m0 + wm * 64 + mt * 16 + (lane >> 2);
#pragma unroll
        for (int nt = 0; nt < 4; nt++) {
            int col = n0 + wn * 32 + nt * 8 + (lane & 3) * 2;
            epi_frag(g, acc[mt][nt], row0, col);
        }
    }
}

__global__ __launch_bounds__(256, 1) void gemm_mma_pair(const __grid_constant__ GemmPair p)
{
    extern __shared__ __align__(128) char smem[];
    gemm_body128(p.g[blockIdx.z], smem);
}

// ================= host orchestration =================
struct OpDesc {
    const __nv_bfloat16 *Ah, *Al, *Bh, *Bl;
    int Kp;
};

static void fill_args(GemmArgs& g, const OpDesc* ops, int nops, int M, int Nstore,
                      int ldd, const float* bias, float ps, int act,
                      float* D, __nv_bfloat16* Dh, __nv_bfloat16* Dl)
{
    int T = 0;
    for (int o = 0; o < nops; o++) {
        g.Ah[o] = ops[o].Ah; g.Al[o] = ops[o].Al;
        g.Bh[o] = ops[o].Bh; g.Bl[o] = ops[o].Bl;
        g.Kp[o] = ops[o].Kp;
        T += ops[o].Kp / 64;
    }
    g.nops = nops; g.totChunks = T;
    g.M = M; g.Nstore = Nstore; g.ldd = ldd;
    g.bias = bias; g.ps = ps; g.act = act;
    g.D = D; g.Dh = Dh; g.Dl = Dl;
}

extern "C" void kernel_launch(void* const* d_in, const int* in_sizes, int n_in,
                              void* d_out, int out_size)
{
    const float* x_window  = (const float*)d_in[0];
    const float* x_example = (const float*)d_in[1];
    const int*   e_near    = (const int*)d_in[2];
    const int*   e_close   = (const int*)d_in[3];
    const int*   e_refer   = (const int*)d_in[4];
    const float* W_win     = (const float*)d_in[5];
    const float* W_exp     = (const float*)d_in[6];
    const float* W_post    = (const float*)d_in[7];
    const float* Wl_near   = (const float*)d_in[9];
    const float* Wr_near   = (const float*)d_in[10];
    const float* b_near    = (const float*)d_in[11];
    const float* Wl_close  = (const float*)d_in[12];
    const float* Wr_close  = (const float*)d_in[13];
    const float* b_close   = (const float*)d_in[14];
    const float* Wl_refer  = (const float*)d_in[15];
    const float* Wr_refer  = (const float*)d_in[16];
    const float* b_refer   = (const float*)d_in[17];
    const float* w_pool    = (const float*)d_in[18];
    const float* W_lin     = (const float*)d_in[19];
    const float* b_lin     = (const float*)d_in[20];
    float* out = (float*)d_out;

    cudaFuncSetAttribute(gemm_mma_pair, cudaFuncAttributeMaxDynamicSharedMemorySize, GEMM_SMEM);
    cudaFuncSetAttribute(gemm512_pair, cudaFuncAttributeMaxDynamicSharedMemorySize, GEMM_SMEM2);

    float *score, *bsum, *lin0, *lin1;
    int *cnt, *off, *cur, *csrc;
    __nv_bfloat16 *wth, *wtl, *bigh, *bigl, *pth, *ptl;
    __nv_bfloat16 *phwh[2], *phwl[2], *pheh[2], *phel[2];
    __nv_bfloat16 *pa0h, *pa0l, *pa1h, *pa1l, *pa2h, *pa2l;
    cudaGetSymbolAddress((void**)&score, g_score);
    cudaGetSymbolAddress((void**)&bsum, g_bsum);
    cudaGetSymbolAddress((void**)&lin0, g_lin0);
    cudaGetSymbolAddress((void**)&lin1, g_lin1);
    cudaGetSymbolAddress((void**)&cnt, g_cnt);
    cudaGetSymbolAddress((void**)&off, g_off);
    cudaGetSymbolAddress((void**)&cur, g_cur);
    cudaGetSymbolAddress((void**)&csrc, g_csrc);
    cudaGetSymbolAddress((void**)&wth, g_wth);
    cudaGetSymbolAddress((void**)&wtl, g_wtl);
    cudaGetSymbolAddress((void**)&bigh, g_bigh);
    cudaGetSymbolAddress((void**)&bigl, g_bigl);
    cudaGetSymbolAddress((void**)&pth, g_pth);
    cudaGetSymbolAddress((void**)&ptl, g_ptl);
    cudaGetSymbolAddress((void**)&phwh[0], g_phw0h);
    cudaGetSymbolAddress((void**)&phwl[0], g_phw0l);
    cudaGetSymbolAddress((void**)&phwh[1], g_phw1h);
    cudaGetSymbolAddress((void**)&phwl[1], g_phw1l);
    cudaGetSymbolAddress((void**)&pheh[0], g_phe0h);
    cudaGetSymbolAddress((void**)&phel[0], g_phe0l);
    cudaGetSymbolAddress((void**)&pheh[1], g_phe1h);
    cudaGetSymbolAddress((void**)&phel[1], g_phe1l);
    cudaGetSymbolAddress((void**)&pa0h, g_pa0h);
    cudaGetSymbolAddress((void**)&pa0l, g_pa0l);
    cudaGetSymbolAddress((void**)&pa1h, g_pa1h);
    cudaGetSymbolAddress((void**)&pa1l, g_pa1l);
    cudaGetSymbolAddress((void**)&pa2h, g_pa2h);
    cudaGetSymbolAddress((void**)&pa2l, g_pa2l);

    const unsigned edge_blocks = (EDG + 255) / 256;

    // --- batched weight conversion ---
    {
        ConvBatch cb;
        for (int l = 0; l < NLAYERS; l++) {
            size_t s = (size_t)l * HDIM * HDIM;
            cb.W1[l * 5 + 0] = Wl_near + s;  cb.W2[l * 5 + 0] = nullptr;      cb.dstoff[l * 5 + 0] = WOFF_WLN(l);
            cb.W1[l * 5 + 1] = Wl_refer + s; cb.W2[l * 5 + 1] = nullptr;      cb.dstoff[l * 5 + 1] = WOFF_WLR(l);
            cb.W1[l * 5 + 2] = Wr_near + s;  cb.W2[l * 5 + 2] = Wr_refer + s; cb.dstoff[l * 5 + 2] = WOFF_WSUM(l);
            cb.W1[l * 5 + 3] = Wl_close + s; cb.W2[l * 5 + 3] = nullptr;      cb.dstoff[l * 5 + 3] = WOFF_WLC(l);
            cb.W1[l * 5 + 4] = Wr_close + s; cb.W2[l * 5 + 4] = nullptr;      cb.dstoff[l * 5 + 4] = WOFF_WRC(l);
        }
        cb.W1[20] = W_post; cb.W2[20] = nullptr; cb.dstoff[20] = WOFF_POST;
        dim3 blk(32, 8);
        dim3 gB(HDIM / 32, HDIM / 32, NBATCH);
        conv_w_batch<<<gB, blk>>>(cb, wth, wtl);

        dim3 gWIN(KP_WIN / 32, HDIM / 32);
        conv_w<<<gWIN, blk>>>(W_win, KWIN, HDIM, KP_WIN, wth + WOFF_WIN, wtl + WOFF_WIN);
        dim3 gEXP(128 / 32, HDIM / 32);
        conv_w<<<gEXP, blk>>>(W_exp, KEXP, HDIM, 128, wth + WOFF_EXP, wtl + WOFF_EXP);
        dim3 gLIN(HDIM / 32, 128 / 32);
        conv_w<<<gLIN, blk>>>(W_lin, HDIM, NOUT, HDIM, wth + WOFF_LIN, wtl + WOFF_LIN);
        bias_sum_all<<<(NLAYERS * HDIM + 255) / 256, 256>>>(b_near, b_refer, bsum);
    }

    // --- zero pad rows [NWIN, MP) of plane buffers ---
    {
        PadPtrs pp;
        pp.h[0] = pth;     pp.l[0] = ptl;
        pp.h[1] = phwh[0]; pp.l[1] = phwl[0];
        pp.h[2] = phwh[1]; pp.l[2] = phwl[1];
        pp.h[3] = pheh[0]; pp.l[3] = phel[0];
        pp.h[4] = pheh[1]; pp.l[4] = phel[1];
        pp.h[5] = pa0h;    pp.l[5] = pa0l;
        pp.h[6] = pa1h;    pp.l[6] = pa1l;
        pp.h[7] = pa2h;    pp.l[7] = pa2l;
        int tot = NPAD * (MP - NWIN) * HDIM;
        zero_pad_all<<<(tot + 255) / 256, 256>>>(pp);
    }

    // --- CSR build ---
    {
        EdgePtrs ep;
        ep.es[0] = e_near;  ep.ed[0] = e_near + EDG;
        ep.es[1] = e_refer; ep.ed[1] = e_refer + EDG;
        ep.es[2] = e_close; ep.ed[2] = e_close + EDG;
        zero_int<<<(3 * NWIN + 255) / 256, 256>>>(cnt, 3 * NWIN);
        dim3 ge(edge_blocks, 3);
        hist_all<<<ge, 256>>>(ep, cnt);
        scan_all<<<3, 1024>>>(cnt, off, cur);
        fill_all<<<ge, 256>>>(ep, cur, csrc);
    }

    // --- input projections (paired, 512-thread GEMM) ---
    {
        long long tot = (long long)MP * 128;
        conv_a<<<(unsigned)((tot + 255) / 256), 256>>>(x_example, NEX, KEXP, 128, tot, pa0h, pa0l);
        tot = (long long)MP * KP_WIN;
        conv_a<<<(unsigned)((tot + 255) / 256), 256>>>(x_window, NWIN, KWIN, KP_WIN, tot, bigh, bigl);

        GemmPair pr;
        OpDesc opw = { bigh, bigl, wth + WOFF_WIN, wtl + WOFF_WIN, KP_WIN };
        OpDesc ope = { pa0h, pa0l, wth + WOFF_EXP, wtl + WOFF_EXP, 128 };
        fill_args(pr.g[0], &opw, 1, NWIN, HDIM, HDIM, nullptr, 1.f, 1, nullptr, pth, ptl);
        fill_args(pr.g[1], &ope, 1, NEX, HDIM, HDIM, nullptr, 1.f, 1, nullptr, pa1h, pa1l);
        gemm512_pair<<<dim3(2, 235, 2), 512, GEMM_SMEM2>>>(pr);

        OpDesc opw2 = { pth, ptl, wth + WOFF_POST, wtl + WOFF_POST, HDIM };
        OpDesc ope2 = { pa1h, pa1l, wth + WOFF_POST, wtl + WOFF_POST, HDIM };
        fill_args(pr.g[0], &opw2, 1, NWIN, HDIM, HDIM, nullptr, 1.f, 1, nullptr, phwh[0], phwl[0]);
        fill_args(pr.g[1], &ope2, 1, NEX, HDIM, HDIM, nullptr, 1.f, 1, nullptr, pheh[0], phel[0]);
        gemm512_pair<<<dim3(2, 235, 2), 512, GEMM_SMEM2>>>(pr);
    }

    // --- SAGE layers ---
    int curb = 0;
    for (int l = 0; l < NLAYERS; l++) {
        int nxt = curb ^ 1;
        GatherBatch gb;
        gb.sh[0] = phwh[curb]; gb.sl[0] = phwl[curb];
        gb.sh[1] = pheh[curb]; gb.sl[1] = phel[curb];
        gb.sh[2] = pheh[curb]; gb.sl[2] = phel[curb];
        gb.off[0] = off + 0 * (NWIN + 1); gb.csrc[0] = csrc + 0 * (size_t)EDG; gb.ndst[0] = NWIN;
        gb.off[1] = off + 1 * (NWIN + 1); gb.csrc[1] = csrc + 1 * (size_t)EDG; gb.ndst[1] = NWIN;
        gb.off[2] = off + 2 * (NWIN + 1); gb.csrc[2] = csrc + 2 * (size_t)EDG; gb.ndst[2] = NEX;
        gb.oh[0] = pa0h; gb.ol[0] = pa0l;
        gb.oh[1] = pa1h; gb.ol[1] = pa1l;
        gb.oh[2] = pa2h; gb.ol[2] = pa2l;
        gather_all<<<dim3(MP, 3), 128>>>(gb);

        GemmPair pr;
        OpDesc ops3[3] = {
            { pa0h, pa0l, wth + WOFF_WLN(l), wtl + WOFF_WLN(l), HDIM },
            { pa1h, pa1l, wth + WOFF_WLR(l), wtl + WOFF_WLR(l), HDIM },
            { phwh[curb], phwl[curb], wth + WOFF_WSUM(l), wtl + WOFF_WSUM(l), HDIM },
        };
        OpDesc ops2[2] = {
            { pa2h, pa2l, wth + WOFF_WLC(l), wtl + WOFF_WLC(l), HDIM },
            { pheh[curb], phel[curb], wth + WOFF_WRC(l), wtl + WOFF_WRC(l), HDIM },
        };
        fill_args(pr.g[0], ops3, 3, NWIN, HDIM, HDIM, bsum + (size_t)l * HDIM, 0.5f, 1,
                  nullptr, phwh[nxt], phwl[nxt]);
        fill_args(pr.g[1], ops2, 2, NEX, HDIM, HDIM, b_close + (size_t)l * HDIM, 1.f, 1,
                  nullptr, pheh[nxt], phel[nxt]);
        gemm512_pair<<<dim3(2, 235, 2), 512, GEMM_SMEM2>>>(pr);
        curb = nxt;
    }

    // --- score + low-dim projections (paired 128-wide GEMM) ---
    gemv_score<<<(NEX + 7) / 8, 256>>>(pheh[curb], phel[curb], w_pool, score);
    {
        GemmPair pr;
        OpDesc opw = { phwh[curb], phwl[curb], wth + WOFF_LIN, wtl + WOFF_LIN, HDIM };
        OpDesc ope = { pheh[curb], phel[curb], wth + WOFF_LIN, wtl + WOFF_LIN, HDIM };
        fill_args(pr.g[0], &opw, 1, NWIN, NOUT, NOUT, b_lin, 1.f, 0, lin0, nullptr, nullptr);
        fill_args(pr.g[1], &ope, 1, NEX, NOUT, NOUT, nullptr, 1.f, 0, lin1, nullptr, nullptr);
        gemm_mma_pair<<<dim3(1, 235, 2), 256, GEMM_SMEM>>>(pr);
    }

    // --- low-dim CSRA pooling -> out directly ---
    pool_small<<<NWIN, 128>>>(lin1, lin0, score,
                              off + 1 * (NWIN + 1), csrc + 1 * (size_t)EDG, out);
}

// round 10
// speedup vs baseline: 1.6595x; 1.4123x over previous
#include <cuda_runtime.h>
#include <cuda_fp16.h>
#include <float.h>
#include <math.h>
#include <stdint.h>

#define NWIN 30000
#define NEX  30000
#define EDG  480000
#define HDIM 512
#define NLAYERS 4
#define KWIN 1949
#define KEXP 100
#define NOUT 100
#define MP   30080
#define KP_WIN 1984

// ================= small fp32 scratch =================
__device__ float g_score[NEX];
__device__ float g_bsum[NLAYERS*HDIM];
__device__ __align__(256) float g_lin0[NWIN*NOUT];
__device__ __align__(256) float g_lin1[NEX*NOUT];

// ================= CSR scratch =================
__device__ int g_cnt[3*NWIN];
__device__ int g_off[3*(NWIN+1)];
__device__ int g_cur[3*NWIN];
__device__ int g_csrc[3*EDG];

// ================= fp16 weight buffers [N][Kp], hi & lo =================
#define WOFF_STEP   (HDIM*HDIM)
#define WOFF_LAYER  (5*WOFF_STEP)
#define WOFF_WLN(l) ((l)*WOFF_LAYER + 0*WOFF_STEP)
#define WOFF_WLR(l) ((l)*WOFF_LAYER + 1*WOFF_STEP)
#define WOFF_WSUM(l)((l)*WOFF_LAYER + 2*WOFF_STEP)
#define WOFF_WLC(l) ((l)*WOFF_LAYER + 3*WOFF_STEP)
#define WOFF_WRC(l) ((l)*WOFF_LAYER + 4*WOFF_STEP)
#define WOFF_POST   (NLAYERS*WOFF_LAYER)
#define WOFF_WIN    (WOFF_POST + WOFF_STEP)
#define WOFF_EXP    (WOFF_WIN + HDIM*KP_WIN)
#define WOFF_LIN    (WOFF_EXP + HDIM*128)
#define WTOTAL      (WOFF_LIN + 128*HDIM)
__device__ __align__(256) __half g_wth[WTOTAL];
__device__ __align__(256) __half g_wtl[WTOTAL];

// ================= fp16 activation plane buffers (single plane) =================
__device__ __align__(256) __half g_big[(size_t)MP*KP_WIN];
__device__ __align__(256) __half g_pt[(size_t)MP*HDIM];
__device__ __align__(256) __half g_phw0[(size_t)MP*HDIM];
__device__ __align__(256) __half g_phw1[(size_t)MP*HDIM];
__device__ __align__(256) __half g_phe0[(size_t)MP*HDIM];
__device__ __align__(256) __half g_phe1[(size_t)MP*HDIM];
__device__ __align__(256) __half g_pa0[(size_t)MP*HDIM];
__device__ __align__(256) __half g_pa1[(size_t)MP*HDIM];
__device__ __align__(256) __half g_pa2[(size_t)MP*HDIM];

// ================= batched HxH weight conversion (transpose + fp16 hi/lo) ==========
#define NBATCH 21
struct ConvBatch {
    const float* W1[NBATCH];
    const float* W2[NBATCH];
    int dstoff[NBATCH];
};

__global__ void conv_w_batch(const __grid_constant__ ConvBatch cb,
                             __half* __restrict__ ohb, __half* __restrict__ olb)
{
    __shared__ float t[32][33];
    int z = blockIdx.z;
    const float* W = cb.W1[z];
    const float* W2 = cb.W2[z];
    __half* oh = ohb + cb.dstoff[z];
    __half* ol = olb + cb.dstoff[z];
    int k0 = blockIdx.x * 32, n0 = blockIdx.y * 32;
    int tx = threadIdx.x, ty = threadIdx.y;
#pragma unroll
    for (int i = 0; i < 4; i++) {
        int k = k0 + ty + i * 8, n = n0 + tx;
        float v = W[(size_t)k * HDIM + n];
        if (W2) v += W2[(size_t)k * HDIM + n];
        t[ty + i * 8][tx] = v;
    }
    __syncthreads();
#pragma unroll
    for (int i = 0; i < 4; i++) {
        int n = n0 + ty + i * 8, k = k0 + tx;
        float v = t[tx][ty + i * 8];
        __half hb = __float2half_rn(v);
        oh[(size_t)n * HDIM + k] = hb;
        ol[(size_t)n * HDIM + k] = __float2half_rn(v - __half2float(hb));
    }
}

__global__ void conv_w(const float* __restrict__ W, int K, int N, int Kp,
                       __half* __restrict__ oh, __half* __restrict__ ol)
{
    __shared__ float t[32][33];
    int k0 = blockIdx.x * 32, n0 = blockIdx.y * 32;
    int tx = threadIdx.x, ty = threadIdx.y;
#pragma unroll
    for (int i = 0; i < 4; i++) {
        int k = k0 + ty + i * 8, n = n0 + tx;
        float v = 0.f;
        if (k < K && n < N) v = W[(size_t)k * N + n];
        t[ty + i * 8][tx] = v;
    }
    __syncthreads();
#pragma unroll
    for (int i = 0; i < 4; i++) {
        int n = n0 + ty + i * 8, k = k0 + tx;
        float v = t[tx][ty + i * 8];
        __half hb = __float2half_rn(v);
        oh[(size_t)n * Kp + k] = hb;
        ol[(size_t)n * Kp + k] = __float2half_rn(v - __half2float(hb));
    }
}

// activations -> single fp16 plane
__global__ void conv_a(const float* __restrict__ A, int M, int K, int Kp, long long total,
                       __half* __restrict__ o)
{
    long long i = (long long)blockIdx.x * blockDim.x + threadIdx.x;
    if (i >= total) return;
    int m = (int)(i / Kp);
    int k = (int)(i % Kp);
    float v = 0.f;
    if (m < M && k < K) v = A[(size_t)m * K + k];
    o[i] = __float2half_rn(v);
}

__global__ void bias_sum_all(const float* a, const float* b, float* o)
{
    int i = blockIdx.x * blockDim.x + threadIdx.x;
    if (i < NLAYERS * HDIM) o[i] = a[i] + b[i];
}

__global__ void zero_int(int* p, int n)
{
    int i = blockIdx.x * blockDim.x + threadIdx.x;
    if (i < n) p[i] = 0;
}

// ================= CSR build =================
struct EdgePtrs { const int* es[3]; const int* ed[3]; };

__global__ void hist_all(const __grid_constant__ EdgePtrs ep, int* __restrict__ cnt)
{
    int r = blockIdx.y;
    int e = blockIdx.x * blockDim.x + threadIdx.x;
    if (e < EDG) atomicAdd(&cnt[r * NWIN + ep.ed[r][e]], 1);
}

__global__ void scan_all(const int* __restrict__ cnt, int* __restrict__ off,
                         int* __restrict__ cur)
{
    __shared__ int s[1024];
    int r = blockIdx.x;
    const int* c = cnt + r * NWIN;
    int* of = off + r * (NWIN + 1);
    int* cu = cur + r * NWIN;
    int t = threadIdx.x;
    int chunk = (NWIN + 1023) >> 10;
    int b = t * chunk, e = min(b + chunk, NWIN);
    int sum = 0;
    for (int i = b; i < e; i++) sum += c[i];
    s[t] = sum;
    __syncthreads();
    for (int d = 1; d < 1024; d <<= 1) {
        int v = (t >= d) ? s[t - d] : 0;
        __syncthreads();
        s[t] += v;
        __syncthreads();
    }
    int run = (t == 0) ? 0 : s[t - 1];
    for (int i = b; i < e; i++) {
        of[i] = run; cu[i] = run; run += c[i];
    }
    if (t == 0) of[NWIN] = s[1023];
}

__global__ void fill_all(const __grid_constant__ EdgePtrs ep, int* __restrict__ cur,
                         int* __restrict__ csrc)
{
    int r = blockIdx.y;
    int e = blockIdx.x * blockDim.x + threadIdx.x;
    if (e < EDG) {
        int p = atomicAdd(&cur[r * NWIN + ep.ed[r][e]], 1);
        csrc[(size_t)r * EDG + p] = ep.es[r][e];
    }
}

// ================= fused 3-relation gather-mean (fp16 single plane) =================
struct GatherBatch {
    const __half *src[3];
    const int *off[3], *csrc[3];
    int ndst[3];
    __half *o[3];
};

__device__ __forceinline__ void acc8h(float* acc, uint4 q)
{
    const __half2* h2 = (const __half2*)&q;
#pragma unroll
    for (int j = 0; j < 4; j++) {
        float2 f = __half22float2(h2[j]);
        acc[j * 2 + 0] += f.x;
        acc[j * 2 + 1] += f.y;
    }
}

// block = 128 threads = 2 groups of 64; each group handles one dst row (16B/thread)
__global__ void gather_all(const __grid_constant__ GatherBatch gb)
{
    int r = blockIdx.y;
    int t = threadIdx.x;
    int d = blockIdx.x * 2 + (t >> 6);
    int c = (t & 63) * 8;
    const __half* src = gb.src[r];

    float acc[8];
#pragma unroll
    for (int j = 0; j < 8; j++) acc[j] = 0.f;
    int deg = 0;
    if (d < gb.ndst[r]) {
        const int* off = gb.off[r];
        const int* cs = gb.csrc[r];
        int s0 = off[d], s1 = off[d + 1];
        deg = s1 - s0;
        int e = s0;
        for (; e + 4 <= s1; e += 4) {
            int i0 = cs[e], i1 = cs[e + 1], i2 = cs[e + 2], i3 = cs[e + 3];
            uint4 q0 = *(const uint4*)(src + (size_t)i0 * HDIM + c);
            uint4 q1 = *(const uint4*)(src + (size_t)i1 * HDIM + c);
            uint4 q2 = *(const uint4*)(src + (size_t)i2 * HDIM + c);
            uint4 q3 = *(const uint4*)(src + (size_t)i3 * HDIM + c);
            acc8h(acc, q0); acc8h(acc, q1); acc8h(acc, q2); acc8h(acc, q3);
        }
        for (; e < s1; e++) {
            uint4 q = *(const uint4*)(src + (size_t)cs[e] * HDIM + c);
            acc8h(acc, q);
        }
    }
    float inv = 1.f / (float)max(deg, 1);
    __half2 o2[4];
#pragma unroll
    for (int j = 0; j < 4; j++)
        o2[j] = __floats2half2_rn(acc[j * 2] * inv, acc[j * 2 + 1] * inv);
    *(uint4*)(gb.o[r] + (size_t)d * HDIM + c) = *(uint4*)o2;
}

// ================= low-dim CSRA pooling =================
__global__ void pool_small(const float* __restrict__ helin,
                           const float* __restrict__ hwlin,
                           const float* __restrict__ score,
                           const int* __restrict__ off, const int* __restrict__ csrc,
                           float* __restrict__ out)
{
    __shared__ float red[128];
    __shared__ float wts[128];
    __shared__ int   idx[128];
    int d = blockIdx.x;
    int t = threadIdx.x;
    if (d >= NWIN) return;
    int s0 = off[d], s1 = off[d + 1];

    float m = -FLT_MAX;
    for (int e = s0 + t; e < s1; e += 128) m = fmaxf(m, score[csrc[e]]);
    red[t] = m; __syncthreads();
    for (int w = 64; w; w >>= 1) {
        if (t < w) red[t] = fmaxf(red[t], red[t + w]);
        __syncthreads();
    }
    float smax = red[0];
    __syncthreads();
    float z = 0.f;
    for (int e = s0 + t; e < s1; e += 128) z += expf(score[csrc[e]] - smax);
    red[t] = z; __syncthreads();
    for (int w = 64; w; w >>= 1) {
        if (t < w) red[t] += red[t + w];
        __syncthreads();
    }
    float invz = 1.f / fmaxf(red[0], 1e-12f);
    __syncthreads();

    float acc = 0.f;
    for (int base = s0; base < s1; base += 128) {
        int e = base + t;
        if (e < s1) {
            int si = csrc[e];
            idx[t] = si;
            wts[t] = expf(score[si] - smax) * invz;
        }
        __syncthreads();
        int cnt = min(128, s1 - base);
        if (t < NOUT) {
            for (int j = 0; j < cnt; j++)
                acc += wts[j] * helin[(size_t)idx[j] * NOUT + t];
        }
        __syncthreads();
    }
    if (t < NOUT)
        out[(size_t)d * NOUT + t] = hwlin[(size_t)d * NOUT + t] + 0.5f * acc;
}

__global__ void gemv_score(const __half* __restrict__ he,
                           const float* __restrict__ w, float* __restrict__ sc)
{
    int row = blockIdx.x * 8 + (threadIdx.x >> 5);
    if (row >= NEX) return;
    int lane = threadIdx.x & 31;
    float s = 0.f;
#pragma unroll
    for (int k = lane * 4; k < HDIM; k += 128) {
        __half2 a = *(const __half2*)(he + (size_t)row * HDIM + k);
        __half2 b = *(const __half2*)(he + (size_t)row * HDIM + k + 2);
        float2 fa = __half22float2(a), fb = __half22float2(b);
        s += fa.x * w[k] + fa.y * w[k + 1] + fb.x * w[k + 2] + fb.y * w[k + 3];
    }
#pragma unroll
    for (int o = 16; o; o >>= 1) s += __shfl_down_sync(0xFFFFFFFFu, s, o);
    if (lane == 0) sc[row] = s;
}

// ================= GEMM common (fp16 2-pass: A @ Bh + A @ Bl) =================
struct GemmArgs {
    const __half *A[3], *Bh[3], *Bl[3];
    int Kp[3];
    int nops, totChunks;
    int M, Nstore, ldd;
    const float* bias;
    float ps;
    int act;
    float* D;
    __half* Dh;
};
struct GemmPair { GemmArgs g[2]; };

__device__ __forceinline__ uint32_t smem_u32(const void* p) {
    uint32_t a;
    asm("{ .reg .u64 t; cvta.to.shared.u64 t, %1; cvt.u32.u64 %0, t; }" : "=r"(a) : "l"(p));
    return a;
}
__device__ __forceinline__ void cp16(uint32_t dst, const void* src) {
    asm volatile("cp.async.cg.shared.global [%0], [%1], 16;" :: "r"(dst), "l"(src));
}
__device__ __forceinline__ void cp_commit() { asm volatile("cp.async.commit_group;"); }
__device__ __forceinline__ void cp_wait0() { asm volatile("cp.async.wait_group 0;"); }
__device__ __forceinline__ void cp_wait1() { asm volatile("cp.async.wait_group 1;"); }

__device__ __forceinline__ void ldm_x4(uint32_t* r, uint32_t addr) {
    asm volatile("ldmatrix.sync.aligned.m8n8.x4.shared.b16 {%0,%1,%2,%3}, [%4];"
                 : "=r"(r[0]), "=r"(r[1]), "=r"(r[2]), "=r"(r[3]) : "r"(addr));
}
__device__ __forceinline__ void mma16816(float* c, const uint32_t* a, const uint32_t* b) {
    asm volatile("mma.sync.aligned.m16n8k16.row.col.f32.f16.f16.f32 "
                 "{%0,%1,%2,%3},{%4,%5,%6,%7},{%8,%9},{%0,%1,%2,%3};"
                 : "+f"(c[0]), "+f"(c[1]), "+f"(c[2]), "+f"(c[3])
                 : "r"(a[0]), "r"(a[1]), "r"(a[2]), "r"(a[3]), "r"(b[0]), "r"(b[1]));
}

__device__ __forceinline__ void map_oc(const GemmArgs& g, int t, int& o, int& c) {
    o = 0;
    int rem = t;
    while (o < g.nops - 1 && rem >= (g.Kp[o] >> 6)) { rem -= (g.Kp[o] >> 6); o++; }
    c = rem;
}

__device__ __forceinline__ void epi_frag(const GemmArgs& g, const float* a4,
                                         int row0, int col)
{
    if (col >= g.Nstore) return;
    float b0 = 0.f, b1 = 0.f;
    if (g.bias) {
        b0 = g.bias[col];
        if (col + 1 < g.Nstore) b1 = g.bias[col + 1];
    }
#pragma unroll
    for (int rr = 0; rr < 2; rr++) {
        int r = row0 + rr * 8;
        if (r >= g.M) continue;
        float v0 = (a4[rr * 2 + 0] + b0) * g.ps;
        float v1 = (a4[rr * 2 + 1] + b1) * g.ps;
        if (g.act) {
            v0 = v0 > 0.f ? v0 : 0.2f * v0;
            v1 = v1 > 0.f ? v1 : 0.2f * v1;
        }
        if (g.D) {
            float* dp = g.D + (size_t)r * g.ldd + col;
            if (col + 1 < g.Nstore) *(float2*)dp = make_float2(v0, v1);
            else *dp = v0;
        }
        if (g.Dh) {
            *(__half2*)(g.Dh + (size_t)r * HDIM + col) = __floats2half2_rn(v0, v1);
        }
    }
}

// ================= 512-thread 128x256 GEMM =================
#define STAGE2      81920      // A 16K, Bh 32K, Bl 32K
#define GEMM_SMEM2  (2 * STAGE2)

__device__ __forceinline__ void load_stage512(const GemmArgs& g, int t, uint32_t sb,
                                              int tid, int m0, int n0)
{
    int o, c;
    map_oc(g, t, o, c);
    const int Kp = g.Kp[o];
    const int k0 = c << 6;
    {
        const __half* a_ = g.A[o] + (size_t)m0 * Kp + k0;
#pragma unroll
        for (int it = 0; it < 2; it++) {
            int idx = it * 512 + tid;
            int r = idx >> 3;
            int j = idx & 7;
            uint32_t sw = r * 128 + ((j ^ (r & 7)) << 4);
            cp16(sb + sw, a_ + (size_t)r * Kp + j * 8);
        }
    }
    {
        const __half* bh_ = g.Bh[o] + (size_t)n0 * Kp + k0;
        const __half* bl_ = g.Bl[o] + (size_t)n0 * Kp + k0;
#pragma unroll
        for (int it = 0; it < 4; it++) {
            int idx = it * 512 + tid;
            int r = idx >> 3;
            int j = idx & 7;
            uint32_t sw = r * 128 + ((j ^ (r & 7)) << 4);
            cp16(sb + 16384 + sw, bh_ + (size_t)r * Kp + j * 8);
            cp16(sb + 49152 + sw, bl_ + (size_t)r * Kp + j * 8);
        }
    }
    cp_commit();
}

__device__ __forceinline__ void gemm_body512(const GemmArgs& g, char* smem)
{
    const uint32_t sbase = smem_u32(smem);
    const int tid = threadIdx.x;
    const int lane = tid & 31;
    const int warp = tid >> 5;
    const int wm = warp >> 2;
    const int wn = warp & 3;
    const int m0 = blockIdx.y * 128;
    const int n0 = blockIdx.x * 256;

    float acc[2][8][4];
#pragma unroll
    for (int i = 0; i < 2; i++)
#pragma unroll
        for (int j = 0; j < 8; j++)
#pragma unroll
            for (int q = 0; q < 4; q++) acc[i][j][q] = 0.f;

    const int sx = lane & 7;
    const int arow = (lane & 7) + ((lane >> 3) & 1) * 8;
    const int khia = (lane >> 4) & 1;
    const int brow = (lane & 7) + ((lane >> 4) & 1) * 8;
    const int khib = (lane >> 3) & 1;

    const int T = g.totChunks;
    load_stage512(g, 0, sbase, tid, m0, n0);

    for (int t = 0; t < T; t++) {
        if (t + 1 < T) {
            load_stage512(g, t + 1, sbase + ((t + 1) & 1) * STAGE2, tid, m0, n0);
            cp_wait1();
        } else {
            cp_wait0();
        }
        __syncthreads();

        const uint32_t Ab = sbase + (t & 1) * STAGE2;
        const uint32_t Bh = Ab + 16384;
        const uint32_t Bl = Ab + 49152;

#pragma unroll
        for (int ks = 0; ks < 4; ks++) {
            const uint32_t colA = (uint32_t)(((ks * 2 + khia) ^ sx) << 4);
            const uint32_t colB = (uint32_t)(((ks * 2 + khib) ^ sx) << 4);
            uint32_t ah[2][4];
#pragma unroll
            for (int mt = 0; mt < 2; mt++) {
                int row = wm * 32 + mt * 16 + arow;
                ldm_x4(ah[mt], Ab + row * 128 + colA);
            }
#pragma unroll
            for (int half = 0; half < 2; half++) {
                uint32_t bh[2][4], bl[2][4];
#pragma unroll
                for (int np = 0; np < 2; np++) {
                    int row = wn * 64 + half * 32 + np * 16 + brow;
                    ldm_x4(bh[np], Bh + row * 128 + colB);
                    ldm_x4(bl[np], Bl + row * 128 + colB);
                }
#pragma unroll
                for (int mt = 0; mt < 2; mt++) {
#pragma unroll
                    for (int nt = 0; nt < 4; nt++) {
                        const uint32_t* bhf = &bh[nt >> 1][(nt & 1) * 2];
                        const uint32_t* blf = &bl[nt >> 1][(nt & 1) * 2];
                        float* a_ = acc[mt][half * 4 + nt];
                        mma16816(a_, ah[mt], bhf);
                        mma16816(a_, ah[mt], blf);
                    }
                }
            }
        }
        __syncthreads();
    }

#pragma unroll
    for (int mt = 0; mt < 2; mt++) {
        int row0 = m0 + wm * 32 + mt * 16 + (lane >> 2);
#pragma unroll
        for (int nt = 0; nt < 8; nt++) {
            int col = n0 + wn * 64 + nt * 8 + (lane & 3) * 2;
            epi_frag(g, acc[mt][nt], row0, col);
        }
    }
}

__global__ __launch_bounds__(512, 1) void gemm512_pair(const __grid_constant__ GemmPair p)
{
    extern __shared__ __align__(128) char smem[];
    gemm_body512(p.g[blockIdx.z], smem);
}

// ================= 256-thread 128x128 GEMM =================
#define STAGE_BYTES 49152      // A 16K, Bh 16K, Bl 16K
#define GEMM_SMEM   (2 * STAGE_BYTES)

__device__ __forceinline__ void load_stage(const GemmArgs& g, int t, uint32_t sb,
                                           int tid, int m0, int n0)
{
    int o, c;
    map_oc(g, t, o, c);
    const int Kp = g.Kp[o];
    const int k0 = c << 6;
    {
        const __half* a_ = g.A[o] + (size_t)m0 * Kp + k0;
#pragma unroll
        for (int it = 0; it < 4; it++) {
            int idx = it * 256 + tid;
            int r = idx >> 3;
            int j = idx & 7;
            uint32_t sw = r * 128 + ((j ^ (r & 7)) << 4);
            cp16(sb + sw, a_ + (size_t)r * Kp + j * 8);
        }
    }
    {
        const __half* bh_ = g.Bh[o] + (size_t)n0 * Kp + k0;
        const __half* bl_ = g.Bl[o] + (size_t)n0 * Kp + k0;
#pragma unroll
        for (int it = 0; it < 4; it++) {
            int idx = it * 256 + tid;
            int r = idx >> 3;
            int j = idx & 7;
            uint32_t sw = r * 128 + ((j ^ (r & 7)) << 4);
            cp16(sb + 16384 + sw, bh_ + (size_t)r * Kp + j * 8);
            cp16(sb + 32768 + sw, bl_ + (size_t)r * Kp + j * 8);
        }
    }
    cp_commit();
}

__device__ __forceinline__ void gemm_body128(const GemmArgs& g, char* smem)
{
    const uint32_t sbase = smem_u32(smem);
    const int tid = threadIdx.x;
    const int lane = tid & 31;
    const int warp = tid >> 5;
    const int wm = warp >> 2;
    const int wn = warp & 3;
    const int m0 = blockIdx.y * 128;
    const int n0 = blockIdx.x * 128;

    float acc[4][4][4];
#pragma unroll
    for (int i = 0; i < 4; i++)
#pragma unroll
        for (int j = 0; j < 4; j++)
#pragma unroll
            for (int q = 0; q < 4; q++) acc[i][j][q] = 0.f;

    const int sx = lane & 7;
    const int arow = (lane & 7) + ((lane >> 3) & 1) * 8;
    const int khia = (lane >> 4) & 1;
    const int brow = (lane & 7) + ((lane >> 4) & 1) * 8;
    const int khib = (lane >> 3) & 1;

    const int T = g.totChunks;
    load_stage(g, 0, sbase, tid, m0, n0);

    for (int t = 0; t < T; t++) {
        if (t + 1 < T) {
            load_stage(g, t + 1, sbase + ((t + 1) & 1) * STAGE_BYTES, tid, m0, n0);
            cp_wait1();
        } else {
            cp_wait0();
        }
        __syncthreads();

        const uint32_t Ab = sbase + (t & 1) * STAGE_BYTES;
        const uint32_t Bh = Ab + 16384;
        const uint32_t Bl = Ab + 32768;

#pragma unroll
        for (int ks = 0; ks < 4; ks++) {
            uint32_t ah[4][4], bh[2][4], bl[2][4];
            const uint32_t colA = (uint32_t)(((ks * 2 + khia) ^ sx) << 4);
            const uint32_t colB = (uint32_t)(((ks * 2 + khib) ^ sx) << 4);
#pragma unroll
            for (int mt = 0; mt < 4; mt++) {
                int row = wm * 64 + mt * 16 + arow;
                ldm_x4(ah[mt], Ab + row * 128 + colA);
            }
#pragma unroll
            for (int np = 0; np < 2; np++) {
                int row = wn * 32 + np * 16 + brow;
                ldm_x4(bh[np], Bh + row * 128 + colB);
                ldm_x4(bl[np], Bl + row * 128 + colB);
            }
#pragma unroll
            for (int mt = 0; mt < 4; mt++) {
#pragma unroll
                for (int nt = 0; nt < 4; nt++) {
                    const uint32_t* bhf = &bh[nt >> 1][(nt & 1) * 2];
                    const uint32_t* blf = &bl[nt >> 1][(nt & 1) * 2];
                    mma16816(acc[mt][nt], ah[mt], bhf);
                    mma16816(acc[mt][nt], ah[mt], blf);
                }
            }
        }
        __syncthreads();
    }

#pragma unroll
    for (int mt = 0; mt < 4; mt++) {
        int row0 = m0 + wm * 64 + mt * 16 + (lane >> 2);
#pragma unroll
        for (int nt = 0; nt < 4; nt++) {
            int col = n0 + wn * 32 + nt * 8 + (lane & 3) * 2;
            epi_frag(g, acc[mt][nt], row0, col);
        }
    }
}

__global__ __launch_bounds__(256, 1) void gemm_mma_pair(const __grid_constant__ GemmPair p)
{
    extern __shared__ __align__(128) char smem[];
    gemm_body128(p.g[blockIdx.z], smem);
}

// ================= host orchestration =================
struct OpDesc {
    const __half *A, *Bh, *Bl;
    int Kp;
};

static void fill_args(GemmArgs& g, const OpDesc* ops, int nops, int M, int Nstore,
                      int ldd, const float* bias, float ps, int act,
                      float* D, __half* Dh)
{
    int T = 0;
    for (int o = 0; o < nops; o++) {
        g.A[o] = ops[o].A; g.Bh[o] = ops[o].Bh; g.Bl[o] = ops[o].Bl;
        g.Kp[o] = ops[o].Kp;
        T += ops[o].Kp / 64;
    }
    g.nops = nops; g.totChunks = T;
    g.M = M; g.Nstore = Nstore; g.ldd = ldd;
    g.bias = bias; g.ps = ps; g.act = act;
    g.D = D; g.Dh = Dh;
}

extern "C" void kernel_launch(void* const* d_in, const int* in_sizes, int n_in,
                              void* d_out, int out_size)
{
    const float* x_window  = (const float*)d_in[0];
    const float* x_example = (const float*)d_in[1];
    const int*   e_near    = (const int*)d_in[2];
    const int*   e_close   = (const int*)d_in[3];
    const int*   e_refer   = (const int*)d_in[4];
    const float* W_win     = (const float*)d_in[5];
    const float* W_exp     = (const float*)d_in[6];
    const float* W_post    = (const float*)d_in[7];
    const float* Wl_near   = (const float*)d_in[9];
    const float* Wr_near   = (const float*)d_in[10];
    const float* b_near    = (const float*)d_in[11];
    const float* Wl_close  = (const float*)d_in[12];
    const float* Wr_close  = (const float*)d_in[13];
    const float* b_close   = (const float*)d_in[14];
    const float* Wl_refer  = (const float*)d_in[15];
    const float* Wr_refer  = (const float*)d_in[16];
    const float* b_refer   = (const float*)d_in[17];
    const float* w_pool    = (const float*)d_in[18];
    const float* W_lin     = (const float*)d_in[19];
    const float* b_lin     = (const float*)d_in[20];
    float* out = (float*)d_out;

    cudaFuncSetAttribute(gemm_mma_pair, cudaFuncAttributeMaxDynamicSharedMemorySize, GEMM_SMEM);
    cudaFuncSetAttribute(gemm512_pair, cudaFuncAttributeMaxDynamicSharedMemorySize, GEMM_SMEM2);

    float *score, *bsum, *lin0, *lin1;
    int *cnt, *off, *cur, *csrc;
    __half *wth, *wtl, *big, *pt;
    __half *phw[2], *phe[2], *pa0, *pa1, *pa2;
    cudaGetSymbolAddress((void**)&score, g_score);
    cudaGetSymbolAddress((void**)&bsum, g_bsum);
    cudaGetSymbolAddress((void**)&lin0, g_lin0);
    cudaGetSymbolAddress((void**)&lin1, g_lin1);
    cudaGetSymbolAddress((void**)&cnt, g_cnt);
    cudaGetSymbolAddress((void**)&off, g_off);
    cudaGetSymbolAddress((void**)&cur, g_cur);
    cudaGetSymbolAddress((void**)&csrc, g_csrc);
    cudaGetSymbolAddress((void**)&wth, g_wth);
    cudaGetSymbolAddress((void**)&wtl, g_wtl);
    cudaGetSymbolAddress((void**)&big, g_big);
    cudaGetSymbolAddress((void**)&pt, g_pt);
    cudaGetSymbolAddress((void**)&phw[0], g_phw0);
    cudaGetSymbolAddress((void**)&phw[1], g_phw1);
    cudaGetSymbolAddress((void**)&phe[0], g_phe0);
    cudaGetSymbolAddress((void**)&phe[1], g_phe1);
    cudaGetSymbolAddress((void**)&pa0, g_pa0);
    cudaGetSymbolAddress((void**)&pa1, g_pa1);
    cudaGetSymbolAddress((void**)&pa2, g_pa2);

    const unsigned edge_blocks = (EDG + 255) / 256;

    // --- batched weight conversion ---
    {
        ConvBatch cb;
        for (int l = 0; l < NLAYERS; l++) {
            size_t s = (size_t)l * HDIM * HDIM;
            cb.W1[l * 5 + 0] = Wl_near + s;  cb.W2[l * 5 + 0] = nullptr;      cb.dstoff[l * 5 + 0] = WOFF_WLN(l);
            cb.W1[l * 5 + 1] = Wl_refer + s; cb.W2[l * 5 + 1] = nullptr;      cb.dstoff[l * 5 + 1] = WOFF_WLR(l);
            cb.W1[l * 5 + 2] = Wr_near + s;  cb.W2[l * 5 + 2] = Wr_refer + s; cb.dstoff[l * 5 + 2] = WOFF_WSUM(l);
            cb.W1[l * 5 + 3] = Wl_close + s; cb.W2[l * 5 + 3] = nullptr;      cb.dstoff[l * 5 + 3] = WOFF_WLC(l);
            cb.W1[l * 5 + 4] = Wr_close + s; cb.W2[l * 5 + 4] = nullptr;      cb.dstoff[l * 5 + 4] = WOFF_WRC(l);
        }
        cb.W1[20] = W_post; cb.W2[20] = nullptr; cb.dstoff[20] = WOFF_POST;
        dim3 blk(32, 8);
        dim3 gB(HDIM / 32, HDIM / 32, NBATCH);
        conv_w_batch<<<gB, blk>>>(cb, wth, wtl);

        dim3 gWIN(KP_WIN / 32, HDIM / 32);
        conv_w<<<gWIN, blk>>>(W_win, KWIN, HDIM, KP_WIN, wth + WOFF_WIN, wtl + WOFF_WIN);
        dim3 gEXP(128 / 32, HDIM / 32);
        conv_w<<<gEXP, blk>>>(W_exp, KEXP, HDIM, 128, wth + WOFF_EXP, wtl + WOFF_EXP);
        dim3 gLIN(HDIM / 32, 128 / 32);
        conv_w<<<gLIN, blk>>>(W_lin, HDIM, NOUT, HDIM, wth + WOFF_LIN, wtl + WOFF_LIN);
        bias_sum_all<<<(NLAYERS * HDIM + 255) / 256, 256>>>(b_near, b_refer, bsum);
    }

    // --- CSR build ---
    {
        EdgePtrs ep;
        ep.es[0] = e_near;  ep.ed[0] = e_near + EDG;
        ep.es[1] = e_refer; ep.ed[1] = e_refer + EDG;
        ep.es[2] = e_close; ep.ed[2] = e_close + EDG;
        zero_int<<<(3 * NWIN + 255) / 256, 256>>>(cnt, 3 * NWIN);
        dim3 ge(edge_blocks, 3);
        hist_all<<<ge, 256>>>(ep, cnt);
        scan_all<<<3, 1024>>>(cnt, off, cur);
        fill_all<<<ge, 256>>>(ep, cur, csrc);
    }

    // --- input projections (paired, 512-thread GEMM) ---
    {
        long long tot = (long long)MP * 128;
        conv_a<<<(unsigned)((tot + 255) / 256), 256>>>(x_example, NEX, KEXP, 128, tot, pa0);
        tot = (long long)MP * KP_WIN;
        conv_a<<<(unsigned)((tot + 255) / 256), 256>>>(x_window, NWIN, KWIN, KP_WIN, tot, big);

        GemmPair pr;
        OpDesc opw = { big, wth + WOFF_WIN, wtl + WOFF_WIN, KP_WIN };
        OpDesc ope = { pa0, wth + WOFF_EXP, wtl + WOFF_EXP, 128 };
        fill_args(pr.g[0], &opw, 1, NWIN, HDIM, HDIM, nullptr, 1.f, 1, nullptr, pt);
        fill_args(pr.g[1], &ope, 1, NEX, HDIM, HDIM, nullptr, 1.f, 1, nullptr, pa1);
        gemm512_pair<<<dim3(2, 235, 2), 512, GEMM_SMEM2>>>(pr);

        OpDesc opw2 = { pt, wth + WOFF_POST, wtl + WOFF_POST, HDIM };
        OpDesc ope2 = { pa1, wth + WOFF_POST, wtl + WOFF_POST, HDIM };
        fill_args(pr.g[0], &opw2, 1, NWIN, HDIM, HDIM, nullptr, 1.f, 1, nullptr, phw[0]);
        fill_args(pr.g[1], &ope2, 1, NEX, HDIM, HDIM, nullptr, 1.f, 1, nullptr, phe[0]);
        gemm512_pair<<<dim3(2, 235, 2), 512, GEMM_SMEM2>>>(pr);
    }

    // --- SAGE layers ---
    int curb = 0;
    for (int l = 0; l < NLAYERS; l++) {
        int nxt = curb ^ 1;
        GatherBatch gb;
        gb.src[0] = phw[curb];
        gb.src[1] = phe[curb];
        gb.src[2] = phe[curb];
        gb.off[0] = off + 0 * (NWIN + 1); gb.csrc[0] = csrc + 0 * (size_t)EDG; gb.ndst[0] = NWIN;
        gb.off[1] = off + 1 * (NWIN + 1); gb.csrc[1] = csrc + 1 * (size_t)EDG; gb.ndst[1] = NWIN;
        gb.off[2] = off + 2 * (NWIN + 1); gb.csrc[2] = csrc + 2 * (size_t)EDG; gb.ndst[2] = NEX;
        gb.o[0] = pa0; gb.o[1] = pa1; gb.o[2] = pa2;
        gather_all<<<dim3(MP / 2, 3), 128>>>(gb);

        GemmPair pr;
        OpDesc ops3[3] = {
            { pa0, wth + WOFF_WLN(l), wtl + WOFF_WLN(l), HDIM },
            { pa1, wth + WOFF_WLR(l), wtl + WOFF_WLR(l), HDIM },
            { phw[curb], wth + WOFF_WSUM(l), wtl + WOFF_WSUM(l), HDIM },
        };
        OpDesc ops2[2] = {
            { pa2, wth + WOFF_WLC(l), wtl + WOFF_WLC(l), HDIM },
            { phe[curb], wth + WOFF_WRC(l), wtl + WOFF_WRC(l), HDIM },
        };
        fill_args(pr.g[0], ops3, 3, NWIN, HDIM, HDIM, bsum + (size_t)l * HDIM, 0.5f, 1,
                  nullptr, phw[nxt]);
        fill_args(pr.g[1], ops2, 2, NEX, HDIM, HDIM, b_close + (size_t)l * HDIM, 1.f, 1,
                  nullptr, phe[nxt]);
        gemm512_pair<<<dim3(2, 235, 2), 512, GEMM_SMEM2>>>(pr);
        curb = nxt;
    }

    // --- score + low-dim projections (paired 128-wide GEMM) ---
    gemv_score<<<(NEX + 7) / 8, 256>>>(phe[curb], w_pool, score);
    {
        GemmPair pr;
        OpDesc opw = { phw[curb], wth + WOFF_LIN, wtl + WOFF_LIN, HDIM };
        OpDesc ope = { phe[curb], wth + WOFF_LIN, wtl + WOFF_LIN, HDIM };
        fill_args(pr.g[0], &opw, 1, NWIN, NOUT, NOUT, b_lin, 1.f, 0, lin0, nullptr);
        fill_args(pr.g[1], &ope, 1, NEX, NOUT, NOUT, nullptr, 1.f, 0, lin1, nullptr);
        gemm_mma_pair<<<dim3(1, 235, 2), 256, GEMM_SMEM>>>(pr);
    }

    // --- low-dim CSRA pooling -> out directly ---
    pool_small<<<NWIN, 128>>>(lin1, lin0, score,
                              off + 1 * (NWIN + 1), csrc + 1 * (size_t)EDG, out);
}

// round 11
// speedup vs baseline: 2.3636x; 1.4242x over previous
#include <cuda_runtime.h>
#include <cuda_fp16.h>
#include <float.h>
#include <math.h>
#include <stdint.h>

#define NWIN 30000
#define NEX  30000
#define EDG  480000
#define HDIM 512
#define NLAYERS 4
#define KWIN 1949
#define KEXP 100
#define NOUT 100
#define MP   30080
#define KP_WIN 1984

// ================= small fp32 scratch =================
__device__ float g_score[NEX];
__device__ float g_bsum[NLAYERS*HDIM];
__device__ __align__(256) float g_lin0[NWIN*NOUT];
__device__ __align__(256) float g_lin1[NEX*NOUT];

// ================= CSR scratch =================
__device__ int g_cnt[3*NWIN];
__device__ int g_off[3*(NWIN+1)];
__device__ int g_cur[3*NWIN];
__device__ int g_csrc[3*EDG];

// ================= fp16 weight buffers [N][Kp] (single plane) =================
#define WOFF_STEP   (HDIM*HDIM)
#define WOFF_LAYER  (5*WOFF_STEP)
#define WOFF_WLN(l) ((l)*WOFF_LAYER + 0*WOFF_STEP)
#define WOFF_WLR(l) ((l)*WOFF_LAYER + 1*WOFF_STEP)
#define WOFF_WSUM(l)((l)*WOFF_LAYER + 2*WOFF_STEP)
#define WOFF_WLC(l) ((l)*WOFF_LAYER + 3*WOFF_STEP)
#define WOFF_WRC(l) ((l)*WOFF_LAYER + 4*WOFF_STEP)
#define WOFF_POST   (NLAYERS*WOFF_LAYER)
#define WOFF_WIN    (WOFF_POST + WOFF_STEP)
#define WOFF_EXP    (WOFF_WIN + HDIM*KP_WIN)
#define WOFF_LIN    (WOFF_EXP + HDIM*128)
#define WTOTAL      (WOFF_LIN + 128*HDIM)
__device__ __align__(256) __half g_wt[WTOTAL];

// ================= fp16 activation plane buffers =================
__device__ __align__(256) __half g_big[(size_t)MP*KP_WIN];
__device__ __align__(256) __half g_pt[(size_t)MP*HDIM];
__device__ __align__(256) __half g_phw0[(size_t)MP*HDIM];
__device__ __align__(256) __half g_phw1[(size_t)MP*HDIM];
__device__ __align__(256) __half g_phe0[(size_t)MP*HDIM];
__device__ __align__(256) __half g_phe1[(size_t)MP*HDIM];
__device__ __align__(256) __half g_pa0[(size_t)MP*HDIM];
__device__ __align__(256) __half g_pa1[(size_t)MP*HDIM];
__device__ __align__(256) __half g_pa2[(size_t)MP*HDIM];

// ================= batched HxH weight conversion (transpose, fp16) ==========
#define NBATCH 21
struct ConvBatch {
    const float* W1[NBATCH];
    const float* W2[NBATCH];
    int dstoff[NBATCH];
};

__global__ void conv_w_batch(const __grid_constant__ ConvBatch cb,
                             __half* __restrict__ ob)
{
    __shared__ float t[32][33];
    int z = blockIdx.z;
    const float* W = cb.W1[z];
    const float* W2 = cb.W2[z];
    __half* o = ob + cb.dstoff[z];
    int k0 = blockIdx.x * 32, n0 = blockIdx.y * 32;
    int tx = threadIdx.x, ty = threadIdx.y;
#pragma unroll
    for (int i = 0; i < 4; i++) {
        int k = k0 + ty + i * 8, n = n0 + tx;
        float v = W[(size_t)k * HDIM + n];
        if (W2) v += W2[(size_t)k * HDIM + n];
        t[ty + i * 8][tx] = v;
    }
    __syncthreads();
#pragma unroll
    for (int i = 0; i < 4; i++) {
        int n = n0 + ty + i * 8, k = k0 + tx;
        o[(size_t)n * HDIM + k] = __float2half_rn(t[tx][ty + i * 8]);
    }
}

__global__ void conv_w(const float* __restrict__ W, int K, int N, int Kp,
                       __half* __restrict__ o)
{
    __shared__ float t[32][33];
    int k0 = blockIdx.x * 32, n0 = blockIdx.y * 32;
    int tx = threadIdx.x, ty = threadIdx.y;
#pragma unroll
    for (int i = 0; i < 4; i++) {
        int k = k0 + ty + i * 8, n = n0 + tx;
        float v = 0.f;
        if (k < K && n < N) v = W[(size_t)k * N + n];
        t[ty + i * 8][tx] = v;
    }
    __syncthreads();
#pragma unroll
    for (int i = 0; i < 4; i++) {
        int n = n0 + ty + i * 8, k = k0 + tx;
        o[(size_t)n * Kp + k] = __float2half_rn(t[tx][ty + i * 8]);
    }
}

__global__ void conv_a(const float* __restrict__ A, int M, int K, int Kp, long long total,
                       __half* __restrict__ o)
{
    long long i = (long long)blockIdx.x * blockDim.x + threadIdx.x;
    if (i >= total) return;
    int m = (int)(i / Kp);
    int k = (int)(i % Kp);
    float v = 0.f;
    if (m < M && k < K) v = A[(size_t)m * K + k];
    o[i] = __float2half_rn(v);
}

__global__ void bias_sum_all(const float* a, const float* b, float* o)
{
    int i = blockIdx.x * blockDim.x + threadIdx.x;
    if (i < NLAYERS * HDIM) o[i] = a[i] + b[i];
}

__global__ void zero_int(int* p, int n)
{
    int i = blockIdx.x * blockDim.x + threadIdx.x;
    if (i < n) p[i] = 0;
}

// ================= CSR build =================
struct EdgePtrs { const int* es[3]; const int* ed[3]; };

__global__ void hist_all(const __grid_constant__ EdgePtrs ep, int* __restrict__ cnt)
{
    int r = blockIdx.y;
    int e = blockIdx.x * blockDim.x + threadIdx.x;
    if (e < EDG) atomicAdd(&cnt[r * NWIN + ep.ed[r][e]], 1);
}

__global__ void scan_all(const int* __restrict__ cnt, int* __restrict__ off,
                         int* __restrict__ cur)
{
    __shared__ int s[1024];
    int r = blockIdx.x;
    const int* c = cnt + r * NWIN;
    int* of = off + r * (NWIN + 1);
    int* cu = cur + r * NWIN;
    int t = threadIdx.x;
    int chunk = (NWIN + 1023) >> 10;
    int b = t * chunk, e = min(b + chunk, NWIN);
    int sum = 0;
    for (int i = b; i < e; i++) sum += c[i];
    s[t] = sum;
    __syncthreads();
    for (int d = 1; d < 1024; d <<= 1) {
        int v = (t >= d) ? s[t - d] : 0;
        __syncthreads();
        s[t] += v;
        __syncthreads();
    }
    int run = (t == 0) ? 0 : s[t - 1];
    for (int i = b; i < e; i++) {
        of[i] = run; cu[i] = run; run += c[i];
    }
    if (t == 0) of[NWIN] = s[1023];
}

__global__ void fill_all(const __grid_constant__ EdgePtrs ep, int* __restrict__ cur,
                         int* __restrict__ csrc)
{
    int r = blockIdx.y;
    int e = blockIdx.x * blockDim.x + threadIdx.x;
    if (e < EDG) {
        int p = atomicAdd(&cur[r * NWIN + ep.ed[r][e]], 1);
        csrc[(size_t)r * EDG + p] = ep.es[r][e];
    }
}

// ================= fused 3-relation gather-mean (fp16) =================
struct GatherBatch {
    const __half *src[3];
    const int *off[3], *csrc[3];
    int ndst[3];
    __half *o[3];
};

__device__ __forceinline__ void acc8h(float* acc, uint4 q)
{
    const __half2* h2 = (const __half2*)&q;
#pragma unroll
    for (int j = 0; j < 4; j++) {
        float2 f = __half22float2(h2[j]);
        acc[j * 2 + 0] += f.x;
        acc[j * 2 + 1] += f.y;
    }
}

__global__ void gather_all(const __grid_constant__ GatherBatch gb)
{
    int r = blockIdx.y;
    int t = threadIdx.x;
    int d = blockIdx.x * 2 + (t >> 6);
    int c = (t & 63) * 8;
    const __half* src = gb.src[r];

    float acc[8];
#pragma unroll
    for (int j = 0; j < 8; j++) acc[j] = 0.f;
    int deg = 0;
    if (d < gb.ndst[r]) {
        const int* off = gb.off[r];
        const int* cs = gb.csrc[r];
        int s0 = off[d], s1 = off[d + 1];
        deg = s1 - s0;
        int e = s0;
        for (; e + 4 <= s1; e += 4) {
            int i0 = cs[e], i1 = cs[e + 1], i2 = cs[e + 2], i3 = cs[e + 3];
            uint4 q0 = *(const uint4*)(src + (size_t)i0 * HDIM + c);
            uint4 q1 = *(const uint4*)(src + (size_t)i1 * HDIM + c);
            uint4 q2 = *(const uint4*)(src + (size_t)i2 * HDIM + c);
            uint4 q3 = *(const uint4*)(src + (size_t)i3 * HDIM + c);
            acc8h(acc, q0); acc8h(acc, q1); acc8h(acc, q2); acc8h(acc, q3);
        }
        for (; e < s1; e++) {
            uint4 q = *(const uint4*)(src + (size_t)cs[e] * HDIM + c);
            acc8h(acc, q);
        }
    }
    float inv = 1.f / (float)max(deg, 1);
    __half2 o2[4];
#pragma unroll
    for (int j = 0; j < 4; j++)
        o2[j] = __floats2half2_rn(acc[j * 2] * inv, acc[j * 2 + 1] * inv);
    *(uint4*)(gb.o[r] + (size_t)d * HDIM + c) = *(uint4*)o2;
}

// ================= low-dim CSRA pooling =================
__global__ void pool_small(const float* __restrict__ helin,
                           const float* __restrict__ hwlin,
                           const float* __restrict__ score,
                           const int* __restrict__ off, const int* __restrict__ csrc,
                           float* __restrict__ out)
{
    __shared__ float red[128];
    __shared__ float wts[128];
    __shared__ int   idx[128];
    int d = blockIdx.x;
    int t = threadIdx.x;
    if (d >= NWIN) return;
    int s0 = off[d], s1 = off[d + 1];

    float m = -FLT_MAX;
    for (int e = s0 + t; e < s1; e += 128) m = fmaxf(m, score[csrc[e]]);
    red[t] = m; __syncthreads();
    for (int w = 64; w; w >>= 1) {
        if (t < w) red[t] = fmaxf(red[t], red[t + w]);
        __syncthreads();
    }
    float smax = red[0];
    __syncthreads();
    float z = 0.f;
    for (int e = s0 + t; e < s1; e += 128) z += expf(score[csrc[e]] - smax);
    red[t] = z; __syncthreads();
    for (int w = 64; w; w >>= 1) {
        if (t < w) red[t] += red[t + w];
        __syncthreads();
    }
    float invz = 1.f / fmaxf(red[0], 1e-12f);
    __syncthreads();

    float acc = 0.f;
    for (int base = s0; base < s1; base += 128) {
        int e = base + t;
        if (e < s1) {
            int si = csrc[e];
            idx[t] = si;
            wts[t] = expf(score[si] - smax) * invz;
        }
        __syncthreads();
        int cnt = min(128, s1 - base);
        if (t < NOUT) {
            for (int j = 0; j < cnt; j++)
                acc += wts[j] * helin[(size_t)idx[j] * NOUT + t];
        }
        __syncthreads();
    }
    if (t < NOUT)
        out[(size_t)d * NOUT + t] = hwlin[(size_t)d * NOUT + t] + 0.5f * acc;
}

__global__ void gemv_score(const __half* __restrict__ he,
                           const float* __restrict__ w, float* __restrict__ sc)
{
    int row = blockIdx.x * 8 + (threadIdx.x >> 5);
    if (row >= NEX) return;
    int lane = threadIdx.x & 31;
    float s = 0.f;
#pragma unroll
    for (int k = lane * 4; k < HDIM; k += 128) {
        __half2 a = *(const __half2*)(he + (size_t)row * HDIM + k);
        __half2 b = *(const __half2*)(he + (size_t)row * HDIM + k + 2);
        float2 fa = __half22float2(a), fb = __half22float2(b);
        s += fa.x * w[k] + fa.y * w[k + 1] + fb.x * w[k + 2] + fb.y * w[k + 3];
    }
#pragma unroll
    for (int o = 16; o; o >>= 1) s += __shfl_down_sync(0xFFFFFFFFu, s, o);
    if (lane == 0) sc[row] = s;
}

// ================= GEMM common (fp16 single-pass) =================
struct GemmArgs {
    const __half *A[3], *B[3];
    int Kp[3];
    int nops, totChunks;
    int M, Nstore, ldd;
    const float* bias;
    float ps;
    int act;
    float* D;
    __half* Dh;
};
struct GemmPair { GemmArgs g[2]; };

__device__ __forceinline__ uint32_t smem_u32(const void* p) {
    uint32_t a;
    asm("{ .reg .u64 t; cvta.to.shared.u64 t, %1; cvt.u32.u64 %0, t; }" : "=r"(a) : "l"(p));
    return a;
}
__device__ __forceinline__ void cp16(uint32_t dst, const void* src) {
    asm volatile("cp.async.cg.shared.global [%0], [%1], 16;" :: "r"(dst), "l"(src));
}
__device__ __forceinline__ void cp_commit() { asm volatile("cp.async.commit_group;"); }
__device__ __forceinline__ void cp_wait0() { asm volatile("cp.async.wait_group 0;"); }
__device__ __forceinline__ void cp_wait1() { asm volatile("cp.async.wait_group 1;"); }

__device__ __forceinline__ void ldm_x4(uint32_t* r, uint32_t addr) {
    asm volatile("ldmatrix.sync.aligned.m8n8.x4.shared.b16 {%0,%1,%2,%3}, [%4];"
                 : "=r"(r[0]), "=r"(r[1]), "=r"(r[2]), "=r"(r[3]) : "r"(addr));
}
__device__ __forceinline__ void mma16816(float* c, const uint32_t* a, const uint32_t* b) {
    asm volatile("mma.sync.aligned.m16n8k16.row.col.f32.f16.f16.f32 "
                 "{%0,%1,%2,%3},{%4,%5,%6,%7},{%8,%9},{%0,%1,%2,%3};"
                 : "+f"(c[0]), "+f"(c[1]), "+f"(c[2]), "+f"(c[3])
                 : "r"(a[0]), "r"(a[1]), "r"(a[2]), "r"(a[3]), "r"(b[0]), "r"(b[1]));
}

__device__ __forceinline__ void map_oc(const GemmArgs& g, int t, int& o, int& c) {
    o = 0;
    int rem = t;
    while (o < g.nops - 1 && rem >= (g.Kp[o] >> 6)) { rem -= (g.Kp[o] >> 6); o++; }
    c = rem;
}

__device__ __forceinline__ void epi_frag(const GemmArgs& g, const float* a4,
                                         int row0, int col)
{
    if (col >= g.Nstore) return;
    float b0 = 0.f, b1 = 0.f;
    if (g.bias) {
        b0 = g.bias[col];
        if (col + 1 < g.Nstore) b1 = g.bias[col + 1];
    }
#pragma unroll
    for (int rr = 0; rr < 2; rr++) {
        int r = row0 + rr * 8;
        if (r >= g.M) continue;
        float v0 = (a4[rr * 2 + 0] + b0) * g.ps;
        float v1 = (a4[rr * 2 + 1] + b1) * g.ps;
        if (g.act) {
            v0 = v0 > 0.f ? v0 : 0.2f * v0;
            v1 = v1 > 0.f ? v1 : 0.2f * v1;
        }
        if (g.D) {
            float* dp = g.D + (size_t)r * g.ldd + col;
            if (col + 1 < g.Nstore) *(float2*)dp = make_float2(v0, v1);
            else *dp = v0;
        }
        if (g.Dh) {
            *(__half2*)(g.Dh + (size_t)r * HDIM + col) = __floats2half2_rn(v0, v1);
        }
    }
}

// ================= 512-thread 128x256 GEMM =================
#define STAGE2      49152      // A 16K, B 32K
#define GEMM_SMEM2  (2 * STAGE2)

__device__ __forceinline__ void load_stage512(const GemmArgs& g, int t, uint32_t sb,
                                              int tid, int m0, int n0)
{
    int o, c;
    map_oc(g, t, o, c);
    const int Kp = g.Kp[o];
    const int k0 = c << 6;
    {
        const __half* a_ = g.A[o] + (size_t)m0 * Kp + k0;
#pragma unroll
        for (int it = 0; it < 2; it++) {
            int idx = it * 512 + tid;
            int r = idx >> 3;
            int j = idx & 7;
            uint32_t sw = r * 128 + ((j ^ (r & 7)) << 4);
            cp16(sb + sw, a_ + (size_t)r * Kp + j * 8);
        }
    }
    {
        const __half* b_ = g.B[o] + (size_t)n0 * Kp + k0;
#pragma unroll
        for (int it = 0; it < 4; it++) {
            int idx = it * 512 + tid;
            int r = idx >> 3;
            int j = idx & 7;
            uint32_t sw = r * 128 + ((j ^ (r & 7)) << 4);
            cp16(sb + 16384 + sw, b_ + (size_t)r * Kp + j * 8);
        }
    }
    cp_commit();
}

__device__ __forceinline__ void gemm_body512(const GemmArgs& g, char* smem)
{
    const uint32_t sbase = smem_u32(smem);
    const int tid = threadIdx.x;
    const int lane = tid & 31;
    const int warp = tid >> 5;
    const int wm = warp >> 2;
    const int wn = warp & 3;
    const int m0 = blockIdx.y * 128;
    const int n0 = blockIdx.x * 256;

    float acc[2][8][4];
#pragma unroll
    for (int i = 0; i < 2; i++)
#pragma unroll
        for (int j = 0; j < 8; j++)
#pragma unroll
            for (int q = 0; q < 4; q++) acc[i][j][q] = 0.f;

    const int sx = lane & 7;
    const int arow = (lane & 7) + ((lane >> 3) & 1) * 8;
    const int khia = (lane >> 4) & 1;
    const int brow = (lane & 7) + ((lane >> 4) & 1) * 8;
    const int khib = (lane >> 3) & 1;

    const int T = g.totChunks;
    load_stage512(g, 0, sbase, tid, m0, n0);

    for (int t = 0; t < T; t++) {
        if (t + 1 < T) {
            load_stage512(g, t + 1, sbase + ((t + 1) & 1) * STAGE2, tid, m0, n0);
            cp_wait1();
        } else {
            cp_wait0();
        }
        __syncthreads();

        const uint32_t Ab = sbase + (t & 1) * STAGE2;
        const uint32_t Bb = Ab + 16384;

#pragma unroll
        for (int ks = 0; ks < 4; ks++) {
            const uint32_t colA = (uint32_t)(((ks * 2 + khia) ^ sx) << 4);
            const uint32_t colB = (uint32_t)(((ks * 2 + khib) ^ sx) << 4);
            uint32_t ah[2][4];
#pragma unroll
            for (int mt = 0; mt < 2; mt++) {
                int row = wm * 32 + mt * 16 + arow;
                ldm_x4(ah[mt], Ab + row * 128 + colA);
            }
#pragma unroll
            for (int half = 0; half < 2; half++) {
                uint32_t bh[2][4];
#pragma unroll
                for (int np = 0; np < 2; np++) {
                    int row = wn * 64 + half * 32 + np * 16 + brow;
                    ldm_x4(bh[np], Bb + row * 128 + colB);
                }
#pragma unroll
                for (int mt = 0; mt < 2; mt++) {
#pragma unroll
                    for (int nt = 0; nt < 4; nt++) {
                        const uint32_t* bf = &bh[nt >> 1][(nt & 1) * 2];
                        mma16816(acc[mt][half * 4 + nt], ah[mt], bf);
                    }
                }
            }
        }
        __syncthreads();
    }

#pragma unroll
    for (int mt = 0; mt < 2; mt++) {
        int row0 = m0 + wm * 32 + mt * 16 + (lane >> 2);
#pragma unroll
        for (int nt = 0; nt < 8; nt++) {
            int col = n0 + wn * 64 + nt * 8 + (lane & 3) * 2;
            epi_frag(g, acc[mt][nt], row0, col);
        }
    }
}

__global__ __launch_bounds__(512, 1) void gemm512_pair(const __grid_constant__ GemmPair p)
{
    extern __shared__ __align__(128) char smem[];
    gemm_body512(p.g[blockIdx.z], smem);
}

// ================= 256-thread 128x128 GEMM =================
#define STAGE_BYTES 32768      // A 16K, B 16K
#define GEMM_SMEM   (2 * STAGE_BYTES)

__device__ __forceinline__ void load_stage(const GemmArgs& g, int t, uint32_t sb,
                                           int tid, int m0, int n0)
{
    int o, c;
    map_oc(g, t, o, c);
    const int Kp = g.Kp[o];
    const int k0 = c << 6;
    {
        const __half* a_ = g.A[o] + (size_t)m0 * Kp + k0;
#pragma unroll
        for (int it = 0; it < 4; it++) {
            int idx = it * 256 + tid;
            int r = idx >> 3;
            int j = idx & 7;
            uint32_t sw = r * 128 + ((j ^ (r & 7)) << 4);
            cp16(sb + sw, a_ + (size_t)r * Kp + j * 8);
        }
    }
    {
        const __half* b_ = g.B[o] + (size_t)n0 * Kp + k0;
#pragma unroll
        for (int it = 0; it < 4; it++) {
            int idx = it * 256 + tid;
            int r = idx >> 3;
            int j = idx & 7;
            uint32_t sw = r * 128 + ((j ^ (r & 7)) << 4);
            cp16(sb + 16384 + sw, b_ + (size_t)r * Kp + j * 8);
        }
    }
    cp_commit();
}

__device__ __forceinline__ void gemm_body128(const GemmArgs& g, char* smem)
{
    const uint32_t sbase = smem_u32(smem);
    const int tid = threadIdx.x;
    const int lane = tid & 31;
    const int warp = tid >> 5;
    const int wm = warp >> 2;
    const int wn = warp & 3;
    const int m0 = blockIdx.y * 128;
    const int n0 = blockIdx.x * 128;

    float acc[4][4][4];
#pragma unroll
    for (int i = 0; i < 4; i++)
#pragma unroll
        for (int j = 0; j < 4; j++)
#pragma unroll
            for (int q = 0; q < 4; q++) acc[i][j][q] = 0.f;

    const int sx = lane & 7;
    const int arow = (lane & 7) + ((lane >> 3) & 1) * 8;
    const int khia = (lane >> 4) & 1;
    const int brow = (lane & 7) + ((lane >> 4) & 1) * 8;
    const int khib = (lane >> 3) & 1;

    const int T = g.totChunks;
    load_stage(g, 0, sbase, tid, m0, n0);

    for (int t = 0; t < T; t++) {
        if (t + 1 < T) {
            load_stage(g, t + 1, sbase + ((t + 1) & 1) * STAGE_BYTES, tid, m0, n0);
            cp_wait1();
        } else {
            cp_wait0();
        }
        __syncthreads();

        const uint32_t Ab = sbase + (t & 1) * STAGE_BYTES;
        const uint32_t Bb = Ab + 16384;

#pragma unroll
        for (int ks = 0; ks < 4; ks++) {
            uint32_t ah[4][4], bh[2][4];
            const uint32_t colA = (uint32_t)(((ks * 2 + khia) ^ sx) << 4);
            const uint32_t colB = (uint32_t)(((ks * 2 + khib) ^ sx) << 4);
#pragma unroll
            for (int mt = 0; mt < 4; mt++) {
                int row = wm * 64 + mt * 16 + arow;
                ldm_x4(ah[mt], Ab + row * 128 + colA);
            }
#pragma unroll
            for (int np = 0; np < 2; np++) {
                int row = wn * 32 + np * 16 + brow;
                ldm_x4(bh[np], Bb + row * 128 + colB);
            }
#pragma unroll
            for (int mt = 0; mt < 4; mt++) {
#pragma unroll
                for (int nt = 0; nt < 4; nt++) {
                    const uint32_t* bf = &bh[nt >> 1][(nt & 1) * 2];
                    mma16816(acc[mt][nt], ah[mt], bf);
                }
            }
        }
        __syncthreads();
    }

#pragma unroll
    for (int mt = 0; mt < 4; mt++) {
        int row0 = m0 + wm * 64 + mt * 16 + (lane >> 2);
#pragma unroll
        for (int nt = 0; nt < 4; nt++) {
            int col = n0 + wn * 32 + nt * 8 + (lane & 3) * 2;
            epi_frag(g, acc[mt][nt], row0, col);
        }
    }
}

__global__ __launch_bounds__(256, 1) void gemm_mma_pair(const __grid_constant__ GemmPair p)
{
    extern __shared__ __align__(128) char smem[];
    gemm_body128(p.g[blockIdx.z], smem);
}

// ================= host orchestration =================
struct OpDesc {
    const __half *A, *B;
    int Kp;
};

static void fill_args(GemmArgs& g, const OpDesc* ops, int nops, int M, int Nstore,
                      int ldd, const float* bias, float ps, int act,
                      float* D, __half* Dh)
{
    int T = 0;
    for (int o = 0; o < nops; o++) {
        g.A[o] = ops[o].A; g.B[o] = ops[o].B;
        g.Kp[o] = ops[o].Kp;
        T += ops[o].Kp / 64;
    }
    g.nops = nops; g.totChunks = T;
    g.M = M; g.Nstore = Nstore; g.ldd = ldd;
    g.bias = bias; g.ps = ps; g.act = act;
    g.D = D; g.Dh = Dh;
}

extern "C" void kernel_launch(void* const* d_in, const int* in_sizes, int n_in,
                              void* d_out, int out_size)
{
    const float* x_window  = (const float*)d_in[0];
    const float* x_example = (const float*)d_in[1];
    const int*   e_near    = (const int*)d_in[2];
    const int*   e_close   = (const int*)d_in[3];
    const int*   e_refer   = (const int*)d_in[4];
    const float* W_win     = (const float*)d_in[5];
    const float* W_exp     = (const float*)d_in[6];
    const float* W_post    = (const float*)d_in[7];
    const float* Wl_near   = (const float*)d_in[9];
    const float* Wr_near   = (const float*)d_in[10];
    const float* b_near    = (const float*)d_in[11];
    const float* Wl_close  = (const float*)d_in[12];
    const float* Wr_close  = (const float*)d_in[13];
    const float* b_close   = (const float*)d_in[14];
    const float* Wl_refer  = (const float*)d_in[15];
    const float* Wr_refer  = (const float*)d_in[16];
    const float* b_refer   = (const float*)d_in[17];
    const float* w_pool    = (const float*)d_in[18];
    const float* W_lin     = (const float*)d_in[19];
    const float* b_lin     = (const float*)d_in[20];
    float* out = (float*)d_out;

    cudaFuncSetAttribute(gemm_mma_pair, cudaFuncAttributeMaxDynamicSharedMemorySize, GEMM_SMEM);
    cudaFuncSetAttribute(gemm512_pair, cudaFuncAttributeMaxDynamicSharedMemorySize, GEMM_SMEM2);

    float *score, *bsum, *lin0, *lin1;
    int *cnt, *off, *cur, *csrc;
    __half *wt, *big, *pt;
    __half *phw[2], *phe[2], *pa0, *pa1, *pa2;
    cudaGetSymbolAddress((void**)&score, g_score);
    cudaGetSymbolAddress((void**)&bsum, g_bsum);
    cudaGetSymbolAddress((void**)&lin0, g_lin0);
    cudaGetSymbolAddress((void**)&lin1, g_lin1);
    cudaGetSymbolAddress((void**)&cnt, g_cnt);
    cudaGetSymbolAddress((void**)&off, g_off);
    cudaGetSymbolAddress((void**)&cur, g_cur);
    cudaGetSymbolAddress((void**)&csrc, g_csrc);
    cudaGetSymbolAddress((void**)&wt, g_wt);
    cudaGetSymbolAddress((void**)&big, g_big);
    cudaGetSymbolAddress((void**)&pt, g_pt);
    cudaGetSymbolAddress((void**)&phw[0], g_phw0);
    cudaGetSymbolAddress((void**)&phw[1], g_phw1);
    cudaGetSymbolAddress((void**)&phe[0], g_phe0);
    cudaGetSymbolAddress((void**)&phe[1], g_phe1);
    cudaGetSymbolAddress((void**)&pa0, g_pa0);
    cudaGetSymbolAddress((void**)&pa1, g_pa1);
    cudaGetSymbolAddress((void**)&pa2, g_pa2);

    const unsigned edge_blocks = (EDG + 255) / 256;

    // --- batched weight conversion ---
    {
        ConvBatch cb;
        for (int l = 0; l < NLAYERS; l++) {
            size_t s = (size_t)l * HDIM * HDIM;
            cb.W1[l * 5 + 0] = Wl_near + s;  cb.W2[l * 5 + 0] = nullptr;      cb.dstoff[l * 5 + 0] = WOFF_WLN(l);
            cb.W1[l * 5 + 1] = Wl_refer + s; cb.W2[l * 5 + 1] = nullptr;      cb.dstoff[l * 5 + 1] = WOFF_WLR(l);
            cb.W1[l * 5 + 2] = Wr_near + s;  cb.W2[l * 5 + 2] = Wr_refer + s; cb.dstoff[l * 5 + 2] = WOFF_WSUM(l);
            cb.W1[l * 5 + 3] = Wl_close + s; cb.W2[l * 5 + 3] = nullptr;      cb.dstoff[l * 5 + 3] = WOFF_WLC(l);
            cb.W1[l * 5 + 4] = Wr_close + s; cb.W2[l * 5 + 4] = nullptr;      cb.dstoff[l * 5 + 4] = WOFF_WRC(l);
        }
        cb.W1[20] = W_post; cb.W2[20] = nullptr; cb.dstoff[20] = WOFF_POST;
        dim3 blk(32, 8);
        dim3 gB(HDIM / 32, HDIM / 32, NBATCH);
        conv_w_batch<<<gB, blk>>>(cb, wt);

        dim3 gWIN(KP_WIN / 32, HDIM / 32);
        conv_w<<<gWIN, blk>>>(W_win, KWIN, HDIM, KP_WIN, wt + WOFF_WIN);
        dim3 gEXP(128 / 32, HDIM / 32);
        conv_w<<<gEXP, blk>>>(W_exp, KEXP, HDIM, 128, wt + WOFF_EXP);
        dim3 gLIN(HDIM / 32, 128 / 32);
        conv_w<<<gLIN, blk>>>(W_lin, HDIM, NOUT, HDIM, wt + WOFF_LIN);
        bias_sum_all<<<(NLAYERS * HDIM + 255) / 256, 256>>>(b_near, b_refer, bsum);
    }

    // --- CSR build ---
    {
        EdgePtrs ep;
        ep.es[0] = e_near;  ep.ed[0] = e_near + EDG;
        ep.es[1] = e_refer; ep.ed[1] = e_refer + EDG;
        ep.es[2] = e_close; ep.ed[2] = e_close + EDG;
        zero_int<<<(3 * NWIN + 255) / 256, 256>>>(cnt, 3 * NWIN);
        dim3 ge(edge_blocks, 3);
        hist_all<<<ge, 256>>>(ep, cnt);
        scan_all<<<3, 1024>>>(cnt, off, cur);
        fill_all<<<ge, 256>>>(ep, cur, csrc);
    }

    // --- input projections (paired, 512-thread GEMM) ---
    {
        long long tot = (long long)MP * 128;
        conv_a<<<(unsigned)((tot + 255) / 256), 256>>>(x_example, NEX, KEXP, 128, tot, pa0);
        tot = (long long)MP * KP_WIN;
        conv_a<<<(unsigned)((tot + 255) / 256), 256>>>(x_window, NWIN, KWIN, KP_WIN, tot, big);

        GemmPair pr;
        OpDesc opw = { big, wt + WOFF_WIN, KP_WIN };
        OpDesc ope = { pa0, wt + WOFF_EXP, 128 };
        fill_args(pr.g[0], &opw, 1, NWIN, HDIM, HDIM, nullptr, 1.f, 1, nullptr, pt);
        fill_args(pr.g[1], &ope, 1, NEX, HDIM, HDIM, nullptr, 1.f, 1, nullptr, pa1);
        gemm512_pair<<<dim3(2, 235, 2), 512, GEMM_SMEM2>>>(pr);

        OpDesc opw2 = { pt, wt + WOFF_POST, HDIM };
        OpDesc ope2 = { pa1, wt + WOFF_POST, HDIM };
        fill_args(pr.g[0], &opw2, 1, NWIN, HDIM, HDIM, nullptr, 1.f, 1, nullptr, phw[0]);
        fill_args(pr.g[1], &ope2, 1, NEX, HDIM, HDIM, nullptr, 1.f, 1, nullptr, phe[0]);
        gemm512_pair<<<dim3(2, 235, 2), 512, GEMM_SMEM2>>>(pr);
    }

    // --- SAGE layers ---
    int curb = 0;
    for (int l = 0; l < NLAYERS; l++) {
        int nxt = curb ^ 1;
        GatherBatch gb;
        gb.src[0] = phw[curb];
        gb.src[1] = phe[curb];
        gb.src[2] = phe[curb];
        gb.off[0] = off + 0 * (NWIN + 1); gb.csrc[0] = csrc + 0 * (size_t)EDG; gb.ndst[0] = NWIN;
        gb.off[1] = off + 1 * (NWIN + 1); gb.csrc[1] = csrc + 1 * (size_t)EDG; gb.ndst[1] = NWIN;
        gb.off[2] = off + 2 * (NWIN + 1); gb.csrc[2] = csrc + 2 * (size_t)EDG; gb.ndst[2] = NEX;
        gb.o[0] = pa0; gb.o[1] = pa1; gb.o[2] = pa2;
        gather_all<<<dim3(MP / 2, 3), 128>>>(gb);

        GemmPair pr;
        OpDesc ops3[3] = {
            { pa0, wt + WOFF_WLN(l), HDIM },
            { pa1, wt + WOFF_WLR(l), HDIM },
            { phw[curb], wt + WOFF_WSUM(l), HDIM },
        };
        OpDesc ops2[2] = {
            { pa2, wt + WOFF_WLC(l), HDIM },
            { phe[curb], wt + WOFF_WRC(l), HDIM },
        };
        fill_args(pr.g[0], ops3, 3, NWIN, HDIM, HDIM, bsum + (size_t)l * HDIM, 0.5f, 1,
                  nullptr, phw[nxt]);
        fill_args(pr.g[1], ops2, 2, NEX, HDIM, HDIM, b_close + (size_t)l * HDIM, 1.f, 1,
                  nullptr, phe[nxt]);
        gemm512_pair<<<dim3(2, 235, 2), 512, GEMM_SMEM2>>>(pr);
        curb = nxt;
    }

    // --- score + low-dim projections (paired 128-wide GEMM) ---
    gemv_score<<<(NEX + 7) / 8, 256>>>(phe[curb], w_pool, score);
    {
        GemmPair pr;
        OpDesc opw = { phw[curb], wt + WOFF_LIN, HDIM };
        OpDesc ope = { phe[curb], wt + WOFF_LIN, HDIM };
        fill_args(pr.g[0], &opw, 1, NWIN, NOUT, NOUT, b_lin, 1.f, 0, lin0, nullptr);
        fill_args(pr.g[1], &ope, 1, NEX, NOUT, NOUT, nullptr, 1.f, 0, lin1, nullptr);
        gemm_mma_pair<<<dim3(1, 235, 2), 256, GEMM_SMEM>>>(pr);
    }

    // --- low-dim CSRA pooling -> out directly ---
    pool_small<<<NWIN, 128>>>(lin1, lin0, score,
                              off + 1 * (NWIN + 1), csrc + 1 * (size_t)EDG, out);
}